// round 1
// baseline (speedup 1.0000x reference)
#include <cuda_runtime.h>
#include <cuda_bf16.h>
#include <cstdint>

// ---------------------------------------------------------------------------
// BidirectionalMambaLayer: B=2, L=1024, D_MODEL=768, D_INNER=1536, D_STATE=16,
// DT_RANK=48, D_CONV=4. Two independent Mamba blocks (fwd, bwd-on-flipped-x),
// outputs summed.
// ---------------------------------------------------------------------------

#define SEQL   1024
#define NB     2
#define MTOT   (NB * SEQL)     // 2048 rows (tokens)
#define DMODEL 768
#define DINNER 1536
#define DSTATE 16
#define DTRANK 48
#define DCONV  4
#define XZW    (2 * DINNER)    // 3072
#define XDBLW  (DTRANK + 2 * DSTATE)  // 80

// -------------------------- scratch (device globals) -----------------------
__device__ float g_xz   [2][(size_t)MTOT * XZW];    // in_proj output (u_raw | z)
__device__ float g_u    [2][(size_t)MTOT * DINNER]; // conv+silu output
__device__ float g_xdbl [2][(size_t)MTOT * XDBLW];  // (dt | B | C)
__device__ float g_delta[2][(size_t)MTOT * DINNER]; // softplus(dt @ dt_w + b)
__device__ float g_ypre [2][(size_t)MTOT * DINNER]; // gated scan output

enum { BUF_XZ = 0, BUF_U = 1, BUF_XDBL = 2, BUF_DELTA = 3, BUF_YPRE = 4 };

__device__ __forceinline__ float* scratch_ptr(int id, int dir) {
    switch (id) {
        case BUF_XZ:    return g_xz[dir];
        case BUF_U:     return g_u[dir];
        case BUF_XDBL:  return g_xdbl[dir];
        case BUF_DELTA: return g_delta[dir];
        case BUF_YPRE:  return g_ypre[dir];
    }
    return nullptr;
}

enum { ACT_NONE = 0, ACT_SOFTPLUS = 1 };

// ---------------------------------------------------------------------------
// Generic TN GEMM: C[M,N] (+)= act( A[M,K] * W[N,K]^T + bias )
// BM=BN=128, BK=8, 256 threads, 8x8 micro-tile.
// M is always 2048 (multiple of 128). N, K arbitrary with K % 8 == 0.
// FLIPA / FLIPC flip the sequence index of the row (m ^ 1023 within batch).
// ---------------------------------------------------------------------------
template<int ACT, bool FLIPA, bool FLIPC, bool ACCUM>
__global__ __launch_bounds__(256)
void gemm_tn(const float* __restrict__ Aext, int aId,
             const float* __restrict__ W,
             const float* __restrict__ bias,
             float* __restrict__ Cext, int cId,
             int dir, int N, int K, int lda, int ldc)
{
    const float* A = Aext ? Aext : scratch_ptr(aId, dir);
    float*       C = Cext ? Cext : scratch_ptr(cId, dir);

    __shared__ float sA[8][132];
    __shared__ float sB[8][132];

    const int bm  = blockIdx.y * 128;
    const int bn  = blockIdx.x * 128;
    const int tid = threadIdx.x;
    const int tx  = tid & 15;
    const int ty  = tid >> 4;

    // cooperative loads: each thread loads one float4 of A-tile and one of W-tile
    const int arow = tid >> 1;          // 0..127
    const int acol = (tid & 1) * 4;     // 0 or 4

    int gm = bm + arow;
    if (FLIPA) gm ^= (SEQL - 1);
    const int wn = bn + arow;

    float acc[8][8];
#pragma unroll
    for (int i = 0; i < 8; i++)
#pragma unroll
        for (int j = 0; j < 8; j++) acc[i][j] = 0.f;

    for (int k0 = 0; k0 < K; k0 += 8) {
        float4 av = *(const float4*)(A + (size_t)gm * lda + k0 + acol);
        float4 wv = make_float4(0.f, 0.f, 0.f, 0.f);
        if (wn < N)
            wv = *(const float4*)(W + (size_t)wn * K + k0 + acol);

        sA[acol + 0][arow] = av.x;
        sA[acol + 1][arow] = av.y;
        sA[acol + 2][arow] = av.z;
        sA[acol + 3][arow] = av.w;
        sB[acol + 0][arow] = wv.x;
        sB[acol + 1][arow] = wv.y;
        sB[acol + 2][arow] = wv.z;
        sB[acol + 3][arow] = wv.w;
        __syncthreads();

#pragma unroll
        for (int kk = 0; kk < 8; kk++) {
            float ra[8], rb[8];
            *(float4*)&ra[0] = *(const float4*)&sA[kk][ty * 8];
            *(float4*)&ra[4] = *(const float4*)&sA[kk][ty * 8 + 4];
            *(float4*)&rb[0] = *(const float4*)&sB[kk][tx * 8];
            *(float4*)&rb[4] = *(const float4*)&sB[kk][tx * 8 + 4];
#pragma unroll
            for (int i = 0; i < 8; i++)
#pragma unroll
                for (int j = 0; j < 8; j++)
                    acc[i][j] = fmaf(ra[i], rb[j], acc[i][j]);
        }
        __syncthreads();
    }

#pragma unroll
    for (int i = 0; i < 8; i++) {
        int m  = bm + ty * 8 + i;
        int mc = FLIPC ? (m ^ (SEQL - 1)) : m;
#pragma unroll
        for (int j = 0; j < 8; j++) {
            int n = bn + tx * 8 + j;
            if (n < N) {
                float v = acc[i][j];
                if (bias) v += bias[n];
                if (ACT == ACT_SOFTPLUS)
                    v = (v > 20.f) ? v : log1pf(__expf(v));
                if (ACCUM) C[(size_t)mc * ldc + n] += v;
                else       C[(size_t)mc * ldc + n] = v;
            }
        }
    }
}

// ---------------------------------------------------------------------------
// Causal depthwise conv (D_CONV=4) + bias + SiLU.
// Reads u_raw = first DINNER columns of g_xz[dir], writes g_u[dir].
// ---------------------------------------------------------------------------
__global__ void conv_silu_kernel(int dir,
                                 const float* __restrict__ conv_w,
                                 const float* __restrict__ conv_b)
{
    int idx = blockIdx.x * blockDim.x + threadIdx.x;
    if (idx >= MTOT * DINNER) return;
    int row = idx / DINNER;
    int d   = idx - row * DINNER;
    int l   = row & (SEQL - 1);

    const float* xz = g_xz[dir];
    float s = conv_b[d];
#pragma unroll
    for (int k = 0; k < DCONV; k++) {
        int ls = l - (DCONV - 1) + k;
        if (ls >= 0)
            s = fmaf(conv_w[d * DCONV + k],
                     xz[(size_t)(row - (DCONV - 1) + k) * XZW + d], s);
    }
    // SiLU
    g_u[dir][idx] = s / (1.f + __expf(-s));
}

// ---------------------------------------------------------------------------
// Selective scan. One warp = 2 channels; 16 lanes = 16 states per channel.
// grid: (3072/16 = 192, 2 dirs), 256 threads (8 warps = 16 channels / block).
// Fuses: dA/dBu formation, h recurrence, y = <h,C>, +u*D skip, silu(z) gate.
// ---------------------------------------------------------------------------
__global__ __launch_bounds__(256)
void scan_kernel(const float* __restrict__ fAlog, const float* __restrict__ fD,
                 const float* __restrict__ bAlog, const float* __restrict__ bD)
{
    const int dir = blockIdx.y;
    const float* Alog = dir ? bAlog : fAlog;
    const float* Dp   = dir ? bD    : fD;
    const float* delta = g_delta[dir];
    const float* u     = g_u[dir];
    const float* xdbl  = g_xdbl[dir];
    const float* xz    = g_xz[dir];
    float*       ypre  = g_ypre[dir];

    const int lane = threadIdx.x & 31;
    const int warp = threadIdx.x >> 5;
    const int half = lane >> 4;          // which of the 2 channels in this warp
    const int n    = lane & 15;          // state index

    const int c = blockIdx.x * 16 + warp * 2 + half;  // 0..3071
    const int b = c / DINNER;
    const int d = c - b * DINNER;

    const float Aneg = -__expf(Alog[d * DSTATE + n]);
    const float Dd   = Dp[d];

    float h = 0.f;
    const size_t rowbase = (size_t)b * SEQL;

    for (int l = 0; l < SEQL; l++) {
        const size_t row = rowbase + l;
        const float dl = delta[row * DINNER + d];
        const float uu = u[row * DINNER + d];
        const float Bn = xdbl[row * XDBLW + DTRANK + n];
        const float Cn = xdbl[row * XDBLW + DTRANK + DSTATE + n];

        const float dA = __expf(dl * Aneg);
        h = fmaf(dA, h, dl * Bn * uu);

        float yp = h * Cn;
        yp += __shfl_xor_sync(0xffffffffu, yp, 1);
        yp += __shfl_xor_sync(0xffffffffu, yp, 2);
        yp += __shfl_xor_sync(0xffffffffu, yp, 4);
        yp += __shfl_xor_sync(0xffffffffu, yp, 8);

        if (n == 0) {
            const float zz = xz[row * XZW + DINNER + d];
            float y = fmaf(uu, Dd, yp);
            y *= zz / (1.f + __expf(-zz));   // * silu(z)
            ypre[row * DINNER + d] = y;
        }
    }
}

// ---------------------------------------------------------------------------
// Host launch
// Inputs (metadata order): x, then f_{in_w,conv_w,conv_b,xproj_w,dt_w,dt_b,
// Alog,D,out_w}, then b_{...}.
// ---------------------------------------------------------------------------
extern "C" void kernel_launch(void* const* d_in, const int* in_sizes, int n_in,
                              void* d_out, int out_size)
{
    const float* x = (const float*)d_in[0];
    float* out = (float*)d_out;

    for (int dir = 0; dir < 2; dir++) {
        const float* in_w    = (const float*)d_in[1 + dir * 9 + 0];
        const float* conv_w  = (const float*)d_in[1 + dir * 9 + 1];
        const float* conv_b  = (const float*)d_in[1 + dir * 9 + 2];
        const float* xproj_w = (const float*)d_in[1 + dir * 9 + 3];
        const float* dt_w    = (const float*)d_in[1 + dir * 9 + 4];
        const float* dt_b    = (const float*)d_in[1 + dir * 9 + 5];

        // in_proj: xz[2048,3072] = x(flipped for bwd) @ in_w^T
        dim3 g1(XZW / 128, MTOT / 128);
        if (dir == 0)
            gemm_tn<ACT_NONE, false, false, false><<<g1, 256>>>(
                x, -1, in_w, nullptr, nullptr, BUF_XZ, dir,
                XZW, DMODEL, DMODEL, XZW);
        else
            gemm_tn<ACT_NONE, true, false, false><<<g1, 256>>>(
                x, -1, in_w, nullptr, nullptr, BUF_XZ, dir,
                XZW, DMODEL, DMODEL, XZW);

        // depthwise conv + SiLU
        conv_silu_kernel<<<(MTOT * DINNER + 255) / 256, 256>>>(dir, conv_w, conv_b);

        // x_proj: xdbl[2048,80] = u @ xproj_w^T
        gemm_tn<ACT_NONE, false, false, false><<<dim3(1, MTOT / 128), 256>>>(
            nullptr, BUF_U, xproj_w, nullptr, nullptr, BUF_XDBL, dir,
            XDBLW, DINNER, DINNER, XDBLW);

        // delta: softplus(xdbl[:, :48] @ dt_w^T + dt_b)  [2048,1536]
        gemm_tn<ACT_SOFTPLUS, false, false, false><<<dim3(DINNER / 128, MTOT / 128), 256>>>(
            nullptr, BUF_XDBL, dt_w, dt_b, nullptr, BUF_DELTA, dir,
            DINNER, DTRANK, XDBLW, DINNER);
    }

    // selective scan, both directions concurrently
    {
        const float* fAlog = (const float*)d_in[1 + 0 * 9 + 6];
        const float* fD    = (const float*)d_in[1 + 0 * 9 + 7];
        const float* bAlog = (const float*)d_in[1 + 1 * 9 + 6];
        const float* bD    = (const float*)d_in[1 + 1 * 9 + 7];
        scan_kernel<<<dim3((NB * DINNER) / 16, 2), 256>>>(fAlog, fD, bAlog, bD);
    }

    // out_proj fwd: out = ypre_f @ f_out_w^T
    {
        const float* f_out_w = (const float*)d_in[1 + 0 * 9 + 8];
        gemm_tn<ACT_NONE, false, false, false><<<dim3(DMODEL / 128, MTOT / 128), 256>>>(
            nullptr, BUF_YPRE, f_out_w, nullptr, out, -1, 0,
            DMODEL, DINNER, DINNER, DMODEL);
    }
    // out_proj bwd: out[flip rows] += ypre_b @ b_out_w^T
    {
        const float* b_out_w = (const float*)d_in[1 + 1 * 9 + 8];
        gemm_tn<ACT_NONE, false, true, true><<<dim3(DMODEL / 128, MTOT / 128), 256>>>(
            nullptr, BUF_YPRE, b_out_w, nullptr, out, -1, 1,
            DMODEL, DINNER, DINNER, DMODEL);
    }
}

// round 2
// speedup vs baseline: 1.5474x; 1.5474x over previous
#include <cuda_runtime.h>
#include <cuda_bf16.h>
#include <cstdint>

// ---------------------------------------------------------------------------
// BidirectionalMambaLayer: B=2, L=1024, D_MODEL=768, D_INNER=1536, D_STATE=16,
// DT_RANK=48, D_CONV=4. Two independent Mamba blocks (fwd, bwd-on-flipped-x),
// outputs summed.  Round 2: GEMMs on tensor pipe via mma.sync tf32.
// ---------------------------------------------------------------------------

#define SEQL   1024
#define NB     2
#define MTOT   (NB * SEQL)     // 2048 rows (tokens)
#define DMODEL 768
#define DINNER 1536
#define DSTATE 16
#define DTRANK 48
#define DCONV  4
#define XZW    (2 * DINNER)    // 3072
#define XDBLW  (DTRANK + 2 * DSTATE)  // 80

// -------------------------- scratch (device globals) -----------------------
__device__ float g_xz   [2][(size_t)MTOT * XZW];    // in_proj output (u_raw | z)
__device__ float g_u    [2][(size_t)MTOT * DINNER]; // conv+silu output
__device__ float g_xdbl [2][(size_t)MTOT * XDBLW];  // (dt | B | C)
__device__ float g_delta[2][(size_t)MTOT * DINNER]; // softplus(dt @ dt_w + b)
__device__ float g_ypre [2][(size_t)MTOT * DINNER]; // gated scan output

enum { BUF_XZ = 0, BUF_U = 1, BUF_XDBL = 2, BUF_DELTA = 3, BUF_YPRE = 4 };

__device__ __forceinline__ float* scratch_ptr(int id, int dir) {
    switch (id) {
        case BUF_XZ:    return g_xz[dir];
        case BUF_U:     return g_u[dir];
        case BUF_XDBL:  return g_xdbl[dir];
        case BUF_DELTA: return g_delta[dir];
        case BUF_YPRE:  return g_ypre[dir];
    }
    return nullptr;
}

enum { ACT_NONE = 0, ACT_SOFTPLUS = 1 };

__device__ __forceinline__ float tf32r(float x) {
    uint32_t u;
    asm("cvt.rna.tf32.f32 %0, %1;" : "=r"(u) : "f"(x));
    return __uint_as_float(u);
}

// ---------------------------------------------------------------------------
// Tensor-core TN GEMM (tf32 mma.sync): C[M,N] (+)= act( A[M,K]*W[N,K]^T + b )
// BM=BN=128, BK=16, 256 threads (8 warps as 2m x 4n), warp tile 64x32,
// mma.m16n8k8.tf32. K % 16 == 0, M % 128 == 0, N arbitrary.
// FLIPA / FLIPC flip the sequence index of the row (m ^ 1023 within batch).
// ---------------------------------------------------------------------------
template<int ACT, bool FLIPA, bool FLIPC, bool ACCUM>
__global__ __launch_bounds__(256, 2)
void gemm_mma(const float* __restrict__ Aext, int aId,
              const float* __restrict__ W,
              const float* __restrict__ bias,
              float* __restrict__ Cext, int cId,
              int dir, int N, int K, int lda, int ldc)
{
    const float* A = Aext ? Aext : scratch_ptr(aId, dir);
    float*       C = Cext ? Cext : scratch_ptr(cId, dir);

    __shared__ float sA[16][132];   // [k][m], tf32-rounded
    __shared__ float sB[16][132];   // [k][n], tf32-rounded

    const int bm   = blockIdx.y * 128;
    const int bn   = blockIdx.x * 128;
    const int tid  = threadIdx.x;
    const int lane = tid & 31;
    const int warp = tid >> 5;
    const int wm   = warp >> 2;       // 0..1  (m)
    const int wn   = warp & 3;        // 0..3  (n)
    const int gr   = lane >> 2;       // 0..7
    const int tq   = lane & 3;        // 0..3

    float acc[4][4][4];
#pragma unroll
    for (int mt = 0; mt < 4; mt++)
#pragma unroll
        for (int nt = 0; nt < 4; nt++)
#pragma unroll
            for (int r = 0; r < 4; r++) acc[mt][nt][r] = 0.f;

    for (int k0 = 0; k0 < K; k0 += 16) {
        __syncthreads();   // previous tile fully consumed
        // cooperative load: 512 float4 per matrix, 2 each per thread
#pragma unroll
        for (int r = 0; r < 2; r++) {
            const int f   = tid + r * 256;   // 0..511
            const int row = f >> 2;          // 0..127
            const int kq  = (f & 3) * 4;     // 0,4,8,12

            int gm = bm + row;
            if (FLIPA) gm ^= (SEQL - 1);
            float4 av = *(const float4*)(A + (size_t)gm * lda + k0 + kq);
            sA[kq + 0][row] = tf32r(av.x);
            sA[kq + 1][row] = tf32r(av.y);
            sA[kq + 2][row] = tf32r(av.z);
            sA[kq + 3][row] = tf32r(av.w);

            const int wnr = bn + row;
            float4 wv = make_float4(0.f, 0.f, 0.f, 0.f);
            if (wnr < N)
                wv = *(const float4*)(W + (size_t)wnr * K + k0 + kq);
            sB[kq + 0][row] = tf32r(wv.x);
            sB[kq + 1][row] = tf32r(wv.y);
            sB[kq + 2][row] = tf32r(wv.z);
            sB[kq + 3][row] = tf32r(wv.w);
        }
        __syncthreads();

#pragma unroll
        for (int ks = 0; ks < 2; ks++) {
            const int kb = ks * 8;
            uint32_t a[4][4], b[4][2];
#pragma unroll
            for (int mt = 0; mt < 4; mt++) {
                const int m0 = wm * 64 + mt * 16 + gr;
                a[mt][0] = __float_as_uint(sA[kb + tq][m0]);
                a[mt][1] = __float_as_uint(sA[kb + tq][m0 + 8]);
                a[mt][2] = __float_as_uint(sA[kb + tq + 4][m0]);
                a[mt][3] = __float_as_uint(sA[kb + tq + 4][m0 + 8]);
            }
#pragma unroll
            for (int nt = 0; nt < 4; nt++) {
                const int n0 = wn * 32 + nt * 8 + gr;
                b[nt][0] = __float_as_uint(sB[kb + tq][n0]);
                b[nt][1] = __float_as_uint(sB[kb + tq + 4][n0]);
            }
#pragma unroll
            for (int mt = 0; mt < 4; mt++)
#pragma unroll
                for (int nt = 0; nt < 4; nt++) {
                    asm volatile(
                        "mma.sync.aligned.m16n8k8.row.col.f32.tf32.tf32.f32 "
                        "{%0,%1,%2,%3}, {%4,%5,%6,%7}, {%8,%9}, {%0,%1,%2,%3};"
                        : "+f"(acc[mt][nt][0]), "+f"(acc[mt][nt][1]),
                          "+f"(acc[mt][nt][2]), "+f"(acc[mt][nt][3])
                        : "r"(a[mt][0]), "r"(a[mt][1]), "r"(a[mt][2]), "r"(a[mt][3]),
                          "r"(b[nt][0]), "r"(b[nt][1]));
                }
        }
    }

    // epilogue
#pragma unroll
    for (int mt = 0; mt < 4; mt++) {
        const int m0 = bm + wm * 64 + mt * 16 + gr;
#pragma unroll
        for (int half = 0; half < 2; half++) {
            int m  = m0 + half * 8;
            int mc = FLIPC ? (m ^ (SEQL - 1)) : m;
#pragma unroll
            for (int nt = 0; nt < 4; nt++) {
                const int nbase = bn + wn * 32 + nt * 8 + 2 * tq;
#pragma unroll
                for (int j = 0; j < 2; j++) {
                    const int n = nbase + j;
                    if (n < N) {
                        float v = acc[mt][nt][half * 2 + j];
                        if (bias) v += bias[n];
                        if (ACT == ACT_SOFTPLUS)
                            v = (v > 20.f) ? v : log1pf(__expf(v));
                        if (ACCUM) C[(size_t)mc * ldc + n] += v;
                        else       C[(size_t)mc * ldc + n] = v;
                    }
                }
            }
        }
    }
}

// ---------------------------------------------------------------------------
// Causal depthwise conv (D_CONV=4) + bias + SiLU.
// ---------------------------------------------------------------------------
__global__ void conv_silu_kernel(int dir,
                                 const float* __restrict__ conv_w,
                                 const float* __restrict__ conv_b)
{
    int idx = blockIdx.x * blockDim.x + threadIdx.x;
    if (idx >= MTOT * DINNER) return;
    int row = idx / DINNER;
    int d   = idx - row * DINNER;
    int l   = row & (SEQL - 1);

    const float* xz = g_xz[dir];
    float s = conv_b[d];
#pragma unroll
    for (int k = 0; k < DCONV; k++) {
        int ls = l - (DCONV - 1) + k;
        if (ls >= 0)
            s = fmaf(conv_w[d * DCONV + k],
                     xz[(size_t)(row - (DCONV - 1) + k) * XZW + d], s);
    }
    g_u[dir][idx] = s / (1.f + __expf(-s));
}

// ---------------------------------------------------------------------------
// Selective scan. One warp = 2 channels; 16 lanes = 16 states per channel.
// ---------------------------------------------------------------------------
__global__ __launch_bounds__(256)
void scan_kernel(const float* __restrict__ fAlog, const float* __restrict__ fD,
                 const float* __restrict__ bAlog, const float* __restrict__ bD)
{
    const int dir = blockIdx.y;
    const float* Alog = dir ? bAlog : fAlog;
    const float* Dp   = dir ? bD    : fD;
    const float* delta = g_delta[dir];
    const float* u     = g_u[dir];
    const float* xdbl  = g_xdbl[dir];
    const float* xz    = g_xz[dir];
    float*       ypre  = g_ypre[dir];

    const int lane = threadIdx.x & 31;
    const int warp = threadIdx.x >> 5;
    const int half = lane >> 4;
    const int n    = lane & 15;

    const int c = blockIdx.x * 16 + warp * 2 + half;  // 0..3071
    const int b = c / DINNER;
    const int d = c - b * DINNER;

    const float Aneg = -__expf(Alog[d * DSTATE + n]);
    const float Dd   = Dp[d];

    float h = 0.f;
    const size_t rowbase = (size_t)b * SEQL;

    for (int l = 0; l < SEQL; l++) {
        const size_t row = rowbase + l;
        const float dl = delta[row * DINNER + d];
        const float uu = u[row * DINNER + d];
        const float Bn = xdbl[row * XDBLW + DTRANK + n];
        const float Cn = xdbl[row * XDBLW + DTRANK + DSTATE + n];

        const float dA = __expf(dl * Aneg);
        h = fmaf(dA, h, dl * Bn * uu);

        float yp = h * Cn;
        yp += __shfl_xor_sync(0xffffffffu, yp, 1);
        yp += __shfl_xor_sync(0xffffffffu, yp, 2);
        yp += __shfl_xor_sync(0xffffffffu, yp, 4);
        yp += __shfl_xor_sync(0xffffffffu, yp, 8);

        if (n == 0) {
            const float zz = xz[row * XZW + DINNER + d];
            float y = fmaf(uu, Dd, yp);
            y *= zz / (1.f + __expf(-zz));
            ypre[row * DINNER + d] = y;
        }
    }
}

// ---------------------------------------------------------------------------
// Host launch
// ---------------------------------------------------------------------------
extern "C" void kernel_launch(void* const* d_in, const int* in_sizes, int n_in,
                              void* d_out, int out_size)
{
    const float* x = (const float*)d_in[0];
    float* out = (float*)d_out;

    for (int dir = 0; dir < 2; dir++) {
        const float* in_w    = (const float*)d_in[1 + dir * 9 + 0];
        const float* conv_w  = (const float*)d_in[1 + dir * 9 + 1];
        const float* conv_b  = (const float*)d_in[1 + dir * 9 + 2];
        const float* xproj_w = (const float*)d_in[1 + dir * 9 + 3];
        const float* dt_w    = (const float*)d_in[1 + dir * 9 + 4];
        const float* dt_b    = (const float*)d_in[1 + dir * 9 + 5];

        // in_proj: xz[2048,3072] = x(flipped for bwd) @ in_w^T
        dim3 g1(XZW / 128, MTOT / 128);
        if (dir == 0)
            gemm_mma<ACT_NONE, false, false, false><<<g1, 256>>>(
                x, -1, in_w, nullptr, nullptr, BUF_XZ, dir,
                XZW, DMODEL, DMODEL, XZW);
        else
            gemm_mma<ACT_NONE, true, false, false><<<g1, 256>>>(
                x, -1, in_w, nullptr, nullptr, BUF_XZ, dir,
                XZW, DMODEL, DMODEL, XZW);

        // depthwise conv + SiLU
        conv_silu_kernel<<<(MTOT * DINNER + 255) / 256, 256>>>(dir, conv_w, conv_b);

        // x_proj: xdbl[2048,80] = u @ xproj_w^T
        gemm_mma<ACT_NONE, false, false, false><<<dim3(1, MTOT / 128), 256>>>(
            nullptr, BUF_U, xproj_w, nullptr, nullptr, BUF_XDBL, dir,
            XDBLW, DINNER, DINNER, XDBLW);

        // delta: softplus(xdbl[:, :48] @ dt_w^T + dt_b)  [2048,1536]
        gemm_mma<ACT_SOFTPLUS, false, false, false><<<dim3(DINNER / 128, MTOT / 128), 256>>>(
            nullptr, BUF_XDBL, dt_w, dt_b, nullptr, BUF_DELTA, dir,
            DINNER, DTRANK, XDBLW, DINNER);
    }

    // selective scan, both directions concurrently
    {
        const float* fAlog = (const float*)d_in[1 + 0 * 9 + 6];
        const float* fD    = (const float*)d_in[1 + 0 * 9 + 7];
        const float* bAlog = (const float*)d_in[1 + 1 * 9 + 6];
        const float* bD    = (const float*)d_in[1 + 1 * 9 + 7];
        scan_kernel<<<dim3((NB * DINNER) / 16, 2), 256>>>(fAlog, fD, bAlog, bD);
    }

    // out_proj fwd: out = ypre_f @ f_out_w^T
    {
        const float* f_out_w = (const float*)d_in[1 + 0 * 9 + 8];
        gemm_mma<ACT_NONE, false, false, false><<<dim3(DMODEL / 128, MTOT / 128), 256>>>(
            nullptr, BUF_YPRE, f_out_w, nullptr, out, -1, 0,
            DMODEL, DINNER, DINNER, DMODEL);
    }
    // out_proj bwd: out[flip rows] += ypre_b @ b_out_w^T
    {
        const float* b_out_w = (const float*)d_in[1 + 1 * 9 + 8];
        gemm_mma<ACT_NONE, false, true, true><<<dim3(DMODEL / 128, MTOT / 128), 256>>>(
            nullptr, BUF_YPRE, b_out_w, nullptr, out, -1, 1,
            DMODEL, DINNER, DINNER, DMODEL);
    }
}

// round 3
// speedup vs baseline: 1.8909x; 1.2219x over previous
#include <cuda_runtime.h>
#include <cuda_bf16.h>
#include <cstdint>

// ---------------------------------------------------------------------------
// BidirectionalMambaLayer: B=2, L=1024, D_MODEL=768, D_INNER=1536, D_STATE=16,
// DT_RANK=48, D_CONV=4.
// Round 3: dir-merged launches, register-prefetch GEMM mainloop, fused
// atomic out_proj, scan writes bwd output pre-flipped.
// ---------------------------------------------------------------------------

#define SEQL   1024
#define NB     2
#define MTOT   (NB * SEQL)     // 2048 rows (tokens)
#define DMODEL 768
#define DINNER 1536
#define DSTATE 16
#define DTRANK 48
#define DCONV  4
#define XZW    (2 * DINNER)    // 3072
#define XDBLW  (DTRANK + 2 * DSTATE)  // 80

// -------------------------- scratch (device globals) -----------------------
__device__ float g_xz   [2][(size_t)MTOT * XZW];    // in_proj output (u_raw | z)
__device__ float g_u    [2][(size_t)MTOT * DINNER]; // conv+silu output
__device__ float g_xdbl [2][(size_t)MTOT * XDBLW];  // (dt | B | C)
__device__ float g_delta[2][(size_t)MTOT * DINNER]; // softplus(dt @ dt_w + b)
__device__ float g_ypre [2][(size_t)MTOT * DINNER]; // gated scan output (dir1 pre-flipped)

enum { BUF_XZ = 0, BUF_U = 1, BUF_XDBL = 2, BUF_DELTA = 3, BUF_YPRE = 4 };

__device__ __forceinline__ float* scratch_ptr(int id, int dir) {
    switch (id) {
        case BUF_XZ:    return g_xz[dir];
        case BUF_U:     return g_u[dir];
        case BUF_XDBL:  return g_xdbl[dir];
        case BUF_DELTA: return g_delta[dir];
        case BUF_YPRE:  return g_ypre[dir];
    }
    return nullptr;
}

enum { ACT_NONE = 0, ACT_SOFTPLUS = 1 };

__device__ __forceinline__ float tf32r(float x) {
    uint32_t u;
    asm("cvt.rna.tf32.f32 %0, %1;" : "=r"(u) : "f"(x));
    return __uint_as_float(u);
}

// ---------------------------------------------------------------------------
// Tensor-core TN GEMM (tf32 mma.sync), dir-merged via blockIdx.z:
//   C_dir[M,N] (+)= act( A_dir[M,K] * W_dir[N,K]^T + bias_dir )
// BM=BN=128, BK=16, 256 threads (8 warps, 2m x 4n), warp tile 64x32,
// mma.m16n8k8.tf32.  Register-prefetch double buffering on the k-loop.
// FLIPA1: flip sequence index of A rows for dir==1 (m ^ 1023).
// ATOMIC: epilogue atomicAdd into shared C (zero-initialized by caller).
// ---------------------------------------------------------------------------
template<int ACT, bool FLIPA1, bool ATOMIC>
__global__ __launch_bounds__(256, 2)
void gemm_mma(const float* __restrict__ Aext, int aId,
              const float* __restrict__ W0, const float* __restrict__ W1,
              const float* __restrict__ bias0, const float* __restrict__ bias1,
              float* __restrict__ Cext, int cId,
              int N, int K, int lda, int ldc)
{
    const int dir = blockIdx.z;
    const float* A    = Aext ? Aext : scratch_ptr(aId, dir);
    const float* W    = dir ? W1 : W0;
    const float* bias = dir ? bias1 : bias0;
    float*       C    = Cext ? Cext : scratch_ptr(cId, dir);

    __shared__ float sA[16][132];   // [k][m], tf32-rounded
    __shared__ float sB[16][132];   // [k][n], tf32-rounded

    const int bm   = blockIdx.y * 128;
    const int bn   = blockIdx.x * 128;
    const int tid  = threadIdx.x;
    const int lane = tid & 31;
    const int warp = tid >> 5;
    const int wm   = warp >> 2;       // 0..1  (m)
    const int wn   = warp & 3;        // 0..3  (n)
    const int gr   = lane >> 2;       // 0..7
    const int tq   = lane & 3;        // 0..3

    // cooperative-load geometry: thread owns rows (tid>>2) and 64+(tid>>2),
    // k-quad kq = (tid&3)*4, for both A and W tiles.
    const int lrow0 = tid >> 2;          // 0..63
    const int lrow1 = lrow0 + 64;        // 64..127
    const int kq    = (tid & 3) * 4;     // 0,4,8,12

    int gm0 = bm + lrow0;
    int gm1 = bm + lrow1;
    if (FLIPA1 && dir) { gm0 ^= (SEQL - 1); gm1 ^= (SEQL - 1); }
    const int wr0 = bn + lrow0;
    const int wr1 = bn + lrow1;
    const bool wv0ok = (wr0 < N);
    const bool wv1ok = (wr1 < N);

    float acc[4][4][4];
#pragma unroll
    for (int mt = 0; mt < 4; mt++)
#pragma unroll
        for (int nt = 0; nt < 4; nt++)
#pragma unroll
            for (int r = 0; r < 4; r++) acc[mt][nt][r] = 0.f;

    // prefetch first tile into registers
    float4 pa0, pa1, pw0, pw1;
    {
        pa0 = *(const float4*)(A + (size_t)gm0 * lda + kq);
        pa1 = *(const float4*)(A + (size_t)gm1 * lda + kq);
        pw0 = wv0ok ? *(const float4*)(W + (size_t)wr0 * K + kq)
                    : make_float4(0.f, 0.f, 0.f, 0.f);
        pw1 = wv1ok ? *(const float4*)(W + (size_t)wr1 * K + kq)
                    : make_float4(0.f, 0.f, 0.f, 0.f);
    }

    for (int k0 = 0; k0 < K; k0 += 16) {
        // store prefetched tile to smem (tf32-rounded)
        sA[kq + 0][lrow0] = tf32r(pa0.x);
        sA[kq + 1][lrow0] = tf32r(pa0.y);
        sA[kq + 2][lrow0] = tf32r(pa0.z);
        sA[kq + 3][lrow0] = tf32r(pa0.w);
        sA[kq + 0][lrow1] = tf32r(pa1.x);
        sA[kq + 1][lrow1] = tf32r(pa1.y);
        sA[kq + 2][lrow1] = tf32r(pa1.z);
        sA[kq + 3][lrow1] = tf32r(pa1.w);
        sB[kq + 0][lrow0] = tf32r(pw0.x);
        sB[kq + 1][lrow0] = tf32r(pw0.y);
        sB[kq + 2][lrow0] = tf32r(pw0.z);
        sB[kq + 3][lrow0] = tf32r(pw0.w);
        sB[kq + 0][lrow1] = tf32r(pw1.x);
        sB[kq + 1][lrow1] = tf32r(pw1.y);
        sB[kq + 2][lrow1] = tf32r(pw1.z);
        sB[kq + 3][lrow1] = tf32r(pw1.w);
        __syncthreads();

        // issue next tile's gmem loads; they drain behind the MMA compute
        if (k0 + 16 < K) {
            const int kn = k0 + 16 + kq;
            pa0 = *(const float4*)(A + (size_t)gm0 * lda + kn);
            pa1 = *(const float4*)(A + (size_t)gm1 * lda + kn);
            if (wv0ok) pw0 = *(const float4*)(W + (size_t)wr0 * K + kn);
            if (wv1ok) pw1 = *(const float4*)(W + (size_t)wr1 * K + kn);
        }

#pragma unroll
        for (int ks = 0; ks < 2; ks++) {
            const int kb = ks * 8;
            uint32_t a[4][4], b[4][2];
#pragma unroll
            for (int mt = 0; mt < 4; mt++) {
                const int m0 = wm * 64 + mt * 16 + gr;
                a[mt][0] = __float_as_uint(sA[kb + tq][m0]);
                a[mt][1] = __float_as_uint(sA[kb + tq][m0 + 8]);
                a[mt][2] = __float_as_uint(sA[kb + tq + 4][m0]);
                a[mt][3] = __float_as_uint(sA[kb + tq + 4][m0 + 8]);
            }
#pragma unroll
            for (int nt = 0; nt < 4; nt++) {
                const int n0 = wn * 32 + nt * 8 + gr;
                b[nt][0] = __float_as_uint(sB[kb + tq][n0]);
                b[nt][1] = __float_as_uint(sB[kb + tq + 4][n0]);
            }
#pragma unroll
            for (int mt = 0; mt < 4; mt++)
#pragma unroll
                for (int nt = 0; nt < 4; nt++) {
                    asm volatile(
                        "mma.sync.aligned.m16n8k8.row.col.f32.tf32.tf32.f32 "
                        "{%0,%1,%2,%3}, {%4,%5,%6,%7}, {%8,%9}, {%0,%1,%2,%3};"
                        : "+f"(acc[mt][nt][0]), "+f"(acc[mt][nt][1]),
                          "+f"(acc[mt][nt][2]), "+f"(acc[mt][nt][3])
                        : "r"(a[mt][0]), "r"(a[mt][1]), "r"(a[mt][2]), "r"(a[mt][3]),
                          "r"(b[nt][0]), "r"(b[nt][1]));
                }
        }
        __syncthreads();
    }

    // epilogue
#pragma unroll
    for (int mt = 0; mt < 4; mt++) {
        const int m0 = bm + wm * 64 + mt * 16 + gr;
#pragma unroll
        for (int half = 0; half < 2; half++) {
            const int m = m0 + half * 8;
#pragma unroll
            for (int nt = 0; nt < 4; nt++) {
                const int nbase = bn + wn * 32 + nt * 8 + 2 * tq;
#pragma unroll
                for (int j = 0; j < 2; j++) {
                    const int n = nbase + j;
                    if (n < N) {
                        float v = acc[mt][nt][half * 2 + j];
                        if (bias) v += bias[n];
                        if (ACT == ACT_SOFTPLUS)
                            v = (v > 20.f) ? v : log1pf(__expf(v));
                        if (ATOMIC) atomicAdd(&C[(size_t)m * ldc + n], v);
                        else        C[(size_t)m * ldc + n] = v;
                    }
                }
            }
        }
    }
}

// ---------------------------------------------------------------------------
// Causal depthwise conv (D_CONV=4) + bias + SiLU. dirs merged on blockIdx.y.
// ---------------------------------------------------------------------------
__global__ void conv_silu_kernel(const float* __restrict__ f_conv_w,
                                 const float* __restrict__ f_conv_b,
                                 const float* __restrict__ b_conv_w,
                                 const float* __restrict__ b_conv_b)
{
    const int dir = blockIdx.y;
    const float* conv_w = dir ? b_conv_w : f_conv_w;
    const float* conv_b = dir ? b_conv_b : f_conv_b;

    int idx = blockIdx.x * blockDim.x + threadIdx.x;
    if (idx >= MTOT * DINNER) return;
    int row = idx / DINNER;
    int d   = idx - row * DINNER;
    int l   = row & (SEQL - 1);

    const float* xz = g_xz[dir];
    float s = conv_b[d];
#pragma unroll
    for (int k = 0; k < DCONV; k++) {
        int ls = l - (DCONV - 1) + k;
        if (ls >= 0)
            s = fmaf(conv_w[d * DCONV + k],
                     xz[(size_t)(row - (DCONV - 1) + k) * XZW + d], s);
    }
    g_u[dir][idx] = s / (1.f + __expf(-s));
}

// ---------------------------------------------------------------------------
// Selective scan. One warp = 2 channels; 16 lanes = 16 states per channel.
// dir1 writes its output with the sequence index flipped so that downstream
// out_proj needs no row flip.
// ---------------------------------------------------------------------------
__global__ __launch_bounds__(256)
void scan_kernel(const float* __restrict__ fAlog, const float* __restrict__ fD,
                 const float* __restrict__ bAlog, const float* __restrict__ bD)
{
    const int dir = blockIdx.y;
    const float* Alog = dir ? bAlog : fAlog;
    const float* Dp   = dir ? bD    : fD;
    const float* delta = g_delta[dir];
    const float* u     = g_u[dir];
    const float* xdbl  = g_xdbl[dir];
    const float* xz    = g_xz[dir];
    float*       ypre  = g_ypre[dir];

    const int lane = threadIdx.x & 31;
    const int warp = threadIdx.x >> 5;
    const int half = lane >> 4;
    const int n    = lane & 15;

    const int c = blockIdx.x * 16 + warp * 2 + half;  // 0..3071
    const int b = c / DINNER;
    const int d = c - b * DINNER;

    const float Aneg = -__expf(Alog[d * DSTATE + n]);
    const float Dd   = Dp[d];

    float h = 0.f;
    const size_t rowbase = (size_t)b * SEQL;

    for (int l = 0; l < SEQL; l++) {
        const size_t row = rowbase + l;
        const float dl = delta[row * DINNER + d];
        const float uu = u[row * DINNER + d];
        const float Bn = xdbl[row * XDBLW + DTRANK + n];
        const float Cn = xdbl[row * XDBLW + DTRANK + DSTATE + n];

        const float dA = __expf(dl * Aneg);
        h = fmaf(dA, h, dl * Bn * uu);

        float yp = h * Cn;
        yp += __shfl_xor_sync(0xffffffffu, yp, 1);
        yp += __shfl_xor_sync(0xffffffffu, yp, 2);
        yp += __shfl_xor_sync(0xffffffffu, yp, 4);
        yp += __shfl_xor_sync(0xffffffffu, yp, 8);

        if (n == 0) {
            const float zz = xz[row * XZW + DINNER + d];
            float y = fmaf(uu, Dd, yp);
            y *= zz / (1.f + __expf(-zz));
            const size_t orow = dir ? (row ^ (SEQL - 1)) : row;  // pre-flip bwd
            ypre[orow * DINNER + d] = y;
        }
    }
}

// ---------------------------------------------------------------------------
// Zero an external buffer (for atomic-accumulate epilogues).
// ---------------------------------------------------------------------------
__global__ void zero_kernel(float* __restrict__ p, int n)
{
    int i = blockIdx.x * blockDim.x + threadIdx.x;
    if (i < n) p[i] = 0.f;
}

// ---------------------------------------------------------------------------
// Host launch.  Inputs: x, then f_{in_w,conv_w,conv_b,xproj_w,dt_w,dt_b,
// Alog,D,out_w}, then b_{...}.
// ---------------------------------------------------------------------------
extern "C" void kernel_launch(void* const* d_in, const int* in_sizes, int n_in,
                              void* d_out, int out_size)
{
    const float* x = (const float*)d_in[0];
    float* out = (float*)d_out;

    const float* f_in_w    = (const float*)d_in[1];
    const float* f_conv_w  = (const float*)d_in[2];
    const float* f_conv_b  = (const float*)d_in[3];
    const float* f_xproj_w = (const float*)d_in[4];
    const float* f_dt_w    = (const float*)d_in[5];
    const float* f_dt_b    = (const float*)d_in[6];
    const float* f_Alog    = (const float*)d_in[7];
    const float* f_D       = (const float*)d_in[8];
    const float* f_out_w   = (const float*)d_in[9];
    const float* b_in_w    = (const float*)d_in[10];
    const float* b_conv_w  = (const float*)d_in[11];
    const float* b_conv_b  = (const float*)d_in[12];
    const float* b_xproj_w = (const float*)d_in[13];
    const float* b_dt_w    = (const float*)d_in[14];
    const float* b_dt_b    = (const float*)d_in[15];
    const float* b_Alog    = (const float*)d_in[16];
    const float* b_D       = (const float*)d_in[17];
    const float* b_out_w   = (const float*)d_in[18];

    // zero output early (atomic out_proj accumulates into it)
    zero_kernel<<<(MTOT * DMODEL + 255) / 256, 256>>>(out, MTOT * DMODEL);

    // in_proj (both dirs): xz = x(flip for dir1) @ in_w^T   [2048,3072]
    gemm_mma<ACT_NONE, true, false><<<dim3(XZW / 128, MTOT / 128, 2), 256>>>(
        x, -1, f_in_w, b_in_w, nullptr, nullptr,
        nullptr, BUF_XZ, XZW, DMODEL, DMODEL, XZW);

    // depthwise conv + SiLU (both dirs)
    conv_silu_kernel<<<dim3((MTOT * DINNER + 255) / 256, 2), 256>>>(
        f_conv_w, f_conv_b, b_conv_w, b_conv_b);

    // x_proj (both dirs): xdbl = u @ xproj_w^T   [2048,80]
    gemm_mma<ACT_NONE, false, false><<<dim3(1, MTOT / 128, 2), 256>>>(
        nullptr, BUF_U, f_xproj_w, b_xproj_w, nullptr, nullptr,
        nullptr, BUF_XDBL, XDBLW, DINNER, DINNER, XDBLW);

    // delta (both dirs): softplus(xdbl[:, :48] @ dt_w^T + dt_b)   [2048,1536]
    gemm_mma<ACT_SOFTPLUS, false, false><<<dim3(DINNER / 128, MTOT / 128, 2), 256>>>(
        nullptr, BUF_XDBL, f_dt_w, b_dt_w, f_dt_b, b_dt_b,
        nullptr, BUF_DELTA, DINNER, DTRANK, XDBLW, DINNER);

    // selective scan (both dirs; dir1 output pre-flipped)
    scan_kernel<<<dim3((NB * DINNER) / 16, 2), 256>>>(f_Alog, f_D, b_Alog, b_D);

    // out_proj fused (both dirs): out += ypre_dir @ out_w_dir^T  (atomic)
    gemm_mma<ACT_NONE, false, true><<<dim3(DMODEL / 128, MTOT / 128, 2), 256>>>(
        nullptr, BUF_YPRE, f_out_w, b_out_w, nullptr, nullptr,
        out, -1, DMODEL, DINNER, DINNER, DMODEL);
}

// round 4
// speedup vs baseline: 2.1235x; 1.1230x over previous
#include <cuda_runtime.h>
#include <cuda_bf16.h>
#include <cstdint>

// ---------------------------------------------------------------------------
// BidirectionalMambaLayer: B=2, L=1024, D_MODEL=768, D_INNER=1536, D_STATE=16,
// DT_RANK=48, D_CONV=4.
// Round 4: cp.async 2-stage pipelined tf32 mma GEMM, split-K for small-N
// GEMMs, dir-merged launches, fused atomic out_proj.
// ---------------------------------------------------------------------------

#define SEQL   1024
#define NB     2
#define MTOT   (NB * SEQL)     // 2048 rows (tokens)
#define DMODEL 768
#define DINNER 1536
#define DSTATE 16
#define DTRANK 48
#define DCONV  4
#define XZW    (2 * DINNER)    // 3072
#define XDBLW  (DTRANK + 2 * DSTATE)  // 80

#define SAS 20   // smem row stride (floats): 16 + 4 pad, conflict-free frags

// -------------------------- scratch (device globals) -----------------------
__device__ float g_xz   [2][(size_t)MTOT * XZW];
__device__ float g_u    [2][(size_t)MTOT * DINNER];
__device__ float g_xdbl [2][(size_t)MTOT * XDBLW];
__device__ float g_delta[2][(size_t)MTOT * DINNER];
__device__ float g_ypre [2][(size_t)MTOT * DINNER];

enum { BUF_XZ = 0, BUF_U = 1, BUF_XDBL = 2, BUF_DELTA = 3, BUF_YPRE = 4 };

__device__ __forceinline__ float* scratch_ptr(int id, int dir) {
    switch (id) {
        case BUF_XZ:    return g_xz[dir];
        case BUF_U:     return g_u[dir];
        case BUF_XDBL:  return g_xdbl[dir];
        case BUF_DELTA: return g_delta[dir];
        case BUF_YPRE:  return g_ypre[dir];
    }
    return nullptr;
}

enum { ACT_NONE = 0, ACT_SOFTPLUS = 1 };

__device__ __forceinline__ float tf32r(float x) {
    uint32_t u;
    asm("cvt.rna.tf32.f32 %0, %1;" : "=r"(u) : "f"(x));
    return __uint_as_float(u);
}
__device__ __forceinline__ uint32_t tf32u(float x) {
    uint32_t u;
    asm("cvt.rna.tf32.f32 %0, %1;" : "=r"(u) : "f"(x));
    return u;
}

__device__ __forceinline__ void cp16(uint32_t saddr, const float* gptr, bool ok) {
    int sz = ok ? 16 : 0;   // zfill when out of bounds
    asm volatile("cp.async.cg.shared.global [%0], [%1], 16, %2;"
                 :: "r"(saddr), "l"(gptr), "r"(sz));
}
__device__ __forceinline__ void cp_commit() {
    asm volatile("cp.async.commit_group;");
}
__device__ __forceinline__ void cp_wait0() {
    asm volatile("cp.async.wait_group 0;");
}

// ---------------------------------------------------------------------------
// Tensor-core TN GEMM (tf32 mma.sync), dir-merged via blockIdx.z, optional
// split-K via blockIdx.x = split * nxt + ntile:
//   C_dir[M,N] (+)= act( A_dir[M, kbeg:kend] * W_dir[N, kbeg:kend]^T + bias )
// BM=BN=128, BK=16, 256 threads (8 warps, 2m x 4n), warp tile 64x32,
// mma.m16n8k8.tf32.  2-stage cp.async smem pipeline, one sync per k-tile.
// FLIPA1: flip sequence index of A rows for dir==1 (m ^ 1023).
// ATOMIC: epilogue atomicAdd (required when split-K > 1).
// ---------------------------------------------------------------------------
template<int ACT, bool FLIPA1, bool ATOMIC>
__global__ __launch_bounds__(256, 2)
void gemm_mma(const float* __restrict__ Aext, int aId,
              const float* __restrict__ W0, const float* __restrict__ W1,
              const float* __restrict__ bias0, const float* __restrict__ bias1,
              float* __restrict__ Cext, int cId,
              int N, int K, int lda, int ldc, int nxt, int kchunk)
{
    const int dir = blockIdx.z;
    const float* A    = Aext ? Aext : scratch_ptr(aId, dir);
    const float* W    = dir ? W1 : W0;
    const float* bias = dir ? bias1 : bias0;
    float*       C    = Cext ? Cext : scratch_ptr(cId, dir);

    const int split = blockIdx.x / nxt;
    const int bn    = (blockIdx.x - split * nxt) * 128;
    const int bm    = blockIdx.y * 128;
    const int kbeg  = split * kchunk;
    const int kend  = (kbeg + kchunk < K) ? (kbeg + kchunk) : K;
    const int T     = (kend - kbeg) >> 4;      // k-tiles of 16

    __shared__ float sA[2][128 * SAS];
    __shared__ float sB[2][128 * SAS];

    const int tid  = threadIdx.x;
    const int lane = tid & 31;
    const int warp = tid >> 5;
    const int wm   = warp >> 2;       // 0..1
    const int wn   = warp & 3;        // 0..3
    const int gr   = lane >> 2;       // 0..7
    const int tq   = lane & 3;        // 0..3

    // cooperative-load geometry: thread owns rows tid>>2 and 64+(tid>>2),
    // 16B chunk kq = (tid&3)*4.
    const int lrow0 = tid >> 2;
    const int lrow1 = lrow0 + 64;
    const int kq    = (tid & 3) * 4;

    int gm0 = bm + lrow0;
    int gm1 = bm + lrow1;
    if (FLIPA1 && dir) { gm0 ^= (SEQL - 1); gm1 ^= (SEQL - 1); }
    const int wr0 = bn + lrow0;
    const int wr1 = bn + lrow1;
    const bool wok0 = (wr0 < N);
    const bool wok1 = (wr1 < N);

    const uint32_t sA0 = (uint32_t)__cvta_generic_to_shared(&sA[0][0]);
    const uint32_t sB0 = (uint32_t)__cvta_generic_to_shared(&sB[0][0]);
    const uint32_t stage_bytes = 128 * SAS * 4;
    const uint32_t offA0 = (lrow0 * SAS + kq) * 4;
    const uint32_t offA1 = (lrow1 * SAS + kq) * 4;

    const float* gA0 = A + (size_t)gm0 * lda + kbeg + kq;
    const float* gA1 = A + (size_t)gm1 * lda + kbeg + kq;
    const float* gW0 = W + (size_t)wr0 * K + kbeg + kq;
    const float* gW1 = W + (size_t)wr1 * K + kbeg + kq;

    float acc[4][4][4];
#pragma unroll
    for (int mt = 0; mt < 4; mt++)
#pragma unroll
        for (int nt = 0; nt < 4; nt++)
#pragma unroll
            for (int r = 0; r < 4; r++) acc[mt][nt][r] = 0.f;

    // prologue: issue tile 0 into stage 0
    {
        cp16(sA0 + offA0, gA0, true);
        cp16(sA0 + offA1, gA1, true);
        cp16(sB0 + offA0, gW0, wok0);
        cp16(sB0 + offA1, gW1, wok1);
        cp_commit();
    }

    for (int t = 0; t < T; t++) {
        const int st = t & 1;
        cp_wait0();
        __syncthreads();

        if (t + 1 < T) {
            const int stn = st ^ 1;
            const int ko  = (t + 1) * 16;
            cp16(sA0 + stn * stage_bytes + offA0, gA0 + ko, true);
            cp16(sA0 + stn * stage_bytes + offA1, gA1 + ko, true);
            cp16(sB0 + stn * stage_bytes + offA0, gW0 + ko, wok0);
            cp16(sB0 + stn * stage_bytes + offA1, gW1 + ko, wok1);
            cp_commit();
        }

        const float* cA = &sA[st][0];
        const float* cB = &sB[st][0];
#pragma unroll
        for (int ks = 0; ks < 2; ks++) {
            const int kb = ks * 8;
            uint32_t a[4][4], b[4][2];
#pragma unroll
            for (int mt = 0; mt < 4; mt++) {
                const int m0 = wm * 64 + mt * 16 + gr;
                a[mt][0] = tf32u(cA[m0 * SAS + kb + tq]);
                a[mt][1] = tf32u(cA[(m0 + 8) * SAS + kb + tq]);
                a[mt][2] = tf32u(cA[m0 * SAS + kb + tq + 4]);
                a[mt][3] = tf32u(cA[(m0 + 8) * SAS + kb + tq + 4]);
            }
#pragma unroll
            for (int nt = 0; nt < 4; nt++) {
                const int n0 = wn * 32 + nt * 8 + gr;
                b[nt][0] = tf32u(cB[n0 * SAS + kb + tq]);
                b[nt][1] = tf32u(cB[n0 * SAS + kb + tq + 4]);
            }
#pragma unroll
            for (int mt = 0; mt < 4; mt++)
#pragma unroll
                for (int nt = 0; nt < 4; nt++) {
                    asm volatile(
                        "mma.sync.aligned.m16n8k8.row.col.f32.tf32.tf32.f32 "
                        "{%0,%1,%2,%3}, {%4,%5,%6,%7}, {%8,%9}, {%0,%1,%2,%3};"
                        : "+f"(acc[mt][nt][0]), "+f"(acc[mt][nt][1]),
                          "+f"(acc[mt][nt][2]), "+f"(acc[mt][nt][3])
                        : "r"(a[mt][0]), "r"(a[mt][1]), "r"(a[mt][2]), "r"(a[mt][3]),
                          "r"(b[nt][0]), "r"(b[nt][1]));
                }
        }
        __syncthreads();
    }

    // epilogue
#pragma unroll
    for (int mt = 0; mt < 4; mt++) {
        const int m0 = bm + wm * 64 + mt * 16 + gr;
#pragma unroll
        for (int half = 0; half < 2; half++) {
            const int m = m0 + half * 8;
#pragma unroll
            for (int nt = 0; nt < 4; nt++) {
                const int nbase = bn + wn * 32 + nt * 8 + 2 * tq;
#pragma unroll
                for (int j = 0; j < 2; j++) {
                    const int n = nbase + j;
                    if (n < N) {
                        float v = acc[mt][nt][half * 2 + j];
                        if (bias) v += bias[n];
                        if (ACT == ACT_SOFTPLUS)
                            v = (v > 20.f) ? v : log1pf(__expf(v));
                        if (ATOMIC) atomicAdd(&C[(size_t)m * ldc + n], v);
                        else        C[(size_t)m * ldc + n] = v;
                    }
                }
            }
        }
    }
}

// ---------------------------------------------------------------------------
// Causal depthwise conv (D_CONV=4) + bias + SiLU. dirs merged on blockIdx.y.
// ---------------------------------------------------------------------------
__global__ void conv_silu_kernel(const float* __restrict__ f_conv_w,
                                 const float* __restrict__ f_conv_b,
                                 const float* __restrict__ b_conv_w,
                                 const float* __restrict__ b_conv_b)
{
    const int dir = blockIdx.y;
    const float* conv_w = dir ? b_conv_w : f_conv_w;
    const float* conv_b = dir ? b_conv_b : f_conv_b;

    int idx = blockIdx.x * blockDim.x + threadIdx.x;
    if (idx >= MTOT * DINNER) return;
    int row = idx / DINNER;
    int d   = idx - row * DINNER;
    int l   = row & (SEQL - 1);

    const float* xz = g_xz[dir];
    float s = conv_b[d];
#pragma unroll
    for (int k = 0; k < DCONV; k++) {
        int ls = l - (DCONV - 1) + k;
        if (ls >= 0)
            s = fmaf(conv_w[d * DCONV + k],
                     xz[(size_t)(row - (DCONV - 1) + k) * XZW + d], s);
    }
    g_u[dir][idx] = s / (1.f + __expf(-s));
}

// ---------------------------------------------------------------------------
// Selective scan. One warp = 2 channels; 16 lanes = 16 states per channel.
// dir1 output written with flipped sequence index.
// ---------------------------------------------------------------------------
__global__ __launch_bounds__(256)
void scan_kernel(const float* __restrict__ fAlog, const float* __restrict__ fD,
                 const float* __restrict__ bAlog, const float* __restrict__ bD)
{
    const int dir = blockIdx.y;
    const float* Alog = dir ? bAlog : fAlog;
    const float* Dp   = dir ? bD    : fD;
    const float* delta = g_delta[dir];
    const float* u     = g_u[dir];
    const float* xdbl  = g_xdbl[dir];
    const float* xz    = g_xz[dir];
    float*       ypre  = g_ypre[dir];

    const int lane = threadIdx.x & 31;
    const int warp = threadIdx.x >> 5;
    const int half = lane >> 4;
    const int n    = lane & 15;

    const int c = blockIdx.x * 16 + warp * 2 + half;  // 0..3071
    const int b = c / DINNER;
    const int d = c - b * DINNER;

    const float Aneg = -__expf(Alog[d * DSTATE + n]);
    const float Dd   = Dp[d];

    float h = 0.f;
    const size_t rowbase = (size_t)b * SEQL;

    for (int l = 0; l < SEQL; l++) {
        const size_t row = rowbase + l;
        const float dl = delta[row * DINNER + d];
        const float uu = u[row * DINNER + d];
        const float Bn = xdbl[row * XDBLW + DTRANK + n];
        const float Cn = xdbl[row * XDBLW + DTRANK + DSTATE + n];

        const float dA = __expf(dl * Aneg);
        h = fmaf(dA, h, dl * Bn * uu);

        float yp = h * Cn;
        yp += __shfl_xor_sync(0xffffffffu, yp, 1);
        yp += __shfl_xor_sync(0xffffffffu, yp, 2);
        yp += __shfl_xor_sync(0xffffffffu, yp, 4);
        yp += __shfl_xor_sync(0xffffffffu, yp, 8);

        if (n == 0) {
            const float zz = xz[row * XZW + DINNER + d];
            float y = fmaf(uu, Dd, yp);
            y *= zz / (1.f + __expf(-zz));
            const size_t orow = dir ? (row ^ (SEQL - 1)) : row;
            ypre[orow * DINNER + d] = y;
        }
    }
}

// ---------------------------------------------------------------------------
// Zeroing kernels (for atomic / split-K accumulation targets).
// ---------------------------------------------------------------------------
__global__ void zero_kernel(float* __restrict__ p, int n)
{
    int i = blockIdx.x * blockDim.x + threadIdx.x;
    if (i < n) p[i] = 0.f;
}
__global__ void zero_scratch_kernel(int id, int n)
{
    float* p = scratch_ptr(id, blockIdx.y);
    int i = blockIdx.x * blockDim.x + threadIdx.x;
    if (i < n) p[i] = 0.f;
}

// ---------------------------------------------------------------------------
// Host launch.
// ---------------------------------------------------------------------------
extern "C" void kernel_launch(void* const* d_in, const int* in_sizes, int n_in,
                              void* d_out, int out_size)
{
    const float* x = (const float*)d_in[0];
    float* out = (float*)d_out;

    const float* f_in_w    = (const float*)d_in[1];
    const float* f_conv_w  = (const float*)d_in[2];
    const float* f_conv_b  = (const float*)d_in[3];
    const float* f_xproj_w = (const float*)d_in[4];
    const float* f_dt_w    = (const float*)d_in[5];
    const float* f_dt_b    = (const float*)d_in[6];
    const float* f_Alog    = (const float*)d_in[7];
    const float* f_D       = (const float*)d_in[8];
    const float* f_out_w   = (const float*)d_in[9];
    const float* b_in_w    = (const float*)d_in[10];
    const float* b_conv_w  = (const float*)d_in[11];
    const float* b_conv_b  = (const float*)d_in[12];
    const float* b_xproj_w = (const float*)d_in[13];
    const float* b_dt_w    = (const float*)d_in[14];
    const float* b_dt_b    = (const float*)d_in[15];
    const float* b_Alog    = (const float*)d_in[16];
    const float* b_D       = (const float*)d_in[17];
    const float* b_out_w   = (const float*)d_in[18];

    // zero accumulation targets (out, xdbl)
    zero_kernel<<<(MTOT * DMODEL + 255) / 256, 256>>>(out, MTOT * DMODEL);
    zero_scratch_kernel<<<dim3((MTOT * XDBLW + 255) / 256, 2), 256>>>(
        BUF_XDBL, MTOT * XDBLW);

    // in_proj (both dirs): xz = x(flip for dir1) @ in_w^T   [2048,3072]
    gemm_mma<ACT_NONE, true, false><<<dim3(XZW / 128, MTOT / 128, 2), 256>>>(
        x, -1, f_in_w, b_in_w, nullptr, nullptr,
        nullptr, BUF_XZ, XZW, DMODEL, DMODEL, XZW, XZW / 128, DMODEL);

    // depthwise conv + SiLU (both dirs)
    conv_silu_kernel<<<dim3((MTOT * DINNER + 255) / 256, 2), 256>>>(
        f_conv_w, f_conv_b, b_conv_w, b_conv_b);

    // x_proj (both dirs), split-K x8: xdbl += u @ xproj_w^T   [2048,80]
    gemm_mma<ACT_NONE, false, true><<<dim3(8, MTOT / 128, 2), 256>>>(
        nullptr, BUF_U, f_xproj_w, b_xproj_w, nullptr, nullptr,
        nullptr, BUF_XDBL, XDBLW, DINNER, DINNER, XDBLW, 1, DINNER / 8);

    // delta (both dirs): softplus(xdbl[:, :48] @ dt_w^T + dt_b)   [2048,1536]
    gemm_mma<ACT_SOFTPLUS, false, false><<<dim3(DINNER / 128, MTOT / 128, 2), 256>>>(
        nullptr, BUF_XDBL, f_dt_w, b_dt_w, f_dt_b, b_dt_b,
        nullptr, BUF_DELTA, DINNER, DTRANK, XDBLW, DINNER, DINNER / 128, DTRANK);

    // selective scan (both dirs; dir1 output pre-flipped)
    scan_kernel<<<dim3((NB * DINNER) / 16, 2), 256>>>(f_Alog, f_D, b_Alog, b_D);

    // out_proj fused (both dirs), split-K x2: out += ypre @ out_w^T (atomic)
    gemm_mma<ACT_NONE, false, true><<<dim3((DMODEL / 128) * 2, MTOT / 128, 2), 256>>>(
        nullptr, BUF_YPRE, f_out_w, b_out_w, nullptr, nullptr,
        out, -1, DMODEL, DINNER, DINNER, DMODEL, DMODEL / 128, DINNER / 2);
}

// round 5
// speedup vs baseline: 3.3020x; 1.5550x over previous
#include <cuda_runtime.h>
#include <cuda_bf16.h>
#include <cstdint>

// ---------------------------------------------------------------------------
// BidirectionalMambaLayer: B=2, L=1024, D_MODEL=768, D_INNER=1536, D_STATE=16,
// DT_RANK=48, D_CONV=4.
// Round 5: 3-stage cp.async GEMM pipeline, software-pipelined scan loads,
// vectorized conv/zero. Same numerics as round 4.
// ---------------------------------------------------------------------------

#define SEQL   1024
#define NB     2
#define MTOT   (NB * SEQL)     // 2048 rows (tokens)
#define DMODEL 768
#define DINNER 1536
#define DSTATE 16
#define DTRANK 48
#define DCONV  4
#define XZW    (2 * DINNER)    // 3072
#define XDBLW  (DTRANK + 2 * DSTATE)  // 80

#define SAS    20   // smem row stride (floats): conflict-free fragment loads
#define STAGES 3

// -------------------------- scratch (device globals) -----------------------
__device__ float g_xz   [2][(size_t)MTOT * XZW];
__device__ float g_u    [2][(size_t)MTOT * DINNER];
__device__ float g_xdbl [2][(size_t)MTOT * XDBLW];
__device__ float g_delta[2][(size_t)MTOT * DINNER];
__device__ float g_ypre [2][(size_t)MTOT * DINNER];

enum { BUF_XZ = 0, BUF_U = 1, BUF_XDBL = 2, BUF_DELTA = 3, BUF_YPRE = 4 };

__device__ __forceinline__ float* scratch_ptr(int id, int dir) {
    switch (id) {
        case BUF_XZ:    return g_xz[dir];
        case BUF_U:     return g_u[dir];
        case BUF_XDBL:  return g_xdbl[dir];
        case BUF_DELTA: return g_delta[dir];
        case BUF_YPRE:  return g_ypre[dir];
    }
    return nullptr;
}

enum { ACT_NONE = 0, ACT_SOFTPLUS = 1 };

__device__ __forceinline__ uint32_t tf32u(float x) {
    uint32_t u;
    asm("cvt.rna.tf32.f32 %0, %1;" : "=r"(u) : "f"(x));
    return u;
}

__device__ __forceinline__ void cp16(uint32_t saddr, const float* gptr, bool ok) {
    int sz = ok ? 16 : 0;   // zfill when out of bounds
    asm volatile("cp.async.cg.shared.global [%0], [%1], 16, %2;"
                 :: "r"(saddr), "l"(gptr), "r"(sz));
}
__device__ __forceinline__ void cp_commit() {
    asm volatile("cp.async.commit_group;");
}
__device__ __forceinline__ void cp_wait1() {
    asm volatile("cp.async.wait_group 1;");
}
__device__ __forceinline__ void cp_wait0() {
    asm volatile("cp.async.wait_group 0;");
}

// ---------------------------------------------------------------------------
// Tensor-core TN GEMM (tf32 mma.sync), dir-merged via blockIdx.z, optional
// split-K via blockIdx.x = split * nxt + ntile:
//   C_dir[M,N] (+)= act( A_dir[M, kbeg:kend] * W_dir[N, kbeg:kend]^T + bias )
// BM=BN=128, BK=16, 256 threads (8 warps, 2m x 4n), warp tile 64x32,
// mma.m16n8k8.tf32.  3-stage cp.async pipeline (2 tiles in flight).
// ---------------------------------------------------------------------------
template<int ACT, bool FLIPA1, bool ATOMIC>
__global__ __launch_bounds__(256, 2)
void gemm_mma(const float* __restrict__ Aext, int aId,
              const float* __restrict__ W0, const float* __restrict__ W1,
              const float* __restrict__ bias0, const float* __restrict__ bias1,
              float* __restrict__ Cext, int cId,
              int N, int K, int lda, int ldc, int nxt, int kchunk)
{
    const int dir = blockIdx.z;
    const float* A    = Aext ? Aext : scratch_ptr(aId, dir);
    const float* W    = dir ? W1 : W0;
    const float* bias = dir ? bias1 : bias0;
    float*       C    = Cext ? Cext : scratch_ptr(cId, dir);

    const int split = blockIdx.x / nxt;
    const int bn    = (blockIdx.x - split * nxt) * 128;
    const int bm    = blockIdx.y * 128;
    const int kbeg  = split * kchunk;
    const int kend  = (kbeg + kchunk < K) ? (kbeg + kchunk) : K;
    const int T     = (kend - kbeg) >> 4;      // k-tiles of 16

    __shared__ float sA[STAGES][128 * SAS];
    __shared__ float sB[STAGES][128 * SAS];

    const int tid  = threadIdx.x;
    const int lane = tid & 31;
    const int warp = tid >> 5;
    const int wm   = warp >> 2;       // 0..1
    const int wn   = warp & 3;        // 0..3
    const int gr   = lane >> 2;       // 0..7
    const int tq   = lane & 3;        // 0..3

    const int lrow0 = tid >> 2;          // 0..63
    const int lrow1 = lrow0 + 64;        // 64..127
    const int kq    = (tid & 3) * 4;     // 0,4,8,12

    int gm0 = bm + lrow0;
    int gm1 = bm + lrow1;
    if (FLIPA1 && dir) { gm0 ^= (SEQL - 1); gm1 ^= (SEQL - 1); }
    const int wr0 = bn + lrow0;
    const int wr1 = bn + lrow1;
    const bool wok0 = (wr0 < N);
    const bool wok1 = (wr1 < N);

    const uint32_t sAb = (uint32_t)__cvta_generic_to_shared(&sA[0][0]);
    const uint32_t sBb = (uint32_t)__cvta_generic_to_shared(&sB[0][0]);
    const uint32_t stage_bytes = 128 * SAS * 4;
    const uint32_t offA0 = (lrow0 * SAS + kq) * 4;
    const uint32_t offA1 = (lrow1 * SAS + kq) * 4;

    const float* gA0 = A + (size_t)gm0 * lda + kbeg + kq;
    const float* gA1 = A + (size_t)gm1 * lda + kbeg + kq;
    const float* gW0 = W + (size_t)wr0 * K + kbeg + kq;
    const float* gW1 = W + (size_t)wr1 * K + kbeg + kq;

    float acc[4][4][4];
#pragma unroll
    for (int mt = 0; mt < 4; mt++)
#pragma unroll
        for (int nt = 0; nt < 4; nt++)
#pragma unroll
            for (int r = 0; r < 4; r++) acc[mt][nt][r] = 0.f;

    // prologue: issue tiles 0 and 1 into stages 0 and 1
    {
        cp16(sAb + offA0, gA0, true);
        cp16(sAb + offA1, gA1, true);
        cp16(sBb + offA0, gW0, wok0);
        cp16(sBb + offA1, gW1, wok1);
        cp_commit();
        if (T > 1) {
            cp16(sAb + stage_bytes + offA0, gA0 + 16, true);
            cp16(sAb + stage_bytes + offA1, gA1 + 16, true);
            cp16(sBb + stage_bytes + offA0, gW0 + 16, wok0);
            cp16(sBb + stage_bytes + offA1, gW1 + 16, wok1);
            cp_commit();
        }
    }

    int st = 0;
    for (int t = 0; t < T; t++) {
        if (t + 1 < T) cp_wait1();    // tile t complete, t+1 may fly
        else           cp_wait0();
        __syncthreads();              // stage (t+2)%3 free for rewrite

        if (t + 2 < T) {
            const int stn = (st + 2 >= STAGES) ? (st + 2 - STAGES) : (st + 2);
            const int ko  = (t + 2) * 16;
            cp16(sAb + stn * stage_bytes + offA0, gA0 + ko, true);
            cp16(sAb + stn * stage_bytes + offA1, gA1 + ko, true);
            cp16(sBb + stn * stage_bytes + offA0, gW0 + ko, wok0);
            cp16(sBb + stn * stage_bytes + offA1, gW1 + ko, wok1);
            cp_commit();
        }

        const float* cA = &sA[st][0];
        const float* cB = &sB[st][0];
#pragma unroll
        for (int ks = 0; ks < 2; ks++) {
            const int kb = ks * 8;
            uint32_t a[4][4], b[4][2];
#pragma unroll
            for (int mt = 0; mt < 4; mt++) {
                const int m0 = wm * 64 + mt * 16 + gr;
                a[mt][0] = tf32u(cA[m0 * SAS + kb + tq]);
                a[mt][1] = tf32u(cA[(m0 + 8) * SAS + kb + tq]);
                a[mt][2] = tf32u(cA[m0 * SAS + kb + tq + 4]);
                a[mt][3] = tf32u(cA[(m0 + 8) * SAS + kb + tq + 4]);
            }
#pragma unroll
            for (int nt = 0; nt < 4; nt++) {
                const int n0 = wn * 32 + nt * 8 + gr;
                b[nt][0] = tf32u(cB[n0 * SAS + kb + tq]);
                b[nt][1] = tf32u(cB[n0 * SAS + kb + tq + 4]);
            }
#pragma unroll
            for (int mt = 0; mt < 4; mt++)
#pragma unroll
                for (int nt = 0; nt < 4; nt++) {
                    asm volatile(
                        "mma.sync.aligned.m16n8k8.row.col.f32.tf32.tf32.f32 "
                        "{%0,%1,%2,%3}, {%4,%5,%6,%7}, {%8,%9}, {%0,%1,%2,%3};"
                        : "+f"(acc[mt][nt][0]), "+f"(acc[mt][nt][1]),
                          "+f"(acc[mt][nt][2]), "+f"(acc[mt][nt][3])
                        : "r"(a[mt][0]), "r"(a[mt][1]), "r"(a[mt][2]), "r"(a[mt][3]),
                          "r"(b[nt][0]), "r"(b[nt][1]));
                }
        }
        st = (st + 1 >= STAGES) ? 0 : (st + 1);
    }

    // epilogue
#pragma unroll
    for (int mt = 0; mt < 4; mt++) {
        const int m0 = bm + wm * 64 + mt * 16 + gr;
#pragma unroll
        for (int half = 0; half < 2; half++) {
            const int m = m0 + half * 8;
#pragma unroll
            for (int nt = 0; nt < 4; nt++) {
                const int nbase = bn + wn * 32 + nt * 8 + 2 * tq;
#pragma unroll
                for (int j = 0; j < 2; j++) {
                    const int n = nbase + j;
                    if (n < N) {
                        float v = acc[mt][nt][half * 2 + j];
                        if (bias) v += bias[n];
                        if (ACT == ACT_SOFTPLUS)
                            v = (v > 20.f) ? v : log1pf(__expf(v));
                        if (ATOMIC) atomicAdd(&C[(size_t)m * ldc + n], v);
                        else        C[(size_t)m * ldc + n] = v;
                    }
                }
            }
        }
    }
}

// ---------------------------------------------------------------------------
// Causal depthwise conv (D_CONV=4) + bias + SiLU, float4-vectorized
// (4 consecutive channels per thread). dirs merged on blockIdx.y.
// ---------------------------------------------------------------------------
__global__ void conv_silu_kernel(const float* __restrict__ f_conv_w,
                                 const float* __restrict__ f_conv_b,
                                 const float* __restrict__ b_conv_w,
                                 const float* __restrict__ b_conv_b)
{
    const int dir = blockIdx.y;
    const float* conv_w = dir ? b_conv_w : f_conv_w;
    const float* conv_b = dir ? b_conv_b : f_conv_b;

    int idx = blockIdx.x * blockDim.x + threadIdx.x;   // over MTOT*DINNER/4
    if (idx >= MTOT * DINNER / 4) return;
    const int row = idx / (DINNER / 4);
    const int d4  = (idx - row * (DINNER / 4)) * 4;
    const int l   = row & (SEQL - 1);

    const float* xz = g_xz[dir];
    float4 s = *(const float4*)(conv_b + d4);
#pragma unroll
    for (int k = 0; k < DCONV; k++) {
        const int ls = l - (DCONV - 1) + k;
        if (ls >= 0) {
            const float4 xv = *(const float4*)(xz +
                (size_t)(row - (DCONV - 1) + k) * XZW + d4);
            // conv_w layout [DINNER][DCONV]
            s.x = fmaf(conv_w[(d4 + 0) * DCONV + k], xv.x, s.x);
            s.y = fmaf(conv_w[(d4 + 1) * DCONV + k], xv.y, s.y);
            s.z = fmaf(conv_w[(d4 + 2) * DCONV + k], xv.z, s.z);
            s.w = fmaf(conv_w[(d4 + 3) * DCONV + k], xv.w, s.w);
        }
    }
    float4 o;
    o.x = s.x / (1.f + __expf(-s.x));
    o.y = s.y / (1.f + __expf(-s.y));
    o.z = s.z / (1.f + __expf(-s.z));
    o.w = s.w / (1.f + __expf(-s.w));
    *(float4*)(g_u[dir] + (size_t)row * DINNER + d4) = o;
}

// ---------------------------------------------------------------------------
// Selective scan, software-pipelined loads (next iteration's operands issue
// before the current exp/shfl chain). One warp = 2 channels; 16 lanes = 16
// states. dir1 output written with flipped sequence index.
// ---------------------------------------------------------------------------
__global__ __launch_bounds__(256)
void scan_kernel(const float* __restrict__ fAlog, const float* __restrict__ fD,
                 const float* __restrict__ bAlog, const float* __restrict__ bD)
{
    const int dir = blockIdx.y;
    const float* Alog = dir ? bAlog : fAlog;
    const float* Dp   = dir ? bD    : fD;
    const float* delta = g_delta[dir];
    const float* u     = g_u[dir];
    const float* xdbl  = g_xdbl[dir];
    const float* xz    = g_xz[dir];
    float*       ypre  = g_ypre[dir];

    const int lane = threadIdx.x & 31;
    const int warp = threadIdx.x >> 5;
    const int half = lane >> 4;
    const int n    = lane & 15;

    const int c = blockIdx.x * 16 + warp * 2 + half;  // 0..3071
    const int b = c / DINNER;
    const int d = c - b * DINNER;

    const float Aneg = -__expf(Alog[d * DSTATE + n]);
    const float Dd   = Dp[d];
    const bool  ln0  = (n == 0);

    const size_t rowbase = (size_t)b * SEQL;
    const float* pDl = delta + rowbase * DINNER + d;
    const float* pU  = u     + rowbase * DINNER + d;
    const float* pB  = xdbl  + rowbase * XDBLW + DTRANK + n;
    const float* pC  = pB + DSTATE;
    const float* pZ  = xz    + rowbase * XZW + DINNER + d;

    // prefetch iteration 0
    float dl = pDl[0];
    float uu = pU[0];
    float Bn = pB[0];
    float Cn = pC[0];
    float zz = ln0 ? pZ[0] : 0.f;

    float h = 0.f;

    for (int l = 0; l < SEQL; l++) {
        // issue next iteration's loads first (off the critical path)
        float dl2 = 0.f, uu2 = 0.f, Bn2 = 0.f, Cn2 = 0.f, zz2 = 0.f;
        if (l + 1 < SEQL) {
            dl2 = pDl[(size_t)(l + 1) * DINNER];
            uu2 = pU [(size_t)(l + 1) * DINNER];
            Bn2 = pB [(size_t)(l + 1) * XDBLW];
            Cn2 = pC [(size_t)(l + 1) * XDBLW];
            if (ln0) zz2 = pZ[(size_t)(l + 1) * XZW];
        }

        const float dA = __expf(dl * Aneg);
        h = fmaf(dA, h, dl * Bn * uu);

        float yp = h * Cn;
        yp += __shfl_xor_sync(0xffffffffu, yp, 1);
        yp += __shfl_xor_sync(0xffffffffu, yp, 2);
        yp += __shfl_xor_sync(0xffffffffu, yp, 4);
        yp += __shfl_xor_sync(0xffffffffu, yp, 8);

        if (ln0) {
            float y = fmaf(uu, Dd, yp);
            y *= zz / (1.f + __expf(-zz));
            const size_t row  = rowbase + l;
            const size_t orow = dir ? (row ^ (SEQL - 1)) : row;
            ypre[orow * DINNER + d] = y;
        }

        dl = dl2; uu = uu2; Bn = Bn2; Cn = Cn2; zz = zz2;
    }
}

// ---------------------------------------------------------------------------
// Zeroing kernels (float4).
// ---------------------------------------------------------------------------
__global__ void zero_kernel(float4* __restrict__ p, int n4)
{
    int i = blockIdx.x * blockDim.x + threadIdx.x;
    if (i < n4) p[i] = make_float4(0.f, 0.f, 0.f, 0.f);
}
__global__ void zero_scratch_kernel(int id, int n4)
{
    float4* p = (float4*)scratch_ptr(id, blockIdx.y);
    int i = blockIdx.x * blockDim.x + threadIdx.x;
    if (i < n4) p[i] = make_float4(0.f, 0.f, 0.f, 0.f);
}

// ---------------------------------------------------------------------------
// Host launch.
// ---------------------------------------------------------------------------
extern "C" void kernel_launch(void* const* d_in, const int* in_sizes, int n_in,
                              void* d_out, int out_size)
{
    const float* x = (const float*)d_in[0];
    float* out = (float*)d_out;

    const float* f_in_w    = (const float*)d_in[1];
    const float* f_conv_w  = (const float*)d_in[2];
    const float* f_conv_b  = (const float*)d_in[3];
    const float* f_xproj_w = (const float*)d_in[4];
    const float* f_dt_w    = (const float*)d_in[5];
    const float* f_dt_b    = (const float*)d_in[6];
    const float* f_Alog    = (const float*)d_in[7];
    const float* f_D       = (const float*)d_in[8];
    const float* f_out_w   = (const float*)d_in[9];
    const float* b_in_w    = (const float*)d_in[10];
    const float* b_conv_w  = (const float*)d_in[11];
    const float* b_conv_b  = (const float*)d_in[12];
    const float* b_xproj_w = (const float*)d_in[13];
    const float* b_dt_w    = (const float*)d_in[14];
    const float* b_dt_b    = (const float*)d_in[15];
    const float* b_Alog    = (const float*)d_in[16];
    const float* b_D       = (const float*)d_in[17];
    const float* b_out_w   = (const float*)d_in[18];

    // zero accumulation targets (out, xdbl)
    zero_kernel<<<(MTOT * DMODEL / 4 + 255) / 256, 256>>>(
        (float4*)out, MTOT * DMODEL / 4);
    zero_scratch_kernel<<<dim3((MTOT * XDBLW / 4 + 255) / 256, 2), 256>>>(
        BUF_XDBL, MTOT * XDBLW / 4);

    // in_proj (both dirs): xz = x(flip for dir1) @ in_w^T   [2048,3072]
    gemm_mma<ACT_NONE, true, false><<<dim3(XZW / 128, MTOT / 128, 2), 256>>>(
        x, -1, f_in_w, b_in_w, nullptr, nullptr,
        nullptr, BUF_XZ, XZW, DMODEL, DMODEL, XZW, XZW / 128, DMODEL);

    // depthwise conv + SiLU (both dirs)
    conv_silu_kernel<<<dim3((MTOT * DINNER / 4 + 255) / 256, 2), 256>>>(
        f_conv_w, f_conv_b, b_conv_w, b_conv_b);

    // x_proj (both dirs), split-K x8: xdbl += u @ xproj_w^T   [2048,80]
    gemm_mma<ACT_NONE, false, true><<<dim3(8, MTOT / 128, 2), 256>>>(
        nullptr, BUF_U, f_xproj_w, b_xproj_w, nullptr, nullptr,
        nullptr, BUF_XDBL, XDBLW, DINNER, DINNER, XDBLW, 1, DINNER / 8);

    // delta (both dirs): softplus(xdbl[:, :48] @ dt_w^T + dt_b)   [2048,1536]
    gemm_mma<ACT_SOFTPLUS, false, false><<<dim3(DINNER / 128, MTOT / 128, 2), 256>>>(
        nullptr, BUF_XDBL, f_dt_w, b_dt_w, f_dt_b, b_dt_b,
        nullptr, BUF_DELTA, DINNER, DTRANK, XDBLW, DINNER, DINNER / 128, DTRANK);

    // selective scan (both dirs; dir1 output pre-flipped)
    scan_kernel<<<dim3((NB * DINNER) / 16, 2), 256>>>(f_Alog, f_D, b_Alog, b_D);

    // out_proj fused (both dirs), split-K x2: out += ypre @ out_w^T (atomic)
    gemm_mma<ACT_NONE, false, true><<<dim3((DMODEL / 128) * 2, MTOT / 128, 2), 256>>>(
        nullptr, BUF_YPRE, f_out_w, b_out_w, nullptr, nullptr,
        out, -1, DMODEL, DINNER, DINNER, DMODEL, DMODEL / 128, DINNER / 2);
}

// round 7
// speedup vs baseline: 3.4616x; 1.0483x over previous
#include <cuda_runtime.h>
#include <cuda_bf16.h>
#include <cstdint>

// ---------------------------------------------------------------------------
// BidirectionalMambaLayer — Round 7: legacy tf32 mma.sync everywhere
// (tcgen05 unavailable: harness PTX targets sm_103 without 'a' features).
// All GEMM operands pre-rounded to tf32 (no cvt in mainloop), BK=32 2-stage
// pipeline for big GEMMs, l-tiled conv, pipelined scan.
// ---------------------------------------------------------------------------

#define SEQL   1024
#define NB     2
#define MTOT   (NB * SEQL)
#define DMODEL 768
#define DINNER 1536
#define DSTATE 16
#define DTRANK 48
#define DCONV  4
#define XZW    (2 * DINNER)            // 3072
#define XDBLW  (DTRANK + 2 * DSTATE)   // 80

// -------------------------- scratch (device globals) -----------------------
__device__ float g_xz   [2][(size_t)MTOT * XZW];
__device__ float g_u    [2][(size_t)MTOT * DINNER];   // exact (scan)
__device__ float g_ur   [2][(size_t)MTOT * DINNER];   // tf32-rounded (x_proj)
__device__ float g_xdbl [2][(size_t)MTOT * XDBLW];    // exact totals (scan B/C)
__device__ float g_dtr  [2][(size_t)MTOT * DTRANK];   // rounded dt (delta GEMM)
__device__ float g_delta[2][(size_t)MTOT * DINNER];
__device__ float g_ypre [2][(size_t)MTOT * DINNER];   // rounded at scan write
__device__ float g_xr   [(size_t)MTOT * DMODEL];      // rounded x
__device__ float g_win  [2][(size_t)XZW * DMODEL];
__device__ float g_wxp  [2][(size_t)XDBLW * DINNER];
__device__ float g_wdt  [2][(size_t)DINNER * DTRANK];
__device__ float g_wout [2][(size_t)DMODEL * DINNER];

enum { BUF_XZ = 0, BUF_U, BUF_UR, BUF_XDBL, BUF_DTR, BUF_DELTA, BUF_YPRE,
       BUF_XR, BUF_WIN, BUF_WXP, BUF_WDT, BUF_WOUT };

__device__ __forceinline__ float* scratch_ptr(int id, int dir) {
    switch (id) {
        case BUF_XZ:    return g_xz[dir];
        case BUF_U:     return g_u[dir];
        case BUF_UR:    return g_ur[dir];
        case BUF_XDBL:  return g_xdbl[dir];
        case BUF_DTR:   return g_dtr[dir];
        case BUF_DELTA: return g_delta[dir];
        case BUF_YPRE:  return g_ypre[dir];
        case BUF_XR:    return g_xr;
        case BUF_WIN:   return g_win[dir];
        case BUF_WXP:   return g_wxp[dir];
        case BUF_WDT:   return g_wdt[dir];
        case BUF_WOUT:  return g_wout[dir];
    }
    return nullptr;
}

enum { ACT_NONE = 0, ACT_SOFTPLUS = 1 };

__device__ __forceinline__ uint32_t tf32u(float x) {
    uint32_t u;
    asm("cvt.rna.tf32.f32 %0, %1;" : "=r"(u) : "f"(x));
    return u;
}
__device__ __forceinline__ float tf32rf(float x) { return __uint_as_float(tf32u(x)); }

__device__ __forceinline__ void cp16(uint32_t saddr, const float* gptr, bool ok) {
    int sz = ok ? 16 : 0;
    asm volatile("cp.async.cg.shared.global [%0], [%1], 16, %2;"
                 :: "r"(saddr), "l"(gptr), "r"(sz));
}
__device__ __forceinline__ void cp_commit() { asm volatile("cp.async.commit_group;"); }
__device__ __forceinline__ void cp_wait1()  { asm volatile("cp.async.wait_group 1;"); }
__device__ __forceinline__ void cp_wait0()  { asm volatile("cp.async.wait_group 0;"); }

// ---------------------------------------------------------------------------
// tf32 mma.sync TN GEMM, dir-merged (blockIdx.z), optional split-K
// (blockIdx.x = split*nxt + ntile):
//   C_dir[M,N] (+)= act( A_dir[M,kbeg:kend] * W_dir[N,kbeg:kend]^T + bias )
// BM=BN=128, 256 threads (8 warps 2m x 4n), warp tile 64x32, m16n8k8.tf32.
// All operands MUST be pre-rounded tf32 (no cvt in mainloop).
// BK (32 or 16) k-tile, STG-stage cp.async pipeline.
// ---------------------------------------------------------------------------
template<int ACT, bool FLIPA1, bool ATOMIC, int BK, int STG>
__global__ __launch_bounds__(256, 2)
void gemm_mma(int aId, int bId,
              const float* __restrict__ bias0, const float* __restrict__ bias1,
              float* __restrict__ Cext, int cId,
              int N, int K, int lda, int ldc, int nxt, int kchunk)
{
    constexpr int SASX = BK + 4;          // smem row stride (floats)
    constexpr int CPR  = BK / 4;          // 16B chunks per row
    constexpr int LIT  = 128 * CPR / 256; // load iterations per matrix

    const int dir = blockIdx.z;
    const float* A    = scratch_ptr(aId, dir);
    const float* W    = scratch_ptr(bId, dir);
    const float* bias = dir ? bias1 : bias0;
    float*       C    = Cext ? Cext : scratch_ptr(cId, dir);

    const int split = blockIdx.x / nxt;
    const int bn    = (blockIdx.x - split * nxt) * 128;
    const int bm    = blockIdx.y * 128;
    const int kbeg  = split * kchunk;
    const int T     = kchunk / BK;

    __shared__ float sA[STG][128 * SASX];
    __shared__ float sB[STG][128 * SASX];

    const int tid  = threadIdx.x;
    const int lane = tid & 31;
    const int warp = tid >> 5;
    const int wm   = warp >> 2;
    const int wn   = warp & 3;
    const int gr   = lane >> 2;
    const int tq   = lane & 3;

    const uint32_t sAb = (uint32_t)__cvta_generic_to_shared(&sA[0][0]);
    const uint32_t sBb = (uint32_t)__cvta_generic_to_shared(&sB[0][0]);
    const uint32_t stage_bytes = 128 * SASX * 4;

    // per-thread chunk geometry
    int arow[LIT], aq[LIT];
    uint32_t soff[LIT];
#pragma unroll
    for (int i = 0; i < LIT; i++) {
        const int c = tid + i * 256;
        arow[i] = c / CPR;
        aq[i]   = (c - arow[i] * CPR) * 4;
        soff[i] = (uint32_t)(arow[i] * SASX + aq[i]) * 4;
    }

    auto load_tile = [&](int t, int st) {
        const int kof = kbeg + t * BK;
#pragma unroll
        for (int i = 0; i < LIT; i++) {
            int gm = bm + arow[i];
            if (FLIPA1 && dir) gm ^= (SEQL - 1);
            cp16(sAb + st * stage_bytes + soff[i],
                 A + (size_t)gm * lda + kof + aq[i], true);
        }
#pragma unroll
        for (int i = 0; i < LIT; i++) {
            const int wr = bn + arow[i];
            cp16(sBb + st * stage_bytes + soff[i],
                 W + (size_t)wr * K + kof + aq[i], wr < N);
        }
        cp_commit();
    };

    float acc[4][4][4];
#pragma unroll
    for (int mt = 0; mt < 4; mt++)
#pragma unroll
        for (int nt = 0; nt < 4; nt++)
#pragma unroll
            for (int r = 0; r < 4; r++) acc[mt][nt][r] = 0.f;

    // prologue
    load_tile(0, 0);
    if (T > 1) load_tile(1, 1 % STG);

    for (int t = 0; t < T; t++) {
        const int st = t % STG;
        if (t + 1 < T) cp_wait1(); else cp_wait0();
        __syncthreads();

        if (STG >= 3 && t + 2 < T) {           // 3-stage: prefetch before compute
            load_tile(t + 2, (t + 2) % STG);
        }

        const uint32_t* cA = (const uint32_t*)&sA[st][0];
        const uint32_t* cB = (const uint32_t*)&sB[st][0];
#pragma unroll
        for (int ks = 0; ks < BK / 8; ks++) {
            const int kb = ks * 8;
            uint32_t a[4][4], b[4][2];
#pragma unroll
            for (int mt = 0; mt < 4; mt++) {
                const int m0 = wm * 64 + mt * 16 + gr;
                a[mt][0] = cA[m0 * SASX + kb + tq];
                a[mt][1] = cA[(m0 + 8) * SASX + kb + tq];
                a[mt][2] = cA[m0 * SASX + kb + tq + 4];
                a[mt][3] = cA[(m0 + 8) * SASX + kb + tq + 4];
            }
#pragma unroll
            for (int nt = 0; nt < 4; nt++) {
                const int n0 = wn * 32 + nt * 8 + gr;
                b[nt][0] = cB[n0 * SASX + kb + tq];
                b[nt][1] = cB[n0 * SASX + kb + tq + 4];
            }
#pragma unroll
            for (int mt = 0; mt < 4; mt++)
#pragma unroll
                for (int nt = 0; nt < 4; nt++) {
                    asm volatile(
                        "mma.sync.aligned.m16n8k8.row.col.f32.tf32.tf32.f32 "
                        "{%0,%1,%2,%3}, {%4,%5,%6,%7}, {%8,%9}, {%0,%1,%2,%3};"
                        : "+f"(acc[mt][nt][0]), "+f"(acc[mt][nt][1]),
                          "+f"(acc[mt][nt][2]), "+f"(acc[mt][nt][3])
                        : "r"(a[mt][0]), "r"(a[mt][1]), "r"(a[mt][2]), "r"(a[mt][3]),
                          "r"(b[nt][0]), "r"(b[nt][1]));
                }
        }

        if (STG == 2 && t + 2 < T) {           // 2-stage: reload stage just read
            __syncthreads();
            load_tile(t + 2, st);
        }
    }

    // epilogue
#pragma unroll
    for (int mt = 0; mt < 4; mt++) {
        const int m0 = bm + wm * 64 + mt * 16 + gr;
#pragma unroll
        for (int half = 0; half < 2; half++) {
            const int m = m0 + half * 8;
#pragma unroll
            for (int nt = 0; nt < 4; nt++) {
                const int nbase = bn + wn * 32 + nt * 8 + 2 * tq;
#pragma unroll
                for (int j = 0; j < 2; j++) {
                    const int n = nbase + j;
                    if (n < N) {
                        float v = acc[mt][nt][half * 2 + j];
                        if (bias) v += bias[n];
                        if (ACT == ACT_SOFTPLUS)
                            v = (v > 20.f) ? v : log1pf(__expf(v));
                        if (ATOMIC) atomicAdd(&C[(size_t)m * ldc + n], v);
                        else        C[(size_t)m * ldc + n] = v;
                    }
                }
            }
        }
    }
}

// ---------------------------------------------------------------------------
// tf32 pre-rounding (grid-stride; blockIdx.y selects tensor).
// ---------------------------------------------------------------------------
__global__ void round_tf32_kernel(const float4* __restrict__ x,
                                  const float4* __restrict__ fiw, const float4* __restrict__ biw,
                                  const float4* __restrict__ fow, const float4* __restrict__ bow,
                                  const float4* __restrict__ fxp, const float4* __restrict__ bxp,
                                  const float4* __restrict__ fdw, const float4* __restrict__ bdw)
{
    const float4* src; float4* dst; int n4;
    switch (blockIdx.y) {
        case 0:  src = x;   dst = (float4*)g_xr;      n4 = MTOT * DMODEL / 4;    break;
        case 1:  src = fiw; dst = (float4*)g_win[0];  n4 = XZW * DMODEL / 4;     break;
        case 2:  src = biw; dst = (float4*)g_win[1];  n4 = XZW * DMODEL / 4;     break;
        case 3:  src = fow; dst = (float4*)g_wout[0]; n4 = DMODEL * DINNER / 4;  break;
        case 4:  src = bow; dst = (float4*)g_wout[1]; n4 = DMODEL * DINNER / 4;  break;
        case 5:  src = fxp; dst = (float4*)g_wxp[0];  n4 = XDBLW * DINNER / 4;   break;
        case 6:  src = bxp; dst = (float4*)g_wxp[1];  n4 = XDBLW * DINNER / 4;   break;
        case 7:  src = fdw; dst = (float4*)g_wdt[0];  n4 = DINNER * DTRANK / 4;  break;
        default: src = bdw; dst = (float4*)g_wdt[1];  n4 = DINNER * DTRANK / 4;  break;
    }
    for (int i = blockIdx.x * blockDim.x + threadIdx.x; i < n4;
         i += gridDim.x * blockDim.x) {
        float4 v = src[i];
        v.x = tf32rf(v.x); v.y = tf32rf(v.y);
        v.z = tf32rf(v.z); v.w = tf32rf(v.w);
        dst[i] = v;
    }
}

// round dt columns of xdbl totals -> g_dtr (RNA on sums == round-5 numerics)
__global__ void round_dt_kernel()
{
    const int dir = blockIdx.y;
    const int e = blockIdx.x * blockDim.x + threadIdx.x;
    if (e >= MTOT * DTRANK) return;
    const int row = e / DTRANK;
    const int j   = e - row * DTRANK;
    g_dtr[dir][e] = tf32rf(g_xdbl[dir][(size_t)row * XDBLW + j]);
}

// ---------------------------------------------------------------------------
// Causal depthwise conv (D_CONV=4) + bias + SiLU, l-tiled x4, float4 channels.
// Writes exact u (scan) and tf32-rounded u (x_proj operand).
// ---------------------------------------------------------------------------
__global__ void conv_silu_kernel(const float* __restrict__ f_conv_w,
                                 const float* __restrict__ f_conv_b,
                                 const float* __restrict__ b_conv_w,
                                 const float* __restrict__ b_conv_b)
{
    const int dir = blockIdx.y;
    const float* conv_w = dir ? b_conv_w : f_conv_w;
    const float* conv_b = dir ? b_conv_b : f_conv_b;

    const int NCH = DINNER / 4;
    const int idx = blockIdx.x * blockDim.x + threadIdx.x;
    if (idx >= (MTOT / 4) * NCH) return;
    const int rt   = idx / NCH;
    const int d4   = (idx - rt * NCH) * 4;
    const int row0 = rt * 4;
    const int l0   = row0 & (SEQL - 1);

    const float* xz = g_xz[dir];
    float cw[4][4];
#pragma unroll
    for (int j = 0; j < 4; j++) {
        const float4 w = *(const float4*)(conv_w + (d4 + j) * DCONV);
        cw[j][0] = w.x; cw[j][1] = w.y; cw[j][2] = w.z; cw[j][3] = w.w;
    }

    float4 xv[7];
#pragma unroll
    for (int j = 0; j < 7; j++) {
        const int l = l0 - 3 + j;
        xv[j] = (l >= 0)
              ? *(const float4*)(xz + (size_t)(row0 - 3 + j) * XZW + d4)
              : make_float4(0.f, 0.f, 0.f, 0.f);
    }
    const float4 bias = *(const float4*)(conv_b + d4);

#pragma unroll
    for (int i = 0; i < 4; i++) {
        float4 s = bias;
#pragma unroll
        for (int k = 0; k < 4; k++) {
            const float4 xvv = xv[i + k];
            s.x = fmaf(cw[0][k], xvv.x, s.x);
            s.y = fmaf(cw[1][k], xvv.y, s.y);
            s.z = fmaf(cw[2][k], xvv.z, s.z);
            s.w = fmaf(cw[3][k], xvv.w, s.w);
        }
        float4 o;
        o.x = s.x / (1.f + __expf(-s.x));
        o.y = s.y / (1.f + __expf(-s.y));
        o.z = s.z / (1.f + __expf(-s.z));
        o.w = s.w / (1.f + __expf(-s.w));
        *(float4*)(g_u[dir] + (size_t)(row0 + i) * DINNER + d4) = o;
        float4 r;
        r.x = tf32rf(o.x); r.y = tf32rf(o.y);
        r.z = tf32rf(o.z); r.w = tf32rf(o.w);
        *(float4*)(g_ur[dir] + (size_t)(row0 + i) * DINNER + d4) = r;
    }
}

// ---------------------------------------------------------------------------
// Selective scan, software-pipelined; dir1 output pre-flipped; tf32-rounded.
// ---------------------------------------------------------------------------
__global__ __launch_bounds__(256)
void scan_kernel(const float* __restrict__ fAlog, const float* __restrict__ fD,
                 const float* __restrict__ bAlog, const float* __restrict__ bD)
{
    const int dir = blockIdx.y;
    const float* Alog = dir ? bAlog : fAlog;
    const float* Dp   = dir ? bD    : fD;
    const float* delta = g_delta[dir];
    const float* u     = g_u[dir];
    const float* xdbl  = g_xdbl[dir];
    const float* xz    = g_xz[dir];
    float*       ypre  = g_ypre[dir];

    const int lane = threadIdx.x & 31;
    const int warp = threadIdx.x >> 5;
    const int half = lane >> 4;
    const int n    = lane & 15;

    const int c = blockIdx.x * 16 + warp * 2 + half;
    const int b = c / DINNER;
    const int d = c - b * DINNER;

    const float Aneg = -__expf(Alog[d * DSTATE + n]);
    const float Dd   = Dp[d];
    const bool  ln0  = (n == 0);

    const size_t rowbase = (size_t)b * SEQL;
    const float* pDl = delta + rowbase * DINNER + d;
    const float* pU  = u     + rowbase * DINNER + d;
    const float* pB  = xdbl  + rowbase * XDBLW + DTRANK + n;
    const float* pC  = pB + DSTATE;
    const float* pZ  = xz    + rowbase * XZW + DINNER + d;

    float dl = pDl[0];
    float uu = pU[0];
    float Bn = pB[0];
    float Cn = pC[0];
    float zz = ln0 ? pZ[0] : 0.f;

    float h = 0.f;

    for (int l = 0; l < SEQL; l++) {
        float dl2 = 0.f, uu2 = 0.f, Bn2 = 0.f, Cn2 = 0.f, zz2 = 0.f;
        if (l + 1 < SEQL) {
            dl2 = pDl[(size_t)(l + 1) * DINNER];
            uu2 = pU [(size_t)(l + 1) * DINNER];
            Bn2 = pB [(size_t)(l + 1) * XDBLW];
            Cn2 = pC [(size_t)(l + 1) * XDBLW];
            if (ln0) zz2 = pZ[(size_t)(l + 1) * XZW];
        }

        const float dA = __expf(dl * Aneg);
        h = fmaf(dA, h, dl * Bn * uu);

        float yp = h * Cn;
        yp += __shfl_xor_sync(0xffffffffu, yp, 1);
        yp += __shfl_xor_sync(0xffffffffu, yp, 2);
        yp += __shfl_xor_sync(0xffffffffu, yp, 4);
        yp += __shfl_xor_sync(0xffffffffu, yp, 8);

        if (ln0) {
            float y = fmaf(uu, Dd, yp);
            y *= zz / (1.f + __expf(-zz));
            const size_t row  = rowbase + l;
            const size_t orow = dir ? (row ^ (SEQL - 1)) : row;
            ypre[orow * DINNER + d] = tf32rf(y);
        }

        dl = dl2; uu = uu2; Bn = Bn2; Cn = Cn2; zz = zz2;
    }
}

// ---------------------------------------------------------------------------
// Zeroing kernels.
// ---------------------------------------------------------------------------
__global__ void zero_kernel(float4* __restrict__ p, int n4)
{
    int i = blockIdx.x * blockDim.x + threadIdx.x;
    if (i < n4) p[i] = make_float4(0.f, 0.f, 0.f, 0.f);
}
__global__ void zero_scratch_kernel(int id, int n4)
{
    float4* p = (float4*)scratch_ptr(id, blockIdx.y);
    int i = blockIdx.x * blockDim.x + threadIdx.x;
    if (i < n4) p[i] = make_float4(0.f, 0.f, 0.f, 0.f);
}

// ---------------------------------------------------------------------------
// Host launch.
// ---------------------------------------------------------------------------
extern "C" void kernel_launch(void* const* d_in, const int* in_sizes, int n_in,
                              void* d_out, int out_size)
{
    const float* x = (const float*)d_in[0];
    float* out = (float*)d_out;

    const float* f_in_w    = (const float*)d_in[1];
    const float* f_conv_w  = (const float*)d_in[2];
    const float* f_conv_b  = (const float*)d_in[3];
    const float* f_xproj_w = (const float*)d_in[4];
    const float* f_dt_w    = (const float*)d_in[5];
    const float* f_dt_b    = (const float*)d_in[6];
    const float* f_Alog    = (const float*)d_in[7];
    const float* f_D       = (const float*)d_in[8];
    const float* f_out_w   = (const float*)d_in[9];
    const float* b_in_w    = (const float*)d_in[10];
    const float* b_conv_w  = (const float*)d_in[11];
    const float* b_conv_b  = (const float*)d_in[12];
    const float* b_xproj_w = (const float*)d_in[13];
    const float* b_dt_w    = (const float*)d_in[14];
    const float* b_dt_b    = (const float*)d_in[15];
    const float* b_Alog    = (const float*)d_in[16];
    const float* b_D       = (const float*)d_in[17];
    const float* b_out_w   = (const float*)d_in[18];

    // zero accumulation targets
    zero_kernel<<<(MTOT * DMODEL / 4 + 255) / 256, 256>>>(
        (float4*)out, MTOT * DMODEL / 4);
    zero_scratch_kernel<<<dim3((MTOT * XDBLW / 4 + 255) / 256, 2), 256>>>(
        BUF_XDBL, MTOT * XDBLW / 4);

    // tf32 pre-rounding of all GEMM operands
    round_tf32_kernel<<<dim3(256, 9), 256>>>(
        (const float4*)x,
        (const float4*)f_in_w,    (const float4*)b_in_w,
        (const float4*)f_out_w,   (const float4*)b_out_w,
        (const float4*)f_xproj_w, (const float4*)b_xproj_w,
        (const float4*)f_dt_w,    (const float4*)b_dt_w);

    // in_proj: xz = x(flip dir1) @ in_w^T   [2048,3072], K=768
    gemm_mma<ACT_NONE, true, false, 32, 2><<<dim3(XZW / 128, MTOT / 128, 2), 256>>>(
        BUF_XR, BUF_WIN, nullptr, nullptr, nullptr, BUF_XZ,
        XZW, DMODEL, DMODEL, XZW, XZW / 128, DMODEL);

    // depthwise conv + SiLU (writes u exact + u rounded)
    conv_silu_kernel<<<dim3(((MTOT / 4) * (DINNER / 4) + 255) / 256, 2), 256>>>(
        f_conv_w, f_conv_b, b_conv_w, b_conv_b);

    // x_proj (split-K x8, atomic): xdbl += u_r @ xproj_w^T   [2048,80], K=1536
    gemm_mma<ACT_NONE, false, true, 32, 2><<<dim3(8, MTOT / 128, 2), 256>>>(
        BUF_UR, BUF_WXP, nullptr, nullptr, nullptr, BUF_XDBL,
        XDBLW, DINNER, DINNER, XDBLW, 1, DINNER / 8);

    // round dt columns of the accumulated totals
    round_dt_kernel<<<dim3((MTOT * DTRANK + 255) / 256, 2), 256>>>();

    // delta: softplus(dtr @ dt_w^T + dt_b)   [2048,1536], K=48
    gemm_mma<ACT_SOFTPLUS, false, false, 16, 3><<<dim3(DINNER / 128, MTOT / 128, 2), 256>>>(
        BUF_DTR, BUF_WDT, f_dt_b, b_dt_b, nullptr, BUF_DELTA,
        DINNER, DTRANK, DTRANK, DINNER, DINNER / 128, DTRANK);

    // selective scan (dir1 output pre-flipped, tf32-rounded)
    scan_kernel<<<dim3((NB * DINNER) / 16, 2), 256>>>(f_Alog, f_D, b_Alog, b_D);

    // out_proj (split-K x2, atomic): out += ypre @ out_w^T   [2048,768], K=1536
    gemm_mma<ACT_NONE, false, true, 32, 2><<<dim3((DMODEL / 128) * 2, MTOT / 128, 2), 256>>>(
        BUF_YPRE, BUF_WOUT, nullptr, nullptr, out, -1,
        DMODEL, DINNER, DINNER, DMODEL, DMODEL / 128, DINNER / 2);
}

// round 8
// speedup vs baseline: 4.9414x; 1.4275x over previous
#include <cuda_runtime.h>
#include <cuda_bf16.h>
#include <cstdint>

// ---------------------------------------------------------------------------
// BidirectionalMambaLayer — Round 8: ldmatrix fragment loads in the tf32
// mma.sync GEMM; unroll-8 double-buffered selective scan. Numerics identical
// to round 7 (rel_err 5.115e-4).
// ---------------------------------------------------------------------------

#define SEQL   1024
#define NB     2
#define MTOT   (NB * SEQL)
#define DMODEL 768
#define DINNER 1536
#define DSTATE 16
#define DTRANK 48
#define DCONV  4
#define XZW    (2 * DINNER)            // 3072
#define XDBLW  (DTRANK + 2 * DSTATE)   // 80

// -------------------------- scratch (device globals) -----------------------
__device__ float g_xz   [2][(size_t)MTOT * XZW];
__device__ float g_u    [2][(size_t)MTOT * DINNER];   // exact (scan)
__device__ float g_ur   [2][(size_t)MTOT * DINNER];   // tf32-rounded (x_proj)
__device__ float g_xdbl [2][(size_t)MTOT * XDBLW];    // exact totals (scan B/C)
__device__ float g_dtr  [2][(size_t)MTOT * DTRANK];   // rounded dt
__device__ float g_delta[2][(size_t)MTOT * DINNER];
__device__ float g_ypre [2][(size_t)MTOT * DINNER];   // rounded at scan write
__device__ float g_xr   [(size_t)MTOT * DMODEL];
__device__ float g_win  [2][(size_t)XZW * DMODEL];
__device__ float g_wxp  [2][(size_t)XDBLW * DINNER];
__device__ float g_wdt  [2][(size_t)DINNER * DTRANK];
__device__ float g_wout [2][(size_t)DMODEL * DINNER];

enum { BUF_XZ = 0, BUF_U, BUF_UR, BUF_XDBL, BUF_DTR, BUF_DELTA, BUF_YPRE,
       BUF_XR, BUF_WIN, BUF_WXP, BUF_WDT, BUF_WOUT };

__device__ __forceinline__ float* scratch_ptr(int id, int dir) {
    switch (id) {
        case BUF_XZ:    return g_xz[dir];
        case BUF_U:     return g_u[dir];
        case BUF_UR:    return g_ur[dir];
        case BUF_XDBL:  return g_xdbl[dir];
        case BUF_DTR:   return g_dtr[dir];
        case BUF_DELTA: return g_delta[dir];
        case BUF_YPRE:  return g_ypre[dir];
        case BUF_XR:    return g_xr;
        case BUF_WIN:   return g_win[dir];
        case BUF_WXP:   return g_wxp[dir];
        case BUF_WDT:   return g_wdt[dir];
        case BUF_WOUT:  return g_wout[dir];
    }
    return nullptr;
}

enum { ACT_NONE = 0, ACT_SOFTPLUS = 1 };

__device__ __forceinline__ uint32_t tf32u(float x) {
    uint32_t u;
    asm("cvt.rna.tf32.f32 %0, %1;" : "=r"(u) : "f"(x));
    return u;
}
__device__ __forceinline__ float tf32rf(float x) { return __uint_as_float(tf32u(x)); }

__device__ __forceinline__ void cp16(uint32_t saddr, const float* gptr, bool ok) {
    int sz = ok ? 16 : 0;
    asm volatile("cp.async.cg.shared.global [%0], [%1], 16, %2;"
                 :: "r"(saddr), "l"(gptr), "r"(sz));
}
__device__ __forceinline__ void cp_commit() { asm volatile("cp.async.commit_group;"); }
__device__ __forceinline__ void cp_wait1()  { asm volatile("cp.async.wait_group 1;"); }
__device__ __forceinline__ void cp_wait0()  { asm volatile("cp.async.wait_group 0;"); }

__device__ __forceinline__ void ldsm_x4(uint32_t& r0, uint32_t& r1,
                                        uint32_t& r2, uint32_t& r3, uint32_t a) {
    asm volatile("ldmatrix.sync.aligned.m8n8.x4.shared.b16 {%0,%1,%2,%3}, [%4];"
                 : "=r"(r0), "=r"(r1), "=r"(r2), "=r"(r3) : "r"(a));
}

// ---------------------------------------------------------------------------
// tf32 mma.sync TN GEMM, dir-merged (blockIdx.z), optional split-K.
// BM=BN=128, 256 threads (8 warps 2m x 4n), warp tile 64x32, m16n8k8.tf32.
// Fragment loads via ldmatrix.x4 (tf32 bit patterns moved as b16 pairs).
// Operands MUST be pre-rounded tf32. BK k-tile, STG-stage cp.async pipeline.
// ---------------------------------------------------------------------------
template<int ACT, bool FLIPA1, bool ATOMIC, int BK, int STG>
__global__ __launch_bounds__(256, 2)
void gemm_mma(int aId, int bId,
              const float* __restrict__ bias0, const float* __restrict__ bias1,
              float* __restrict__ Cext, int cId,
              int N, int K, int lda, int ldc, int nxt, int kchunk)
{
    constexpr int SASX = BK + 4;
    constexpr int CPR  = BK / 4;
    constexpr int LIT  = 128 * CPR / 256;

    const int dir = blockIdx.z;
    const float* A    = scratch_ptr(aId, dir);
    const float* W    = scratch_ptr(bId, dir);
    const float* bias = dir ? bias1 : bias0;
    float*       C    = Cext ? Cext : scratch_ptr(cId, dir);

    const int split = blockIdx.x / nxt;
    const int bn    = (blockIdx.x - split * nxt) * 128;
    const int bm    = blockIdx.y * 128;
    const int kbeg  = split * kchunk;
    const int T     = kchunk / BK;

    __shared__ float sA[STG][128 * SASX];
    __shared__ float sB[STG][128 * SASX];

    const int tid  = threadIdx.x;
    const int lane = tid & 31;
    const int warp = tid >> 5;
    const int wm   = warp >> 2;
    const int wn   = warp & 3;
    const int gr   = lane >> 2;
    const int tq   = lane & 3;

    const uint32_t sAb = (uint32_t)__cvta_generic_to_shared(&sA[0][0]);
    const uint32_t sBb = (uint32_t)__cvta_generic_to_shared(&sB[0][0]);
    const uint32_t stage_bytes = 128 * SASX * 4;

    // ldmatrix per-lane offsets (bytes):
    //   A x4 at (mt, kb): matrices (rows lo, k-lo),(rows hi, k-lo),(rows lo, k-hi),(rows hi, k-hi)
    const uint32_t laneA =
        ((uint32_t)((wm * 64 + (lane & 15)) * SASX + (lane >> 4) * 4)) * 4;
    //   B x4 at (pair p, kb): (nt rows, k-lo),(nt rows, k-hi),(nt+1 rows, k-lo),(nt+1 rows, k-hi)
    const uint32_t laneB =
        ((uint32_t)((wn * 32 + (lane & 7) + ((lane & 16) ? 8 : 0)) * SASX +
                    ((lane & 8) ? 4 : 0))) * 4;

    // cp.async chunk geometry
    int arow[LIT], aq[LIT];
    uint32_t soff[LIT];
#pragma unroll
    for (int i = 0; i < LIT; i++) {
        const int c = tid + i * 256;
        arow[i] = c / CPR;
        aq[i]   = (c - arow[i] * CPR) * 4;
        soff[i] = (uint32_t)(arow[i] * SASX + aq[i]) * 4;
    }

    auto load_tile = [&](int t, int st) {
        const int kof = kbeg + t * BK;
#pragma unroll
        for (int i = 0; i < LIT; i++) {
            int gm = bm + arow[i];
            if (FLIPA1 && dir) gm ^= (SEQL - 1);
            cp16(sAb + st * stage_bytes + soff[i],
                 A + (size_t)gm * lda + kof + aq[i], true);
        }
#pragma unroll
        for (int i = 0; i < LIT; i++) {
            const int wr = bn + arow[i];
            cp16(sBb + st * stage_bytes + soff[i],
                 W + (size_t)wr * K + kof + aq[i], wr < N);
        }
        cp_commit();
    };

    float acc[4][4][4];
#pragma unroll
    for (int mt = 0; mt < 4; mt++)
#pragma unroll
        for (int nt = 0; nt < 4; nt++)
#pragma unroll
            for (int r = 0; r < 4; r++) acc[mt][nt][r] = 0.f;

    load_tile(0, 0);
    if (T > 1) load_tile(1, 1 % STG);

    for (int t = 0; t < T; t++) {
        const int st = t % STG;
        if (t + 1 < T) cp_wait1(); else cp_wait0();
        __syncthreads();

        if (STG >= 3 && t + 2 < T) load_tile(t + 2, (t + 2) % STG);

        const uint32_t aAddr = sAb + st * stage_bytes + laneA;
        const uint32_t bAddr = sBb + st * stage_bytes + laneB;
#pragma unroll
        for (int ks = 0; ks < BK / 8; ks++) {
            const uint32_t kb4 = (uint32_t)(ks * 8) * 4;
            uint32_t a[4][4], b[4][2];
#pragma unroll
            for (int mt = 0; mt < 4; mt++)
                ldsm_x4(a[mt][0], a[mt][1], a[mt][2], a[mt][3],
                        aAddr + (uint32_t)(mt * 16 * SASX) * 4 + kb4);
#pragma unroll
            for (int p = 0; p < 2; p++)
                ldsm_x4(b[2 * p][0], b[2 * p][1], b[2 * p + 1][0], b[2 * p + 1][1],
                        bAddr + (uint32_t)(p * 16 * SASX) * 4 + kb4);
#pragma unroll
            for (int mt = 0; mt < 4; mt++)
#pragma unroll
                for (int nt = 0; nt < 4; nt++) {
                    asm volatile(
                        "mma.sync.aligned.m16n8k8.row.col.f32.tf32.tf32.f32 "
                        "{%0,%1,%2,%3}, {%4,%5,%6,%7}, {%8,%9}, {%0,%1,%2,%3};"
                        : "+f"(acc[mt][nt][0]), "+f"(acc[mt][nt][1]),
                          "+f"(acc[mt][nt][2]), "+f"(acc[mt][nt][3])
                        : "r"(a[mt][0]), "r"(a[mt][1]), "r"(a[mt][2]), "r"(a[mt][3]),
                          "r"(b[nt][0]), "r"(b[nt][1]));
                }
        }

        if (STG == 2 && t + 2 < T) {
            __syncthreads();
            load_tile(t + 2, st);
        }
    }

    // epilogue
#pragma unroll
    for (int mt = 0; mt < 4; mt++) {
        const int m0 = bm + wm * 64 + mt * 16 + gr;
#pragma unroll
        for (int half = 0; half < 2; half++) {
            const int m = m0 + half * 8;
#pragma unroll
            for (int nt = 0; nt < 4; nt++) {
                const int nbase = bn + wn * 32 + nt * 8 + 2 * tq;
#pragma unroll
                for (int j = 0; j < 2; j++) {
                    const int n = nbase + j;
                    if (n < N) {
                        float v = acc[mt][nt][half * 2 + j];
                        if (bias) v += bias[n];
                        if (ACT == ACT_SOFTPLUS)
                            v = (v > 20.f) ? v : log1pf(__expf(v));
                        if (ATOMIC) atomicAdd(&C[(size_t)m * ldc + n], v);
                        else        C[(size_t)m * ldc + n] = v;
                    }
                }
            }
        }
    }
}

// ---------------------------------------------------------------------------
// tf32 pre-rounding (grid-stride; blockIdx.y selects tensor).
// ---------------------------------------------------------------------------
__global__ void round_tf32_kernel(const float4* __restrict__ x,
                                  const float4* __restrict__ fiw, const float4* __restrict__ biw,
                                  const float4* __restrict__ fow, const float4* __restrict__ bow,
                                  const float4* __restrict__ fxp, const float4* __restrict__ bxp,
                                  const float4* __restrict__ fdw, const float4* __restrict__ bdw)
{
    const float4* src; float4* dst; int n4;
    switch (blockIdx.y) {
        case 0:  src = x;   dst = (float4*)g_xr;      n4 = MTOT * DMODEL / 4;    break;
        case 1:  src = fiw; dst = (float4*)g_win[0];  n4 = XZW * DMODEL / 4;     break;
        case 2:  src = biw; dst = (float4*)g_win[1];  n4 = XZW * DMODEL / 4;     break;
        case 3:  src = fow; dst = (float4*)g_wout[0]; n4 = DMODEL * DINNER / 4;  break;
        case 4:  src = bow; dst = (float4*)g_wout[1]; n4 = DMODEL * DINNER / 4;  break;
        case 5:  src = fxp; dst = (float4*)g_wxp[0];  n4 = XDBLW * DINNER / 4;   break;
        case 6:  src = bxp; dst = (float4*)g_wxp[1];  n4 = XDBLW * DINNER / 4;   break;
        case 7:  src = fdw; dst = (float4*)g_wdt[0];  n4 = DINNER * DTRANK / 4;  break;
        default: src = bdw; dst = (float4*)g_wdt[1];  n4 = DINNER * DTRANK / 4;  break;
    }
    for (int i = blockIdx.x * blockDim.x + threadIdx.x; i < n4;
         i += gridDim.x * blockDim.x) {
        float4 v = src[i];
        v.x = tf32rf(v.x); v.y = tf32rf(v.y);
        v.z = tf32rf(v.z); v.w = tf32rf(v.w);
        dst[i] = v;
    }
}

__global__ void round_dt_kernel()
{
    const int dir = blockIdx.y;
    const int e = blockIdx.x * blockDim.x + threadIdx.x;
    if (e >= MTOT * DTRANK) return;
    const int row = e / DTRANK;
    const int j   = e - row * DTRANK;
    g_dtr[dir][e] = tf32rf(g_xdbl[dir][(size_t)row * XDBLW + j]);
}

// ---------------------------------------------------------------------------
// Causal depthwise conv (D_CONV=4) + bias + SiLU, l-tiled x4.
// ---------------------------------------------------------------------------
__global__ void conv_silu_kernel(const float* __restrict__ f_conv_w,
                                 const float* __restrict__ f_conv_b,
                                 const float* __restrict__ b_conv_w,
                                 const float* __restrict__ b_conv_b)
{
    const int dir = blockIdx.y;
    const float* conv_w = dir ? b_conv_w : f_conv_w;
    const float* conv_b = dir ? b_conv_b : f_conv_b;

    const int NCH = DINNER / 4;
    const int idx = blockIdx.x * blockDim.x + threadIdx.x;
    if (idx >= (MTOT / 4) * NCH) return;
    const int rt   = idx / NCH;
    const int d4   = (idx - rt * NCH) * 4;
    const int row0 = rt * 4;
    const int l0   = row0 & (SEQL - 1);

    const float* xz = g_xz[dir];
    float cw[4][4];
#pragma unroll
    for (int j = 0; j < 4; j++) {
        const float4 w = *(const float4*)(conv_w + (d4 + j) * DCONV);
        cw[j][0] = w.x; cw[j][1] = w.y; cw[j][2] = w.z; cw[j][3] = w.w;
    }

    float4 xv[7];
#pragma unroll
    for (int j = 0; j < 7; j++) {
        const int l = l0 - 3 + j;
        xv[j] = (l >= 0)
              ? *(const float4*)(xz + (size_t)(row0 - 3 + j) * XZW + d4)
              : make_float4(0.f, 0.f, 0.f, 0.f);
    }
    const float4 bias = *(const float4*)(conv_b + d4);

#pragma unroll
    for (int i = 0; i < 4; i++) {
        float4 s = bias;
#pragma unroll
        for (int k = 0; k < 4; k++) {
            const float4 xvv = xv[i + k];
            s.x = fmaf(cw[0][k], xvv.x, s.x);
            s.y = fmaf(cw[1][k], xvv.y, s.y);
            s.z = fmaf(cw[2][k], xvv.z, s.z);
            s.w = fmaf(cw[3][k], xvv.w, s.w);
        }
        float4 o;
        o.x = s.x / (1.f + __expf(-s.x));
        o.y = s.y / (1.f + __expf(-s.y));
        o.z = s.z / (1.f + __expf(-s.z));
        o.w = s.w / (1.f + __expf(-s.w));
        *(float4*)(g_u[dir] + (size_t)(row0 + i) * DINNER + d4) = o;
        float4 r;
        r.x = tf32rf(o.x); r.y = tf32rf(o.y);
        r.z = tf32rf(o.z); r.w = tf32rf(o.w);
        *(float4*)(g_ur[dir] + (size_t)(row0 + i) * DINNER + d4) = r;
    }
}

// ---------------------------------------------------------------------------
// Selective scan — unroll 8, group double-buffered (loads one group ahead).
// One warp = 2 channels; 16 lanes = 16 states. dir1 output pre-flipped.
// 128-thread blocks (8 channels/block).
// ---------------------------------------------------------------------------
#define UNR   8
#define NGRP  (SEQL / UNR)

__global__ __launch_bounds__(128)
void scan_kernel(const float* __restrict__ fAlog, const float* __restrict__ fD,
                 const float* __restrict__ bAlog, const float* __restrict__ bD)
{
    const int dir = blockIdx.y;
    const float* Alog = dir ? bAlog : fAlog;
    const float* Dp   = dir ? bD    : fD;
    const float* delta = g_delta[dir];
    const float* u     = g_u[dir];
    const float* xdbl  = g_xdbl[dir];
    const float* xz    = g_xz[dir];
    float*       ypre  = g_ypre[dir];

    const int lane = threadIdx.x & 31;
    const int warp = threadIdx.x >> 5;
    const int half = lane >> 4;
    const int n    = lane & 15;

    const int c = blockIdx.x * 8 + warp * 2 + half;   // 0..3071
    const int b = c / DINNER;
    const int d = c - b * DINNER;

    const float Aneg = -__expf(Alog[d * DSTATE + n]);
    const float Dd   = Dp[d];
    const bool  ln0  = (n == 0);

    const size_t rowbase = (size_t)b * SEQL;
    const float* pDl = delta + rowbase * DINNER + d;
    const float* pU  = u     + rowbase * DINNER + d;
    const float* pB  = xdbl  + rowbase * XDBLW + DTRANK + n;
    const float* pC  = pB + DSTATE;
    const float* pZ  = xz    + rowbase * XZW + DINNER + d;

    float cdl[UNR], cuu[UNR], cBn[UNR], cCn[UNR], czz[UNR];

    auto load_grp = [&](int g, float* adl, float* auu, float* aBn,
                        float* aCn, float* azz) {
        const int l0 = g * UNR;
#pragma unroll
        for (int i = 0; i < UNR; i++) {
            adl[i] = pDl[(size_t)(l0 + i) * DINNER];
            auu[i] = pU [(size_t)(l0 + i) * DINNER];
            aBn[i] = pB [(size_t)(l0 + i) * XDBLW];
            aCn[i] = pC [(size_t)(l0 + i) * XDBLW];
        }
        if (ln0) {
#pragma unroll
            for (int i = 0; i < UNR; i++)
                azz[i] = pZ[(size_t)(l0 + i) * XZW];
        }
    };

    load_grp(0, cdl, cuu, cBn, cCn, czz);
    float h = 0.f;

    for (int g = 0; g < NGRP; g++) {
        float ndl[UNR], nuu[UNR], nBn[UNR], nCn[UNR], nzz[UNR];
        load_grp((g + 1 < NGRP) ? (g + 1) : 0, ndl, nuu, nBn, nCn, nzz);

        float dA[UNR];
#pragma unroll
        for (int i = 0; i < UNR; i++) dA[i] = __expf(cdl[i] * Aneg);

        float yp[UNR];
#pragma unroll
        for (int i = 0; i < UNR; i++) {
            h = fmaf(dA[i], h, cdl[i] * cBn[i] * cuu[i]);
            yp[i] = h * cCn[i];
        }

        // 8 independent shfl trees, level-major so they pipeline
#pragma unroll
        for (int s = 1; s <= 8; s <<= 1) {
#pragma unroll
            for (int i = 0; i < UNR; i++)
                yp[i] += __shfl_xor_sync(0xffffffffu, yp[i], s);
        }

        if (ln0) {
            const int l0 = g * UNR;
#pragma unroll
            for (int i = 0; i < UNR; i++) {
                float y = fmaf(cuu[i], Dd, yp[i]);
                const float zz = czz[i];
                y *= zz / (1.f + __expf(-zz));
                const size_t row  = rowbase + l0 + i;
                const size_t orow = dir ? (row ^ (SEQL - 1)) : row;
                ypre[orow * DINNER + d] = tf32rf(y);
            }
        }

#pragma unroll
        for (int i = 0; i < UNR; i++) {
            cdl[i] = ndl[i]; cuu[i] = nuu[i];
            cBn[i] = nBn[i]; cCn[i] = nCn[i]; czz[i] = nzz[i];
        }
    }
}

// ---------------------------------------------------------------------------
// Zeroing kernels.
// ---------------------------------------------------------------------------
__global__ void zero_kernel(float4* __restrict__ p, int n4)
{
    int i = blockIdx.x * blockDim.x + threadIdx.x;
    if (i < n4) p[i] = make_float4(0.f, 0.f, 0.f, 0.f);
}
__global__ void zero_scratch_kernel(int id, int n4)
{
    float4* p = (float4*)scratch_ptr(id, blockIdx.y);
    int i = blockIdx.x * blockDim.x + threadIdx.x;
    if (i < n4) p[i] = make_float4(0.f, 0.f, 0.f, 0.f);
}

// ---------------------------------------------------------------------------
// Host launch.
// ---------------------------------------------------------------------------
extern "C" void kernel_launch(void* const* d_in, const int* in_sizes, int n_in,
                              void* d_out, int out_size)
{
    const float* x = (const float*)d_in[0];
    float* out = (float*)d_out;

    const float* f_in_w    = (const float*)d_in[1];
    const float* f_conv_w  = (const float*)d_in[2];
    const float* f_conv_b  = (const float*)d_in[3];
    const float* f_xproj_w = (const float*)d_in[4];
    const float* f_dt_w    = (const float*)d_in[5];
    const float* f_dt_b    = (const float*)d_in[6];
    const float* f_Alog    = (const float*)d_in[7];
    const float* f_D       = (const float*)d_in[8];
    const float* f_out_w   = (const float*)d_in[9];
    const float* b_in_w    = (const float*)d_in[10];
    const float* b_conv_w  = (const float*)d_in[11];
    const float* b_conv_b  = (const float*)d_in[12];
    const float* b_xproj_w = (const float*)d_in[13];
    const float* b_dt_w    = (const float*)d_in[14];
    const float* b_dt_b    = (const float*)d_in[15];
    const float* b_Alog    = (const float*)d_in[16];
    const float* b_D       = (const float*)d_in[17];
    const float* b_out_w   = (const float*)d_in[18];

    // zero accumulation targets
    zero_kernel<<<(MTOT * DMODEL / 4 + 255) / 256, 256>>>(
        (float4*)out, MTOT * DMODEL / 4);
    zero_scratch_kernel<<<dim3((MTOT * XDBLW / 4 + 255) / 256, 2), 256>>>(
        BUF_XDBL, MTOT * XDBLW / 4);

    // tf32 pre-rounding of all GEMM operands
    round_tf32_kernel<<<dim3(256, 9), 256>>>(
        (const float4*)x,
        (const float4*)f_in_w,    (const float4*)b_in_w,
        (const float4*)f_out_w,   (const float4*)b_out_w,
        (const float4*)f_xproj_w, (const float4*)b_xproj_w,
        (const float4*)f_dt_w,    (const float4*)b_dt_w);

    // in_proj: xz = x(flip dir1) @ in_w^T   [2048,3072], K=768
    gemm_mma<ACT_NONE, true, false, 32, 2><<<dim3(XZW / 128, MTOT / 128, 2), 256>>>(
        BUF_XR, BUF_WIN, nullptr, nullptr, nullptr, BUF_XZ,
        XZW, DMODEL, DMODEL, XZW, XZW / 128, DMODEL);

    // depthwise conv + SiLU (writes u exact + u rounded)
    conv_silu_kernel<<<dim3(((MTOT / 4) * (DINNER / 4) + 255) / 256, 2), 256>>>(
        f_conv_w, f_conv_b, b_conv_w, b_conv_b);

    // x_proj (split-K x8, atomic): xdbl += u_r @ xproj_w^T   [2048,80], K=1536
    gemm_mma<ACT_NONE, false, true, 32, 2><<<dim3(8, MTOT / 128, 2), 256>>>(
        BUF_UR, BUF_WXP, nullptr, nullptr, nullptr, BUF_XDBL,
        XDBLW, DINNER, DINNER, XDBLW, 1, DINNER / 8);

    // round dt columns of the accumulated totals
    round_dt_kernel<<<dim3((MTOT * DTRANK + 255) / 256, 2), 256>>>();

    // delta: softplus(dtr @ dt_w^T + dt_b)   [2048,1536], K=48
    gemm_mma<ACT_SOFTPLUS, false, false, 16, 3><<<dim3(DINNER / 128, MTOT / 128, 2), 256>>>(
        BUF_DTR, BUF_WDT, f_dt_b, b_dt_b, nullptr, BUF_DELTA,
        DINNER, DTRANK, DTRANK, DINNER, DINNER / 128, DTRANK);

    // selective scan (unroll-8 double-buffered; dir1 output pre-flipped)
    scan_kernel<<<dim3((NB * DINNER) / 8, 2), 128>>>(f_Alog, f_D, b_Alog, b_D);

    // out_proj (split-K x2, atomic): out += ypre @ out_w^T   [2048,768], K=1536
    gemm_mma<ACT_NONE, false, true, 32, 2><<<dim3((DMODEL / 128) * 2, MTOT / 128, 2), 256>>>(
        BUF_YPRE, BUF_WOUT, nullptr, nullptr, out, -1,
        DMODEL, DINNER, DINNER, DMODEL, DMODEL / 128, DINNER / 2);
}

// round 9
// speedup vs baseline: 4.9659x; 1.0049x over previous
#include <cuda_runtime.h>
#include <cuda_bf16.h>
#include <cstdint>

// ---------------------------------------------------------------------------
// BidirectionalMambaLayer — Round 9: 3-stage BK=32 cp.async pipeline with
// dynamic smem (one sync per k-tile, load t+2 issued before compute t),
// ldmatrix fragments, fused init kernel. Numerics identical to round 8.
// ---------------------------------------------------------------------------

#define SEQL   1024
#define NB     2
#define MTOT   (NB * SEQL)
#define DMODEL 768
#define DINNER 1536
#define DSTATE 16
#define DTRANK 48
#define DCONV  4
#define XZW    (2 * DINNER)            // 3072
#define XDBLW  (DTRANK + 2 * DSTATE)   // 80

// -------------------------- scratch (device globals) -----------------------
__device__ float g_xz   [2][(size_t)MTOT * XZW];
__device__ float g_u    [2][(size_t)MTOT * DINNER];   // exact (scan)
__device__ float g_ur   [2][(size_t)MTOT * DINNER];   // tf32-rounded (x_proj)
__device__ float g_xdbl [2][(size_t)MTOT * XDBLW];    // exact totals (scan B/C)
__device__ float g_dtr  [2][(size_t)MTOT * DTRANK];   // rounded dt
__device__ float g_delta[2][(size_t)MTOT * DINNER];
__device__ float g_ypre [2][(size_t)MTOT * DINNER];   // rounded at scan write
__device__ float g_xr   [(size_t)MTOT * DMODEL];
__device__ float g_win  [2][(size_t)XZW * DMODEL];
__device__ float g_wxp  [2][(size_t)XDBLW * DINNER];
__device__ float g_wdt  [2][(size_t)DINNER * DTRANK];
__device__ float g_wout [2][(size_t)DMODEL * DINNER];

enum { BUF_XZ = 0, BUF_U, BUF_UR, BUF_XDBL, BUF_DTR, BUF_DELTA, BUF_YPRE,
       BUF_XR, BUF_WIN, BUF_WXP, BUF_WDT, BUF_WOUT };

__device__ __forceinline__ float* scratch_ptr(int id, int dir) {
    switch (id) {
        case BUF_XZ:    return g_xz[dir];
        case BUF_U:     return g_u[dir];
        case BUF_UR:    return g_ur[dir];
        case BUF_XDBL:  return g_xdbl[dir];
        case BUF_DTR:   return g_dtr[dir];
        case BUF_DELTA: return g_delta[dir];
        case BUF_YPRE:  return g_ypre[dir];
        case BUF_XR:    return g_xr;
        case BUF_WIN:   return g_win[dir];
        case BUF_WXP:   return g_wxp[dir];
        case BUF_WDT:   return g_wdt[dir];
        case BUF_WOUT:  return g_wout[dir];
    }
    return nullptr;
}

enum { ACT_NONE = 0, ACT_SOFTPLUS = 1 };

__device__ __forceinline__ uint32_t tf32u(float x) {
    uint32_t u;
    asm("cvt.rna.tf32.f32 %0, %1;" : "=r"(u) : "f"(x));
    return u;
}
__device__ __forceinline__ float tf32rf(float x) { return __uint_as_float(tf32u(x)); }

__device__ __forceinline__ void cp16(uint32_t saddr, const float* gptr, bool ok) {
    int sz = ok ? 16 : 0;
    asm volatile("cp.async.cg.shared.global [%0], [%1], 16, %2;"
                 :: "r"(saddr), "l"(gptr), "r"(sz));
}
__device__ __forceinline__ void cp_commit() { asm volatile("cp.async.commit_group;"); }
__device__ __forceinline__ void cp_wait1()  { asm volatile("cp.async.wait_group 1;"); }
__device__ __forceinline__ void cp_wait0()  { asm volatile("cp.async.wait_group 0;"); }

__device__ __forceinline__ void ldsm_x4(uint32_t& r0, uint32_t& r1,
                                        uint32_t& r2, uint32_t& r3, uint32_t a) {
    asm volatile("ldmatrix.sync.aligned.m8n8.x4.shared.b16 {%0,%1,%2,%3}, [%4];"
                 : "=r"(r0), "=r"(r1), "=r"(r2), "=r"(r3) : "r"(a));
}

// ---------------------------------------------------------------------------
// tf32 mma.sync TN GEMM, dir-merged (blockIdx.z), optional split-K.
// BM=BN=128, 256 threads (8 warps 2m x 4n), warp tile 64x32, m16n8k8.tf32.
// 3-stage cp.async pipeline in DYNAMIC smem: one __syncthreads per k-tile,
// tile t+2's loads issue before compute of tile t.
// Operands MUST be pre-rounded tf32.
// ---------------------------------------------------------------------------
template<int ACT, bool FLIPA1, bool ATOMIC, int BK>
__global__ __launch_bounds__(256, 2)
void gemm_mma(int aId, int bId,
              const float* __restrict__ bias0, const float* __restrict__ bias1,
              float* __restrict__ Cext, int cId,
              int N, int K, int lda, int ldc, int nxt, int kchunk)
{
    constexpr int STG  = 3;
    constexpr int SASX = BK + 4;
    constexpr int CPR  = BK / 4;
    constexpr int LIT  = 128 * CPR / 256;

    const int dir = blockIdx.z;
    const float* A    = scratch_ptr(aId, dir);
    const float* W    = scratch_ptr(bId, dir);
    const float* bias = dir ? bias1 : bias0;
    float*       C    = Cext ? Cext : scratch_ptr(cId, dir);

    const int split = blockIdx.x / nxt;
    const int bn    = (blockIdx.x - split * nxt) * 128;
    const int bm    = blockIdx.y * 128;
    const int kbeg  = split * kchunk;
    const int T     = kchunk / BK;

    extern __shared__ float dynsmem[];

    const int tid  = threadIdx.x;
    const int lane = tid & 31;
    const int warp = tid >> 5;
    const int wm   = warp >> 2;
    const int wn   = warp & 3;
    const int gr   = lane >> 2;
    const int tq   = lane & 3;

    const uint32_t stage_bytes = 128 * SASX * 4;
    const uint32_t sAb = (uint32_t)__cvta_generic_to_shared(dynsmem);
    const uint32_t sBb = sAb + STG * stage_bytes;

    const uint32_t laneA =
        ((uint32_t)((wm * 64 + (lane & 15)) * SASX + (lane >> 4) * 4)) * 4;
    const uint32_t laneB =
        ((uint32_t)((wn * 32 + (lane & 7) + ((lane & 16) ? 8 : 0)) * SASX +
                    ((lane & 8) ? 4 : 0))) * 4;

    int arow[LIT], aq[LIT];
    uint32_t soff[LIT];
#pragma unroll
    for (int i = 0; i < LIT; i++) {
        const int c = tid + i * 256;
        arow[i] = c / CPR;
        aq[i]   = (c - arow[i] * CPR) * 4;
        soff[i] = (uint32_t)(arow[i] * SASX + aq[i]) * 4;
    }

    auto load_tile = [&](int t, int st) {
        const int kof = kbeg + t * BK;
#pragma unroll
        for (int i = 0; i < LIT; i++) {
            int gm = bm + arow[i];
            if (FLIPA1 && dir) gm ^= (SEQL - 1);
            cp16(sAb + st * stage_bytes + soff[i],
                 A + (size_t)gm * lda + kof + aq[i], true);
        }
#pragma unroll
        for (int i = 0; i < LIT; i++) {
            const int wr = bn + arow[i];
            cp16(sBb + st * stage_bytes + soff[i],
                 W + (size_t)wr * K + kof + aq[i], wr < N);
        }
        cp_commit();
    };

    float acc[4][4][4];
#pragma unroll
    for (int mt = 0; mt < 4; mt++)
#pragma unroll
        for (int nt = 0; nt < 4; nt++)
#pragma unroll
            for (int r = 0; r < 4; r++) acc[mt][nt][r] = 0.f;

    load_tile(0, 0);
    if (T > 1) load_tile(1, 1);

    for (int t = 0; t < T; t++) {
        const int st = t % STG;
        if (t + 1 < T) cp_wait1(); else cp_wait0();
        __syncthreads();   // all warps done reading stage (t+2)%3 (tile t-1)

        if (t + 2 < T) load_tile(t + 2, (t + 2) % STG);

        const uint32_t aAddr = sAb + st * stage_bytes + laneA;
        const uint32_t bAddr = sBb + st * stage_bytes + laneB;
#pragma unroll
        for (int ks = 0; ks < BK / 8; ks++) {
            const uint32_t kb4 = (uint32_t)(ks * 8) * 4;
            uint32_t a[4][4], b[4][2];
#pragma unroll
            for (int mt = 0; mt < 4; mt++)
                ldsm_x4(a[mt][0], a[mt][1], a[mt][2], a[mt][3],
                        aAddr + (uint32_t)(mt * 16 * SASX) * 4 + kb4);
#pragma unroll
            for (int p = 0; p < 2; p++)
                ldsm_x4(b[2 * p][0], b[2 * p][1], b[2 * p + 1][0], b[2 * p + 1][1],
                        bAddr + (uint32_t)(p * 16 * SASX) * 4 + kb4);
#pragma unroll
            for (int mt = 0; mt < 4; mt++)
#pragma unroll
                for (int nt = 0; nt < 4; nt++) {
                    asm volatile(
                        "mma.sync.aligned.m16n8k8.row.col.f32.tf32.tf32.f32 "
                        "{%0,%1,%2,%3}, {%4,%5,%6,%7}, {%8,%9}, {%0,%1,%2,%3};"
                        : "+f"(acc[mt][nt][0]), "+f"(acc[mt][nt][1]),
                          "+f"(acc[mt][nt][2]), "+f"(acc[mt][nt][3])
                        : "r"(a[mt][0]), "r"(a[mt][1]), "r"(a[mt][2]), "r"(a[mt][3]),
                          "r"(b[nt][0]), "r"(b[nt][1]));
                }
        }
    }

    // epilogue
#pragma unroll
    for (int mt = 0; mt < 4; mt++) {
        const int m0 = bm + wm * 64 + mt * 16 + gr;
#pragma unroll
        for (int half = 0; half < 2; half++) {
            const int m = m0 + half * 8;
#pragma unroll
            for (int nt = 0; nt < 4; nt++) {
                const int nbase = bn + wn * 32 + nt * 8 + 2 * tq;
#pragma unroll
                for (int j = 0; j < 2; j++) {
                    const int n = nbase + j;
                    if (n < N) {
                        float v = acc[mt][nt][half * 2 + j];
                        if (bias) v += bias[n];
                        if (ACT == ACT_SOFTPLUS)
                            v = (v > 20.f) ? v : log1pf(__expf(v));
                        if (ATOMIC) atomicAdd(&C[(size_t)m * ldc + n], v);
                        else        C[(size_t)m * ldc + n] = v;
                    }
                }
            }
        }
    }
}

// smem sizes for the instantiations
#define SMEM_BK32 (3 * (128 * 36 * 4) * 2)   // 110592 B
#define SMEM_BK16 (3 * (128 * 20 * 4) * 2)   // 61440 B

// ---------------------------------------------------------------------------
// Fused init: zero(out), zero(xdbl), + 9 tf32-rounding slices.
// blockIdx.y: 0=zero out, 1/2=zero xdbl, 3..11 rounding.
// ---------------------------------------------------------------------------
__global__ void init_kernel(float4* __restrict__ out4,
                            const float4* __restrict__ x,
                            const float4* __restrict__ fiw, const float4* __restrict__ biw,
                            const float4* __restrict__ fow, const float4* __restrict__ bow,
                            const float4* __restrict__ fxp, const float4* __restrict__ bxp,
                            const float4* __restrict__ fdw, const float4* __restrict__ bdw)
{
    const float4* src = nullptr; float4* dst; int n4;
    switch (blockIdx.y) {
        case 0:  dst = out4;                  n4 = MTOT * DMODEL / 4;    break;
        case 1:  dst = (float4*)g_xdbl[0];    n4 = MTOT * XDBLW / 4;     break;
        case 2:  dst = (float4*)g_xdbl[1];    n4 = MTOT * XDBLW / 4;     break;
        case 3:  src = x;   dst = (float4*)g_xr;      n4 = MTOT * DMODEL / 4;   break;
        case 4:  src = fiw; dst = (float4*)g_win[0];  n4 = XZW * DMODEL / 4;    break;
        case 5:  src = biw; dst = (float4*)g_win[1];  n4 = XZW * DMODEL / 4;    break;
        case 6:  src = fow; dst = (float4*)g_wout[0]; n4 = DMODEL * DINNER / 4; break;
        case 7:  src = bow; dst = (float4*)g_wout[1]; n4 = DMODEL * DINNER / 4; break;
        case 8:  src = fxp; dst = (float4*)g_wxp[0];  n4 = XDBLW * DINNER / 4;  break;
        case 9:  src = bxp; dst = (float4*)g_wxp[1];  n4 = XDBLW * DINNER / 4;  break;
        case 10: src = fdw; dst = (float4*)g_wdt[0];  n4 = DINNER * DTRANK / 4; break;
        default: src = bdw; dst = (float4*)g_wdt[1];  n4 = DINNER * DTRANK / 4; break;
    }
    if (src == nullptr) {
        for (int i = blockIdx.x * blockDim.x + threadIdx.x; i < n4;
             i += gridDim.x * blockDim.x)
            dst[i] = make_float4(0.f, 0.f, 0.f, 0.f);
    } else {
        for (int i = blockIdx.x * blockDim.x + threadIdx.x; i < n4;
             i += gridDim.x * blockDim.x) {
            float4 v = src[i];
            v.x = tf32rf(v.x); v.y = tf32rf(v.y);
            v.z = tf32rf(v.z); v.w = tf32rf(v.w);
            dst[i] = v;
        }
    }
}

__global__ void round_dt_kernel()
{
    const int dir = blockIdx.y;
    const int e = blockIdx.x * blockDim.x + threadIdx.x;
    if (e >= MTOT * DTRANK) return;
    const int row = e / DTRANK;
    const int j   = e - row * DTRANK;
    g_dtr[dir][e] = tf32rf(g_xdbl[dir][(size_t)row * XDBLW + j]);
}

// ---------------------------------------------------------------------------
// Causal depthwise conv (D_CONV=4) + bias + SiLU, l-tiled x4.
// ---------------------------------------------------------------------------
__global__ void conv_silu_kernel(const float* __restrict__ f_conv_w,
                                 const float* __restrict__ f_conv_b,
                                 const float* __restrict__ b_conv_w,
                                 const float* __restrict__ b_conv_b)
{
    const int dir = blockIdx.y;
    const float* conv_w = dir ? b_conv_w : f_conv_w;
    const float* conv_b = dir ? b_conv_b : f_conv_b;

    const int NCH = DINNER / 4;
    const int idx = blockIdx.x * blockDim.x + threadIdx.x;
    if (idx >= (MTOT / 4) * NCH) return;
    const int rt   = idx / NCH;
    const int d4   = (idx - rt * NCH) * 4;
    const int row0 = rt * 4;
    const int l0   = row0 & (SEQL - 1);

    const float* xz = g_xz[dir];
    float cw[4][4];
#pragma unroll
    for (int j = 0; j < 4; j++) {
        const float4 w = *(const float4*)(conv_w + (d4 + j) * DCONV);
        cw[j][0] = w.x; cw[j][1] = w.y; cw[j][2] = w.z; cw[j][3] = w.w;
    }

    float4 xv[7];
#pragma unroll
    for (int j = 0; j < 7; j++) {
        const int l = l0 - 3 + j;
        xv[j] = (l >= 0)
              ? *(const float4*)(xz + (size_t)(row0 - 3 + j) * XZW + d4)
              : make_float4(0.f, 0.f, 0.f, 0.f);
    }
    const float4 bias = *(const float4*)(conv_b + d4);

#pragma unroll
    for (int i = 0; i < 4; i++) {
        float4 s = bias;
#pragma unroll
        for (int k = 0; k < 4; k++) {
            const float4 xvv = xv[i + k];
            s.x = fmaf(cw[0][k], xvv.x, s.x);
            s.y = fmaf(cw[1][k], xvv.y, s.y);
            s.z = fmaf(cw[2][k], xvv.z, s.z);
            s.w = fmaf(cw[3][k], xvv.w, s.w);
        }
        float4 o;
        o.x = s.x / (1.f + __expf(-s.x));
        o.y = s.y / (1.f + __expf(-s.y));
        o.z = s.z / (1.f + __expf(-s.z));
        o.w = s.w / (1.f + __expf(-s.w));
        *(float4*)(g_u[dir] + (size_t)(row0 + i) * DINNER + d4) = o;
        float4 r;
        r.x = tf32rf(o.x); r.y = tf32rf(o.y);
        r.z = tf32rf(o.z); r.w = tf32rf(o.w);
        *(float4*)(g_ur[dir] + (size_t)(row0 + i) * DINNER + d4) = r;
    }
}

// ---------------------------------------------------------------------------
// Selective scan — unroll 8, group double-buffered. dir1 output pre-flipped.
// ---------------------------------------------------------------------------
#define UNR   8
#define NGRP  (SEQL / UNR)

__global__ __launch_bounds__(128)
void scan_kernel(const float* __restrict__ fAlog, const float* __restrict__ fD,
                 const float* __restrict__ bAlog, const float* __restrict__ bD)
{
    const int dir = blockIdx.y;
    const float* Alog = dir ? bAlog : fAlog;
    const float* Dp   = dir ? bD    : fD;
    const float* delta = g_delta[dir];
    const float* u     = g_u[dir];
    const float* xdbl  = g_xdbl[dir];
    const float* xz    = g_xz[dir];
    float*       ypre  = g_ypre[dir];

    const int lane = threadIdx.x & 31;
    const int warp = threadIdx.x >> 5;
    const int half = lane >> 4;
    const int n    = lane & 15;

    const int c = blockIdx.x * 8 + warp * 2 + half;
    const int b = c / DINNER;
    const int d = c - b * DINNER;

    const float Aneg = -__expf(Alog[d * DSTATE + n]);
    const float Dd   = Dp[d];
    const bool  ln0  = (n == 0);

    const size_t rowbase = (size_t)b * SEQL;
    const float* pDl = delta + rowbase * DINNER + d;
    const float* pU  = u     + rowbase * DINNER + d;
    const float* pB  = xdbl  + rowbase * XDBLW + DTRANK + n;
    const float* pC  = pB + DSTATE;
    const float* pZ  = xz    + rowbase * XZW + DINNER + d;

    float cdl[UNR], cuu[UNR], cBn[UNR], cCn[UNR], czz[UNR];

    auto load_grp = [&](int g, float* adl, float* auu, float* aBn,
                        float* aCn, float* azz) {
        const int l0 = g * UNR;
#pragma unroll
        for (int i = 0; i < UNR; i++) {
            adl[i] = pDl[(size_t)(l0 + i) * DINNER];
            auu[i] = pU [(size_t)(l0 + i) * DINNER];
            aBn[i] = pB [(size_t)(l0 + i) * XDBLW];
            aCn[i] = pC [(size_t)(l0 + i) * XDBLW];
        }
        if (ln0) {
#pragma unroll
            for (int i = 0; i < UNR; i++)
                azz[i] = pZ[(size_t)(l0 + i) * XZW];
        }
    };

    load_grp(0, cdl, cuu, cBn, cCn, czz);
    float h = 0.f;

    for (int g = 0; g < NGRP; g++) {
        float ndl[UNR], nuu[UNR], nBn[UNR], nCn[UNR], nzz[UNR];
        load_grp((g + 1 < NGRP) ? (g + 1) : 0, ndl, nuu, nBn, nCn, nzz);

        float dA[UNR];
#pragma unroll
        for (int i = 0; i < UNR; i++) dA[i] = __expf(cdl[i] * Aneg);

        float yp[UNR];
#pragma unroll
        for (int i = 0; i < UNR; i++) {
            h = fmaf(dA[i], h, cdl[i] * cBn[i] * cuu[i]);
            yp[i] = h * cCn[i];
        }

#pragma unroll
        for (int s = 1; s <= 8; s <<= 1) {
#pragma unroll
            for (int i = 0; i < UNR; i++)
                yp[i] += __shfl_xor_sync(0xffffffffu, yp[i], s);
        }

        if (ln0) {
            const int l0 = g * UNR;
#pragma unroll
            for (int i = 0; i < UNR; i++) {
                float y = fmaf(cuu[i], Dd, yp[i]);
                const float zz = czz[i];
                y *= zz / (1.f + __expf(-zz));
                const size_t row  = rowbase + l0 + i;
                const size_t orow = dir ? (row ^ (SEQL - 1)) : row;
                ypre[orow * DINNER + d] = tf32rf(y);
            }
        }

#pragma unroll
        for (int i = 0; i < UNR; i++) {
            cdl[i] = ndl[i]; cuu[i] = nuu[i];
            cBn[i] = nBn[i]; cCn[i] = nCn[i]; czz[i] = nzz[i];
        }
    }
}

// ---------------------------------------------------------------------------
// Host launch.
// ---------------------------------------------------------------------------
extern "C" void kernel_launch(void* const* d_in, const int* in_sizes, int n_in,
                              void* d_out, int out_size)
{
    const float* x = (const float*)d_in[0];
    float* out = (float*)d_out;

    const float* f_in_w    = (const float*)d_in[1];
    const float* f_conv_w  = (const float*)d_in[2];
    const float* f_conv_b  = (const float*)d_in[3];
    const float* f_xproj_w = (const float*)d_in[4];
    const float* f_dt_w    = (const float*)d_in[5];
    const float* f_dt_b    = (const float*)d_in[6];
    const float* f_Alog    = (const float*)d_in[7];
    const float* f_D       = (const float*)d_in[8];
    const float* f_out_w   = (const float*)d_in[9];
    const float* b_in_w    = (const float*)d_in[10];
    const float* b_conv_w  = (const float*)d_in[11];
    const float* b_conv_b  = (const float*)d_in[12];
    const float* b_xproj_w = (const float*)d_in[13];
    const float* b_dt_w    = (const float*)d_in[14];
    const float* b_dt_b    = (const float*)d_in[15];
    const float* b_Alog    = (const float*)d_in[16];
    const float* b_D       = (const float*)d_in[17];
    const float* b_out_w   = (const float*)d_in[18];

    // opt-in dynamic smem for the GEMM instantiations (idempotent host calls)
    cudaFuncSetAttribute(gemm_mma<ACT_NONE, true,  false, 32>,
                         cudaFuncAttributeMaxDynamicSharedMemorySize, SMEM_BK32);
    cudaFuncSetAttribute(gemm_mma<ACT_NONE, false, true,  32>,
                         cudaFuncAttributeMaxDynamicSharedMemorySize, SMEM_BK32);
    cudaFuncSetAttribute(gemm_mma<ACT_SOFTPLUS, false, false, 16>,
                         cudaFuncAttributeMaxDynamicSharedMemorySize, SMEM_BK16);

    // fused init: zero out/xdbl + tf32 pre-rounding of all GEMM operands
    init_kernel<<<dim3(160, 12), 256>>>(
        (float4*)out, (const float4*)x,
        (const float4*)f_in_w,    (const float4*)b_in_w,
        (const float4*)f_out_w,   (const float4*)b_out_w,
        (const float4*)f_xproj_w, (const float4*)b_xproj_w,
        (const float4*)f_dt_w,    (const float4*)b_dt_w);

    // in_proj: xz = x(flip dir1) @ in_w^T   [2048,3072], K=768
    gemm_mma<ACT_NONE, true, false, 32>
        <<<dim3(XZW / 128, MTOT / 128, 2), 256, SMEM_BK32>>>(
        BUF_XR, BUF_WIN, nullptr, nullptr, nullptr, BUF_XZ,
        XZW, DMODEL, DMODEL, XZW, XZW / 128, DMODEL);

    // depthwise conv + SiLU (writes u exact + u rounded)
    conv_silu_kernel<<<dim3(((MTOT / 4) * (DINNER / 4) + 255) / 256, 2), 256>>>(
        f_conv_w, f_conv_b, b_conv_w, b_conv_b);

    // x_proj (split-K x8, atomic): xdbl += u_r @ xproj_w^T   [2048,80], K=1536
    gemm_mma<ACT_NONE, false, true, 32>
        <<<dim3(8, MTOT / 128, 2), 256, SMEM_BK32>>>(
        BUF_UR, BUF_WXP, nullptr, nullptr, nullptr, BUF_XDBL,
        XDBLW, DINNER, DINNER, XDBLW, 1, DINNER / 8);

    // round dt columns of the accumulated totals
    round_dt_kernel<<<dim3((MTOT * DTRANK + 255) / 256, 2), 256>>>();

    // delta: softplus(dtr @ dt_w^T + dt_b)   [2048,1536], K=48
    gemm_mma<ACT_SOFTPLUS, false, false, 16>
        <<<dim3(DINNER / 128, MTOT / 128, 2), 256, SMEM_BK16>>>(
        BUF_DTR, BUF_WDT, f_dt_b, b_dt_b, nullptr, BUF_DELTA,
        DINNER, DTRANK, DTRANK, DINNER, DINNER / 128, DTRANK);

    // selective scan (unroll-8 double-buffered; dir1 output pre-flipped)
    scan_kernel<<<dim3((NB * DINNER) / 8, 2), 128>>>(f_Alog, f_D, b_Alog, b_D);

    // out_proj (split-K x2, atomic): out += ypre @ out_w^T   [2048,768], K=1536
    gemm_mma<ACT_NONE, false, true, 32>
        <<<dim3((DMODEL / 128) * 2, MTOT / 128, 2), 256, SMEM_BK32>>>(
        BUF_YPRE, BUF_WOUT, nullptr, nullptr, out, -1,
        DMODEL, DINNER, DINNER, DMODEL, DMODEL / 128, DINNER / 2);
}

// round 10
// speedup vs baseline: 5.8931x; 1.1867x over previous
#include <cuda_runtime.h>
#include <cuda_bf16.h>
#include <cuda_fp16.h>
#include <cstdint>

// ---------------------------------------------------------------------------
// BidirectionalMambaLayer — Round 10: fp16-operand mma.sync GEMMs
// (m16n8k16.f16, fp32 accumulate — same 11-bit relative precision as tf32,
// 2x HMMA throughput), 4-stage BK=32 cp.async pipeline, ldmatrix fragments.
// Non-GEMM path identical to round 9.
// ---------------------------------------------------------------------------

#define SEQL   1024
#define NB     2
#define MTOT   (NB * SEQL)
#define DMODEL 768
#define DINNER 1536
#define DSTATE 16
#define DTRANK 48
#define DCONV  4
#define XZW    (2 * DINNER)            // 3072
#define XDBLW  (DTRANK + 2 * DSTATE)   // 80

// -------------------------- scratch (device globals) -----------------------
__device__ float  g_xz   [2][(size_t)MTOT * XZW];
__device__ float  g_u    [2][(size_t)MTOT * DINNER];  // exact (scan)
__device__ __half g_ur   [2][(size_t)MTOT * DINNER];  // fp16 (x_proj A)
__device__ float  g_xdbl [2][(size_t)MTOT * XDBLW];   // exact totals (scan B/C)
__device__ __half g_dtr  [2][(size_t)MTOT * DTRANK];  // fp16 dt (delta A)
__device__ float  g_delta[2][(size_t)MTOT * DINNER];
__device__ __half g_ypre [2][(size_t)MTOT * DINNER];  // fp16 (out_proj A)
__device__ __half g_xr   [(size_t)MTOT * DMODEL];     // fp16 x
__device__ __half g_win  [2][(size_t)XZW * DMODEL];
__device__ __half g_wxp  [2][(size_t)XDBLW * DINNER];
__device__ __half g_wdt  [2][(size_t)DINNER * DTRANK];
__device__ __half g_wout [2][(size_t)DMODEL * DINNER];

enum { HBUF_XR = 0, HBUF_UR, HBUF_DTR, HBUF_YPRE,
       HBUF_WIN, HBUF_WXP, HBUF_WDT, HBUF_WOUT };

__device__ __forceinline__ __half* scratch_h(int id, int dir) {
    switch (id) {
        case HBUF_XR:   return g_xr;
        case HBUF_UR:   return g_ur[dir];
        case HBUF_DTR:  return g_dtr[dir];
        case HBUF_YPRE: return g_ypre[dir];
        case HBUF_WIN:  return g_win[dir];
        case HBUF_WXP:  return g_wxp[dir];
        case HBUF_WDT:  return g_wdt[dir];
        case HBUF_WOUT: return g_wout[dir];
    }
    return nullptr;
}

enum { ACT_NONE = 0, ACT_SOFTPLUS = 1 };

__device__ __forceinline__ void cp16(uint32_t saddr, const __half* gptr, bool ok) {
    int sz = ok ? 16 : 0;
    asm volatile("cp.async.cg.shared.global [%0], [%1], 16, %2;"
                 :: "r"(saddr), "l"(gptr), "r"(sz));
}
__device__ __forceinline__ void cp_commit() { asm volatile("cp.async.commit_group;"); }
__device__ __forceinline__ void cp_wait2()  { asm volatile("cp.async.wait_group 2;"); }
__device__ __forceinline__ void cp_wait1()  { asm volatile("cp.async.wait_group 1;"); }
__device__ __forceinline__ void cp_wait0()  { asm volatile("cp.async.wait_group 0;"); }

__device__ __forceinline__ void ldsm_x4(uint32_t& r0, uint32_t& r1,
                                        uint32_t& r2, uint32_t& r3, uint32_t a) {
    asm volatile("ldmatrix.sync.aligned.m8n8.x4.shared.b16 {%0,%1,%2,%3}, [%4];"
                 : "=r"(r0), "=r"(r1), "=r"(r2), "=r"(r3) : "r"(a));
}

// ---------------------------------------------------------------------------
// fp16 mma.sync TN GEMM, dir-merged (blockIdx.z), optional split-K.
// BM=BN=128, 256 threads (8 warps 2m x 4n), warp tile 64x32, m16n8k16.f16
// with fp32 accumulators. STG-stage cp.async pipeline (dynamic smem),
// one __syncthreads per k-tile. Operands are pre-converted fp16.
// ---------------------------------------------------------------------------
template<int ACT, bool FLIPA1, bool ATOMIC, int BK, int STG>
__global__ __launch_bounds__(256, 2)
void gemm_h(int aId, int bId,
            const float* __restrict__ bias0, const float* __restrict__ bias1,
            float* __restrict__ Cext, float* __restrict__ Cd0, float* __restrict__ Cd1,
            int N, int K, int lda, int ldc, int nxt, int kchunk)
{
    constexpr int SASX = BK + 8;            // smem row stride (halves), 16B pad
    constexpr int CPR  = BK / 8;            // 16B chunks per row
    constexpr int LIT  = 128 * CPR / 256;   // load iters per matrix

    const int dir = blockIdx.z;
    const __half* A = scratch_h(aId, dir);
    const __half* W = scratch_h(bId, dir);
    const float* bias = dir ? bias1 : bias0;
    float*       C    = Cext ? Cext : (dir ? Cd1 : Cd0);

    const int split = blockIdx.x / nxt;
    const int bn    = (blockIdx.x - split * nxt) * 128;
    const int bm    = blockIdx.y * 128;
    const int kbeg  = split * kchunk;
    const int T     = kchunk / BK;

    extern __shared__ __half dynsmem_h[];

    const int tid  = threadIdx.x;
    const int lane = tid & 31;
    const int warp = tid >> 5;
    const int wm   = warp >> 2;
    const int wn   = warp & 3;
    const int gr   = lane >> 2;
    const int tq   = lane & 3;

    const uint32_t stage_bytes = 128 * SASX * 2;
    const uint32_t sAb = (uint32_t)__cvta_generic_to_shared(dynsmem_h);
    const uint32_t sBb = sAb + STG * stage_bytes;

    // ldmatrix lane addresses (bytes)
    const uint32_t laneA =
        ((uint32_t)((wm * 64 + (lane & 15)) * SASX + (lane >> 4) * 8)) * 2;
    const uint32_t laneB =
        ((uint32_t)((wn * 32 + (lane & 7) + ((lane & 16) ? 8 : 0)) * SASX +
                    ((lane & 8) ? 8 : 0))) * 2;

    int arow[LIT], aq[LIT];
    uint32_t soff[LIT];
#pragma unroll
    for (int i = 0; i < LIT; i++) {
        const int c = tid + i * 256;
        arow[i] = c / CPR;
        aq[i]   = (c - arow[i] * CPR) * 8;                      // halves
        soff[i] = (uint32_t)(arow[i] * SASX + aq[i]) * 2;       // bytes
    }

    auto load_tile = [&](int t, int st) {
        const int kof = kbeg + t * BK;
#pragma unroll
        for (int i = 0; i < LIT; i++) {
            int gm = bm + arow[i];
            if (FLIPA1 && dir) gm ^= (SEQL - 1);
            cp16(sAb + st * stage_bytes + soff[i],
                 A + (size_t)gm * lda + kof + aq[i], true);
        }
#pragma unroll
        for (int i = 0; i < LIT; i++) {
            const int wr = bn + arow[i];
            cp16(sBb + st * stage_bytes + soff[i],
                 W + (size_t)wr * K + kof + aq[i], wr < N);
        }
        cp_commit();
    };

    float acc[4][4][4];
#pragma unroll
    for (int mt = 0; mt < 4; mt++)
#pragma unroll
        for (int nt = 0; nt < 4; nt++)
#pragma unroll
            for (int r = 0; r < 4; r++) acc[mt][nt][r] = 0.f;

    // prologue: fill STG-1 stages
#pragma unroll
    for (int p = 0; p < STG - 1; p++)
        if (p < T) load_tile(p, p);

    for (int t = 0; t < T; t++) {
        const int st  = t % STG;
        const int rem = T - 1 - t;
        if (STG == 4) {
            if (rem >= 2) cp_wait2(); else if (rem == 1) cp_wait1(); else cp_wait0();
        } else {
            if (rem >= 1) cp_wait1(); else cp_wait0();
        }
        __syncthreads();

        if (t + STG - 1 < T) load_tile(t + STG - 1, (t + STG - 1) % STG);

        const uint32_t aAddr = sAb + st * stage_bytes + laneA;
        const uint32_t bAddr = sBb + st * stage_bytes + laneB;
#pragma unroll
        for (int ks = 0; ks < BK / 16; ks++) {
            const uint32_t kb2 = (uint32_t)(ks * 16) * 2;   // bytes
            uint32_t a[4][4], b[4][2];
#pragma unroll
            for (int mt = 0; mt < 4; mt++)
                ldsm_x4(a[mt][0], a[mt][1], a[mt][2], a[mt][3],
                        aAddr + (uint32_t)(mt * 16 * SASX) * 2 + kb2);
#pragma unroll
            for (int p = 0; p < 2; p++)
                ldsm_x4(b[2 * p][0], b[2 * p][1], b[2 * p + 1][0], b[2 * p + 1][1],
                        bAddr + (uint32_t)(p * 16 * SASX) * 2 + kb2);
#pragma unroll
            for (int mt = 0; mt < 4; mt++)
#pragma unroll
                for (int nt = 0; nt < 4; nt++) {
                    asm volatile(
                        "mma.sync.aligned.m16n8k16.row.col.f32.f16.f16.f32 "
                        "{%0,%1,%2,%3}, {%4,%5,%6,%7}, {%8,%9}, {%0,%1,%2,%3};"
                        : "+f"(acc[mt][nt][0]), "+f"(acc[mt][nt][1]),
                          "+f"(acc[mt][nt][2]), "+f"(acc[mt][nt][3])
                        : "r"(a[mt][0]), "r"(a[mt][1]), "r"(a[mt][2]), "r"(a[mt][3]),
                          "r"(b[nt][0]), "r"(b[nt][1]));
                }
        }
    }

    // epilogue (fp32)
#pragma unroll
    for (int mt = 0; mt < 4; mt++) {
        const int m0 = bm + wm * 64 + mt * 16 + gr;
#pragma unroll
        for (int half = 0; half < 2; half++) {
            const int m = m0 + half * 8;
#pragma unroll
            for (int nt = 0; nt < 4; nt++) {
                const int nbase = bn + wn * 32 + nt * 8 + 2 * tq;
#pragma unroll
                for (int j = 0; j < 2; j++) {
                    const int n = nbase + j;
                    if (n < N) {
                        float v = acc[mt][nt][half * 2 + j];
                        if (bias) v += bias[n];
                        if (ACT == ACT_SOFTPLUS)
                            v = (v > 20.f) ? v : log1pf(__expf(v));
                        if (ATOMIC) atomicAdd(&C[(size_t)m * ldc + n], v);
                        else        C[(size_t)m * ldc + n] = v;
                    }
                }
            }
        }
    }
}

// smem bytes for the instantiations
#define SMEM_BK32 (4 * (128 * 40 * 2) * 2)   // 81920 B (STG=4)
#define SMEM_BK16 (3 * (128 * 24 * 2) * 2)   // 36864 B (STG=3)

// ---------------------------------------------------------------------------
// Fused init: zero(out), zero(xdbl x2), + 9 fp16-conversion slices.
// ---------------------------------------------------------------------------
__global__ void init_kernel(float4* __restrict__ out4,
                            const float4* __restrict__ x,
                            const float4* __restrict__ fiw, const float4* __restrict__ biw,
                            const float4* __restrict__ fow, const float4* __restrict__ bow,
                            const float4* __restrict__ fxp, const float4* __restrict__ bxp,
                            const float4* __restrict__ fdw, const float4* __restrict__ bdw)
{
    const float4* src = nullptr; __half* hdst = nullptr; float4* zdst = nullptr; int n4;
    switch (blockIdx.y) {
        case 0:  zdst = out4;               n4 = MTOT * DMODEL / 4;    break;
        case 1:  zdst = (float4*)g_xdbl[0]; n4 = MTOT * XDBLW / 4;     break;
        case 2:  zdst = (float4*)g_xdbl[1]; n4 = MTOT * XDBLW / 4;     break;
        case 3:  src = x;   hdst = g_xr;      n4 = MTOT * DMODEL / 4;   break;
        case 4:  src = fiw; hdst = g_win[0];  n4 = XZW * DMODEL / 4;    break;
        case 5:  src = biw; hdst = g_win[1];  n4 = XZW * DMODEL / 4;    break;
        case 6:  src = fow; hdst = g_wout[0]; n4 = DMODEL * DINNER / 4; break;
        case 7:  src = bow; hdst = g_wout[1]; n4 = DMODEL * DINNER / 4; break;
        case 8:  src = fxp; hdst = g_wxp[0];  n4 = XDBLW * DINNER / 4;  break;
        case 9:  src = bxp; hdst = g_wxp[1];  n4 = XDBLW * DINNER / 4;  break;
        case 10: src = fdw; hdst = g_wdt[0];  n4 = DINNER * DTRANK / 4; break;
        default: src = bdw; hdst = g_wdt[1];  n4 = DINNER * DTRANK / 4; break;
    }
    if (src == nullptr) {
        for (int i = blockIdx.x * blockDim.x + threadIdx.x; i < n4;
             i += gridDim.x * blockDim.x)
            zdst[i] = make_float4(0.f, 0.f, 0.f, 0.f);
    } else {
        __half2* d2 = reinterpret_cast<__half2*>(hdst);
        for (int i = blockIdx.x * blockDim.x + threadIdx.x; i < n4;
             i += gridDim.x * blockDim.x) {
            float4 v = src[i];
            d2[2 * i + 0] = __floats2half2_rn(v.x, v.y);
            d2[2 * i + 1] = __floats2half2_rn(v.z, v.w);
        }
    }
}

__global__ void round_dt_kernel()
{
    const int dir = blockIdx.y;
    const int e = blockIdx.x * blockDim.x + threadIdx.x;
    if (e >= MTOT * DTRANK) return;
    const int row = e / DTRANK;
    const int j   = e - row * DTRANK;
    g_dtr[dir][e] = __float2half_rn(g_xdbl[dir][(size_t)row * XDBLW + j]);
}

// ---------------------------------------------------------------------------
// Causal depthwise conv (D_CONV=4) + bias + SiLU, l-tiled x4.
// Writes exact u (scan) and fp16 u (x_proj A operand).
// ---------------------------------------------------------------------------
__global__ void conv_silu_kernel(const float* __restrict__ f_conv_w,
                                 const float* __restrict__ f_conv_b,
                                 const float* __restrict__ b_conv_w,
                                 const float* __restrict__ b_conv_b)
{
    const int dir = blockIdx.y;
    const float* conv_w = dir ? b_conv_w : f_conv_w;
    const float* conv_b = dir ? b_conv_b : f_conv_b;

    const int NCH = DINNER / 4;
    const int idx = blockIdx.x * blockDim.x + threadIdx.x;
    if (idx >= (MTOT / 4) * NCH) return;
    const int rt   = idx / NCH;
    const int d4   = (idx - rt * NCH) * 4;
    const int row0 = rt * 4;
    const int l0   = row0 & (SEQL - 1);

    const float* xz = g_xz[dir];
    float cw[4][4];
#pragma unroll
    for (int j = 0; j < 4; j++) {
        const float4 w = *(const float4*)(conv_w + (d4 + j) * DCONV);
        cw[j][0] = w.x; cw[j][1] = w.y; cw[j][2] = w.z; cw[j][3] = w.w;
    }

    float4 xv[7];
#pragma unroll
    for (int j = 0; j < 7; j++) {
        const int l = l0 - 3 + j;
        xv[j] = (l >= 0)
              ? *(const float4*)(xz + (size_t)(row0 - 3 + j) * XZW + d4)
              : make_float4(0.f, 0.f, 0.f, 0.f);
    }
    const float4 bias = *(const float4*)(conv_b + d4);

#pragma unroll
    for (int i = 0; i < 4; i++) {
        float4 s = bias;
#pragma unroll
        for (int k = 0; k < 4; k++) {
            const float4 xvv = xv[i + k];
            s.x = fmaf(cw[0][k], xvv.x, s.x);
            s.y = fmaf(cw[1][k], xvv.y, s.y);
            s.z = fmaf(cw[2][k], xvv.z, s.z);
            s.w = fmaf(cw[3][k], xvv.w, s.w);
        }
        float4 o;
        o.x = s.x / (1.f + __expf(-s.x));
        o.y = s.y / (1.f + __expf(-s.y));
        o.z = s.z / (1.f + __expf(-s.z));
        o.w = s.w / (1.f + __expf(-s.w));
        *(float4*)(g_u[dir] + (size_t)(row0 + i) * DINNER + d4) = o;
        __half2* h2 = reinterpret_cast<__half2*>(g_ur[dir] + (size_t)(row0 + i) * DINNER + d4);
        h2[0] = __floats2half2_rn(o.x, o.y);
        h2[1] = __floats2half2_rn(o.z, o.w);
    }
}

// ---------------------------------------------------------------------------
// Selective scan — unroll 8, group double-buffered. dir1 output pre-flipped.
// Output stored fp16 (out_proj A operand).
// ---------------------------------------------------------------------------
#define UNR   8
#define NGRP  (SEQL / UNR)

__global__ __launch_bounds__(128)
void scan_kernel(const float* __restrict__ fAlog, const float* __restrict__ fD,
                 const float* __restrict__ bAlog, const float* __restrict__ bD)
{
    const int dir = blockIdx.y;
    const float* Alog = dir ? bAlog : fAlog;
    const float* Dp   = dir ? bD    : fD;
    const float* delta = g_delta[dir];
    const float* u     = g_u[dir];
    const float* xdbl  = g_xdbl[dir];
    const float* xz    = g_xz[dir];
    __half*      ypre  = g_ypre[dir];

    const int lane = threadIdx.x & 31;
    const int warp = threadIdx.x >> 5;
    const int half = lane >> 4;
    const int n    = lane & 15;

    const int c = blockIdx.x * 8 + warp * 2 + half;
    const int b = c / DINNER;
    const int d = c - b * DINNER;

    const float Aneg = -__expf(Alog[d * DSTATE + n]);
    const float Dd   = Dp[d];
    const bool  ln0  = (n == 0);

    const size_t rowbase = (size_t)b * SEQL;
    const float* pDl = delta + rowbase * DINNER + d;
    const float* pU  = u     + rowbase * DINNER + d;
    const float* pB  = xdbl  + rowbase * XDBLW + DTRANK + n;
    const float* pC  = pB + DSTATE;
    const float* pZ  = xz    + rowbase * XZW + DINNER + d;

    float cdl[UNR], cuu[UNR], cBn[UNR], cCn[UNR], czz[UNR];

    auto load_grp = [&](int g, float* adl, float* auu, float* aBn,
                        float* aCn, float* azz) {
        const int l0 = g * UNR;
#pragma unroll
        for (int i = 0; i < UNR; i++) {
            adl[i] = pDl[(size_t)(l0 + i) * DINNER];
            auu[i] = pU [(size_t)(l0 + i) * DINNER];
            aBn[i] = pB [(size_t)(l0 + i) * XDBLW];
            aCn[i] = pC [(size_t)(l0 + i) * XDBLW];
        }
        if (ln0) {
#pragma unroll
            for (int i = 0; i < UNR; i++)
                azz[i] = pZ[(size_t)(l0 + i) * XZW];
        }
    };

    load_grp(0, cdl, cuu, cBn, cCn, czz);
    float h = 0.f;

    for (int g = 0; g < NGRP; g++) {
        float ndl[UNR], nuu[UNR], nBn[UNR], nCn[UNR], nzz[UNR];
        load_grp((g + 1 < NGRP) ? (g + 1) : 0, ndl, nuu, nBn, nCn, nzz);

        float dA[UNR];
#pragma unroll
        for (int i = 0; i < UNR; i++) dA[i] = __expf(cdl[i] * Aneg);

        float yp[UNR];
#pragma unroll
        for (int i = 0; i < UNR; i++) {
            h = fmaf(dA[i], h, cdl[i] * cBn[i] * cuu[i]);
            yp[i] = h * cCn[i];
        }

#pragma unroll
        for (int s = 1; s <= 8; s <<= 1) {
#pragma unroll
            for (int i = 0; i < UNR; i++)
                yp[i] += __shfl_xor_sync(0xffffffffu, yp[i], s);
        }

        if (ln0) {
            const int l0 = g * UNR;
#pragma unroll
            for (int i = 0; i < UNR; i++) {
                float y = fmaf(cuu[i], Dd, yp[i]);
                const float zz = czz[i];
                y *= zz / (1.f + __expf(-zz));
                const size_t row  = rowbase + l0 + i;
                const size_t orow = dir ? (row ^ (SEQL - 1)) : row;
                ypre[orow * DINNER + d] = __float2half_rn(y);
            }
        }

#pragma unroll
        for (int i = 0; i < UNR; i++) {
            cdl[i] = ndl[i]; cuu[i] = nuu[i];
            cBn[i] = nBn[i]; cCn[i] = nCn[i]; czz[i] = nzz[i];
        }
    }
}

// ---------------------------------------------------------------------------
// Host launch.
// ---------------------------------------------------------------------------
extern "C" void kernel_launch(void* const* d_in, const int* in_sizes, int n_in,
                              void* d_out, int out_size)
{
    const float* x = (const float*)d_in[0];
    float* out = (float*)d_out;

    const float* f_in_w    = (const float*)d_in[1];
    const float* f_conv_w  = (const float*)d_in[2];
    const float* f_conv_b  = (const float*)d_in[3];
    const float* f_xproj_w = (const float*)d_in[4];
    const float* f_dt_w    = (const float*)d_in[5];
    const float* f_dt_b    = (const float*)d_in[6];
    const float* f_Alog    = (const float*)d_in[7];
    const float* f_D       = (const float*)d_in[8];
    const float* b_in_w    = (const float*)d_in[10];
    const float* b_conv_w  = (const float*)d_in[11];
    const float* b_conv_b  = (const float*)d_in[12];
    const float* b_xproj_w = (const float*)d_in[13];
    const float* b_dt_w    = (const float*)d_in[14];
    const float* b_dt_b    = (const float*)d_in[15];
    const float* b_Alog    = (const float*)d_in[16];
    const float* b_D       = (const float*)d_in[17];

    // device-global fp32 targets for non-external C
    float* xz0;    float* xz1;
    float* delta0; float* delta1;
    float* xdbl0;  float* xdbl1;
    cudaGetSymbolAddress((void**)&xz0,    g_xz);
    xz1    = xz0    + (size_t)MTOT * XZW;
    cudaGetSymbolAddress((void**)&delta0, g_delta);
    delta1 = delta0 + (size_t)MTOT * DINNER;
    cudaGetSymbolAddress((void**)&xdbl0,  g_xdbl);
    xdbl1  = xdbl0  + (size_t)MTOT * XDBLW;

    // opt-in dynamic smem (idempotent host calls)
    cudaFuncSetAttribute(gemm_h<ACT_NONE, true,  false, 32, 4>,
                         cudaFuncAttributeMaxDynamicSharedMemorySize, SMEM_BK32);
    cudaFuncSetAttribute(gemm_h<ACT_NONE, false, true,  32, 4>,
                         cudaFuncAttributeMaxDynamicSharedMemorySize, SMEM_BK32);
    cudaFuncSetAttribute(gemm_h<ACT_SOFTPLUS, false, false, 16, 3>,
                         cudaFuncAttributeMaxDynamicSharedMemorySize, SMEM_BK16);

    // fused init: zero out/xdbl + fp16 conversion of all GEMM operands
    init_kernel<<<dim3(160, 12), 256>>>(
        (float4*)out, (const float4*)x,
        (const float4*)f_in_w,    (const float4*)b_in_w,
        (const float4*)((const float*)d_in[9]),  (const float4*)((const float*)d_in[18]),
        (const float4*)f_xproj_w, (const float4*)b_xproj_w,
        (const float4*)f_dt_w,    (const float4*)b_dt_w);

    // in_proj: xz = x(flip dir1) @ in_w^T   [2048,3072], K=768
    gemm_h<ACT_NONE, true, false, 32, 4>
        <<<dim3(XZW / 128, MTOT / 128, 2), 256, SMEM_BK32>>>(
        HBUF_XR, HBUF_WIN, nullptr, nullptr, nullptr, xz0, xz1,
        XZW, DMODEL, DMODEL, XZW, XZW / 128, DMODEL);

    // depthwise conv + SiLU (writes u exact + u fp16)
    conv_silu_kernel<<<dim3(((MTOT / 4) * (DINNER / 4) + 255) / 256, 2), 256>>>(
        f_conv_w, f_conv_b, b_conv_w, b_conv_b);

    // x_proj (split-K x8, atomic): xdbl += u_h @ xproj_w^T   [2048,80], K=1536
    gemm_h<ACT_NONE, false, true, 32, 4>
        <<<dim3(8, MTOT / 128, 2), 256, SMEM_BK32>>>(
        HBUF_UR, HBUF_WXP, nullptr, nullptr, nullptr, xdbl0, xdbl1,
        XDBLW, DINNER, DINNER, XDBLW, 1, DINNER / 8);

    // dt columns of accumulated totals -> fp16
    round_dt_kernel<<<dim3((MTOT * DTRANK + 255) / 256, 2), 256>>>();

    // delta: softplus(dt_h @ dt_w^T + dt_b)   [2048,1536], K=48
    gemm_h<ACT_SOFTPLUS, false, false, 16, 3>
        <<<dim3(DINNER / 128, MTOT / 128, 2), 256, SMEM_BK16>>>(
        HBUF_DTR, HBUF_WDT, f_dt_b, b_dt_b, nullptr, delta0, delta1,
        DINNER, DTRANK, DTRANK, DINNER, DINNER / 128, DTRANK);

    // selective scan (unroll-8 double-buffered; dir1 output pre-flipped)
    scan_kernel<<<dim3((NB * DINNER) / 8, 2), 128>>>(f_Alog, f_D, b_Alog, b_D);

    // out_proj (split-K x2, atomic): out += ypre_h @ out_w^T  [2048,768], K=1536
    gemm_h<ACT_NONE, false, true, 32, 4>
        <<<dim3((DMODEL / 128) * 2, MTOT / 128, 2), 256, SMEM_BK32>>>(
        HBUF_YPRE, HBUF_WOUT, nullptr, nullptr, out, nullptr, nullptr,
        DMODEL, DINNER, DINNER, DMODEL, DMODEL / 128, DINNER / 2);
}

// round 11
// speedup vs baseline: 6.1757x; 1.0480x over previous
#include <cuda_runtime.h>
#include <cuda_bf16.h>
#include <cuda_fp16.h>
#include <cstdint>

// ---------------------------------------------------------------------------
// BidirectionalMambaLayer — Round 11: fp16 mma.sync GEMMs with BK=64 k-tiles
// (one barrier per 64 MMAs), fused single-shot small-K delta GEMM.
// Numerics identical to round 10 (rel_err 5.116e-4).
// ---------------------------------------------------------------------------

#define SEQL   1024
#define NB     2
#define MTOT   (NB * SEQL)
#define DMODEL 768
#define DINNER 1536
#define DSTATE 16
#define DTRANK 48
#define DCONV  4
#define XZW    (2 * DINNER)            // 3072
#define XDBLW  (DTRANK + 2 * DSTATE)   // 80

// -------------------------- scratch (device globals) -----------------------
__device__ float  g_xz   [2][(size_t)MTOT * XZW];
__device__ float  g_u    [2][(size_t)MTOT * DINNER];  // exact (scan)
__device__ __half g_ur   [2][(size_t)MTOT * DINNER];  // fp16 (x_proj A)
__device__ float  g_xdbl [2][(size_t)MTOT * XDBLW];   // exact totals
__device__ float  g_delta[2][(size_t)MTOT * DINNER];
__device__ __half g_ypre [2][(size_t)MTOT * DINNER];  // fp16 (out_proj A)
__device__ __half g_xr   [(size_t)MTOT * DMODEL];     // fp16 x
__device__ __half g_win  [2][(size_t)XZW * DMODEL];
__device__ __half g_wxp  [2][(size_t)XDBLW * DINNER];
__device__ __half g_wdt  [2][(size_t)DINNER * DTRANK];
__device__ __half g_wout [2][(size_t)DMODEL * DINNER];

enum { HBUF_XR = 0, HBUF_UR, HBUF_YPRE,
       HBUF_WIN, HBUF_WXP, HBUF_WOUT };

__device__ __forceinline__ __half* scratch_h(int id, int dir) {
    switch (id) {
        case HBUF_XR:   return g_xr;
        case HBUF_UR:   return g_ur[dir];
        case HBUF_YPRE: return g_ypre[dir];
        case HBUF_WIN:  return g_win[dir];
        case HBUF_WXP:  return g_wxp[dir];
        case HBUF_WOUT: return g_wout[dir];
    }
    return nullptr;
}

__device__ __forceinline__ void cp16(uint32_t saddr, const __half* gptr, bool ok) {
    int sz = ok ? 16 : 0;
    asm volatile("cp.async.cg.shared.global [%0], [%1], 16, %2;"
                 :: "r"(saddr), "l"(gptr), "r"(sz));
}
__device__ __forceinline__ void cp_commit() { asm volatile("cp.async.commit_group;"); }
__device__ __forceinline__ void cp_wait0()  { asm volatile("cp.async.wait_group 0;"); }

__device__ __forceinline__ void ldsm_x4(uint32_t& r0, uint32_t& r1,
                                        uint32_t& r2, uint32_t& r3, uint32_t a) {
    asm volatile("ldmatrix.sync.aligned.m8n8.x4.shared.b16 {%0,%1,%2,%3}, [%4];"
                 : "=r"(r0), "=r"(r1), "=r"(r2), "=r"(r3) : "r"(a));
}

#define MMA_F16(acc, a, b)                                              \
    asm volatile(                                                       \
        "mma.sync.aligned.m16n8k16.row.col.f32.f16.f16.f32 "            \
        "{%0,%1,%2,%3}, {%4,%5,%6,%7}, {%8,%9}, {%0,%1,%2,%3};"         \
        : "+f"((acc)[0]), "+f"((acc)[1]), "+f"((acc)[2]), "+f"((acc)[3])\
        : "r"((a)[0]), "r"((a)[1]), "r"((a)[2]), "r"((a)[3]),           \
          "r"((b)[0]), "r"((b)[1]))

// ---------------------------------------------------------------------------
// fp16 mma.sync TN GEMM, BK=64, STG=2 (dynamic smem), dir-merged, split-K.
// BM=BN=128, 256 threads (8 warps 2m x 4n), warp tile 64x32.
// One __syncthreads per 64-k tile; tile t+1 loads overlap tile t compute.
// ---------------------------------------------------------------------------
#define GBK   64
#define GSASX 72                        // 64 + 8 halves pad
#define SMEM_BK64 (2 * (128 * GSASX * 2) * 2)   // 73728 B

template<bool FLIPA1, bool ATOMIC>
__global__ __launch_bounds__(256, 2)
void gemm_h(int aId, int bId,
            float* __restrict__ Cext, float* __restrict__ Cd0, float* __restrict__ Cd1,
            int N, int K, int lda, int ldc, int nxt, int kchunk)
{
    constexpr int CPR = GBK / 8;        // 8 chunks of 16B per row
    constexpr int LIT = 128 * CPR / 256;  // 4 per matrix

    const int dir = blockIdx.z;
    const __half* A = scratch_h(aId, dir);
    const __half* W = scratch_h(bId, dir);
    float*        C = Cext ? Cext : (dir ? Cd1 : Cd0);

    const int split = blockIdx.x / nxt;
    const int bn    = (blockIdx.x - split * nxt) * 128;
    const int bm    = blockIdx.y * 128;
    const int kbeg  = split * kchunk;
    const int T     = kchunk / GBK;

    extern __shared__ __half dynsmem_h[];

    const int tid  = threadIdx.x;
    const int lane = tid & 31;
    const int warp = tid >> 5;
    const int wm   = warp >> 2;
    const int wn   = warp & 3;
    const int gr   = lane >> 2;
    const int tq   = lane & 3;

    const uint32_t stage_bytes = 128 * GSASX * 2;
    const uint32_t sAb = (uint32_t)__cvta_generic_to_shared(dynsmem_h);
    const uint32_t sBb = sAb + 2 * stage_bytes;

    const uint32_t laneA =
        ((uint32_t)((wm * 64 + (lane & 15)) * GSASX + (lane >> 4) * 8)) * 2;
    const uint32_t laneB =
        ((uint32_t)((wn * 32 + (lane & 7) + ((lane & 16) ? 8 : 0)) * GSASX +
                    ((lane & 8) ? 8 : 0))) * 2;

    int arow[LIT], aq[LIT];
    uint32_t soff[LIT];
#pragma unroll
    for (int i = 0; i < LIT; i++) {
        const int c = tid + i * 256;
        arow[i] = c / CPR;
        aq[i]   = (c - arow[i] * CPR) * 8;
        soff[i] = (uint32_t)(arow[i] * GSASX + aq[i]) * 2;
    }

    auto load_tile = [&](int t, int st) {
        const int kof = kbeg + t * GBK;
#pragma unroll
        for (int i = 0; i < LIT; i++) {
            int gm = bm + arow[i];
            if (FLIPA1 && dir) gm ^= (SEQL - 1);
            cp16(sAb + st * stage_bytes + soff[i],
                 A + (size_t)gm * lda + kof + aq[i], true);
        }
#pragma unroll
        for (int i = 0; i < LIT; i++) {
            const int wr = bn + arow[i];
            cp16(sBb + st * stage_bytes + soff[i],
                 W + (size_t)wr * K + kof + aq[i], wr < N);
        }
        cp_commit();
    };

    float acc[4][4][4];
#pragma unroll
    for (int mt = 0; mt < 4; mt++)
#pragma unroll
        for (int nt = 0; nt < 4; nt++)
#pragma unroll
            for (int r = 0; r < 4; r++) acc[mt][nt][r] = 0.f;

    load_tile(0, 0);

    for (int t = 0; t < T; t++) {
        const int st = t & 1;
        cp_wait0();
        __syncthreads();    // stage st^1 fully consumed (tile t-1) by all warps

        if (t + 1 < T) load_tile(t + 1, st ^ 1);

        const uint32_t aAddr = sAb + st * stage_bytes + laneA;
        const uint32_t bAddr = sBb + st * stage_bytes + laneB;
#pragma unroll
        for (int ks = 0; ks < GBK / 16; ks++) {
            const uint32_t kb2 = (uint32_t)(ks * 16) * 2;
            uint32_t a[4][4], b[4][2];
#pragma unroll
            for (int mt = 0; mt < 4; mt++)
                ldsm_x4(a[mt][0], a[mt][1], a[mt][2], a[mt][3],
                        aAddr + (uint32_t)(mt * 16 * GSASX) * 2 + kb2);
#pragma unroll
            for (int p = 0; p < 2; p++)
                ldsm_x4(b[2 * p][0], b[2 * p][1], b[2 * p + 1][0], b[2 * p + 1][1],
                        bAddr + (uint32_t)(p * 16 * GSASX) * 2 + kb2);
#pragma unroll
            for (int mt = 0; mt < 4; mt++)
#pragma unroll
                for (int nt = 0; nt < 4; nt++)
                    MMA_F16(acc[mt][nt], a[mt], b[nt]);
        }
    }

    // epilogue (fp32)
#pragma unroll
    for (int mt = 0; mt < 4; mt++) {
        const int m0 = bm + wm * 64 + mt * 16 + gr;
#pragma unroll
        for (int half = 0; half < 2; half++) {
            const int m = m0 + half * 8;
#pragma unroll
            for (int nt = 0; nt < 4; nt++) {
                const int nbase = bn + wn * 32 + nt * 8 + 2 * tq;
#pragma unroll
                for (int j = 0; j < 2; j++) {
                    const int n = nbase + j;
                    if (n < N) {
                        const float v = acc[mt][nt][half * 2 + j];
                        if (ATOMIC) atomicAdd(&C[(size_t)m * ldc + n], v);
                        else        C[(size_t)m * ldc + n] = v;
                    }
                }
            }
        }
    }
}

// ---------------------------------------------------------------------------
// Fused small-K delta GEMM: delta = softplus(dt @ dt_w^T + dt_b), K=48.
// A = dt columns of g_xdbl (fp32, stride 80) converted to fp16 at smem store;
// B = g_wdt fp16 via cp.async. Whole K fits in smem: one sync, 3 k-steps.
// ---------------------------------------------------------------------------
#define DSASX 56    // 48 + 8 pad
__global__ __launch_bounds__(256, 2)
void gemm_delta(const float* __restrict__ dt_b0, const float* __restrict__ dt_b1)
{
    const int dir = blockIdx.z;
    const float*  Xd = g_xdbl[dir];
    const __half* W  = g_wdt[dir];
    const float*  bias = dir ? dt_b1 : dt_b0;
    float*        Cc = g_delta[dir];

    __shared__ __half sA[128 * DSASX];
    __shared__ __half sB[128 * DSASX];

    const int bn = blockIdx.x * 128;
    const int bm = blockIdx.y * 128;

    const int tid  = threadIdx.x;
    const int lane = tid & 31;
    const int warp = tid >> 5;
    const int wm   = warp >> 2;
    const int wn   = warp & 3;
    const int gr   = lane >> 2;
    const int tq   = lane & 3;

    const uint32_t sAb = (uint32_t)__cvta_generic_to_shared(sA);
    const uint32_t sBb = (uint32_t)__cvta_generic_to_shared(sB);

    // B: 128 rows x 48 halves = 6 chunks/row -> 768 chunks, 3/thread
#pragma unroll
    for (int i = 0; i < 3; i++) {
        const int c = tid + i * 256;
        const int r = c / 6, q = (c - r * 6) * 8;
        cp16(sBb + (uint32_t)(r * DSASX + q) * 2, W + (size_t)(bn + r) * DTRANK + q, true);
    }
    cp_commit();

    // A: 128 rows x 48 floats = 12 float4/row -> 1536, 6/thread; cvt->fp16
#pragma unroll
    for (int i = 0; i < 6; i++) {
        const int c = tid + i * 256;
        const int r = c / 12, q = (c - r * 12) * 4;
        const float4 v = *(const float4*)(Xd + (size_t)(bm + r) * XDBLW + q);
        __half2* d2 = reinterpret_cast<__half2*>(&sA[r * DSASX + q]);
        d2[0] = __floats2half2_rn(v.x, v.y);
        d2[1] = __floats2half2_rn(v.z, v.w);
    }
    cp_wait0();
    __syncthreads();

    const uint32_t laneA =
        ((uint32_t)((wm * 64 + (lane & 15)) * DSASX + (lane >> 4) * 8)) * 2;
    const uint32_t laneB =
        ((uint32_t)((wn * 32 + (lane & 7) + ((lane & 16) ? 8 : 0)) * DSASX +
                    ((lane & 8) ? 8 : 0))) * 2;

    float acc[4][4][4];
#pragma unroll
    for (int mt = 0; mt < 4; mt++)
#pragma unroll
        for (int nt = 0; nt < 4; nt++)
#pragma unroll
            for (int r = 0; r < 4; r++) acc[mt][nt][r] = 0.f;

#pragma unroll
    for (int ks = 0; ks < 3; ks++) {
        const uint32_t kb2 = (uint32_t)(ks * 16) * 2;
        uint32_t a[4][4], b[4][2];
#pragma unroll
        for (int mt = 0; mt < 4; mt++)
            ldsm_x4(a[mt][0], a[mt][1], a[mt][2], a[mt][3],
                    sAb + laneA + (uint32_t)(mt * 16 * DSASX) * 2 + kb2);
#pragma unroll
        for (int p = 0; p < 2; p++)
            ldsm_x4(b[2 * p][0], b[2 * p][1], b[2 * p + 1][0], b[2 * p + 1][1],
                    sBb + laneB + (uint32_t)(p * 16 * DSASX) * 2 + kb2);
#pragma unroll
        for (int mt = 0; mt < 4; mt++)
#pragma unroll
            for (int nt = 0; nt < 4; nt++)
                MMA_F16(acc[mt][nt], a[mt], b[nt]);
    }

    // epilogue: bias + softplus
#pragma unroll
    for (int mt = 0; mt < 4; mt++) {
        const int m0 = bm + wm * 64 + mt * 16 + gr;
#pragma unroll
        for (int half = 0; half < 2; half++) {
            const int m = m0 + half * 8;
#pragma unroll
            for (int nt = 0; nt < 4; nt++) {
                const int nbase = bn + wn * 32 + nt * 8 + 2 * tq;
#pragma unroll
                for (int j = 0; j < 2; j++) {
                    const int n = nbase + j;
                    float v = acc[mt][nt][half * 2 + j] + bias[n];
                    v = (v > 20.f) ? v : log1pf(__expf(v));
                    Cc[(size_t)m * DINNER + n] = v;
                }
            }
        }
    }
}

// ---------------------------------------------------------------------------
// Fused init: zero(out), zero(xdbl x2), + 9 fp16-conversion slices.
// ---------------------------------------------------------------------------
__global__ void init_kernel(float4* __restrict__ out4,
                            const float4* __restrict__ x,
                            const float4* __restrict__ fiw, const float4* __restrict__ biw,
                            const float4* __restrict__ fow, const float4* __restrict__ bow,
                            const float4* __restrict__ fxp, const float4* __restrict__ bxp,
                            const float4* __restrict__ fdw, const float4* __restrict__ bdw)
{
    const float4* src = nullptr; __half* hdst = nullptr; float4* zdst = nullptr; int n4;
    switch (blockIdx.y) {
        case 0:  zdst = out4;               n4 = MTOT * DMODEL / 4;    break;
        case 1:  zdst = (float4*)g_xdbl[0]; n4 = MTOT * XDBLW / 4;     break;
        case 2:  zdst = (float4*)g_xdbl[1]; n4 = MTOT * XDBLW / 4;     break;
        case 3:  src = x;   hdst = g_xr;      n4 = MTOT * DMODEL / 4;   break;
        case 4:  src = fiw; hdst = g_win[0];  n4 = XZW * DMODEL / 4;    break;
        case 5:  src = biw; hdst = g_win[1];  n4 = XZW * DMODEL / 4;    break;
        case 6:  src = fow; hdst = g_wout[0]; n4 = DMODEL * DINNER / 4; break;
        case 7:  src = bow; hdst = g_wout[1]; n4 = DMODEL * DINNER / 4; break;
        case 8:  src = fxp; hdst = g_wxp[0];  n4 = XDBLW * DINNER / 4;  break;
        case 9:  src = bxp; hdst = g_wxp[1];  n4 = XDBLW * DINNER / 4;  break;
        case 10: src = fdw; hdst = g_wdt[0];  n4 = DINNER * DTRANK / 4; break;
        default: src = bdw; hdst = g_wdt[1];  n4 = DINNER * DTRANK / 4; break;
    }
    if (src == nullptr) {
        for (int i = blockIdx.x * blockDim.x + threadIdx.x; i < n4;
             i += gridDim.x * blockDim.x)
            zdst[i] = make_float4(0.f, 0.f, 0.f, 0.f);
    } else {
        __half2* d2 = reinterpret_cast<__half2*>(hdst);
        for (int i = blockIdx.x * blockDim.x + threadIdx.x; i < n4;
             i += gridDim.x * blockDim.x) {
            float4 v = src[i];
            d2[2 * i + 0] = __floats2half2_rn(v.x, v.y);
            d2[2 * i + 1] = __floats2half2_rn(v.z, v.w);
        }
    }
}

// ---------------------------------------------------------------------------
// Causal depthwise conv (D_CONV=4) + bias + SiLU, l-tiled x4.
// ---------------------------------------------------------------------------
__global__ void conv_silu_kernel(const float* __restrict__ f_conv_w,
                                 const float* __restrict__ f_conv_b,
                                 const float* __restrict__ b_conv_w,
                                 const float* __restrict__ b_conv_b)
{
    const int dir = blockIdx.y;
    const float* conv_w = dir ? b_conv_w : f_conv_w;
    const float* conv_b = dir ? b_conv_b : f_conv_b;

    const int NCH = DINNER / 4;
    const int idx = blockIdx.x * blockDim.x + threadIdx.x;
    if (idx >= (MTOT / 4) * NCH) return;
    const int rt   = idx / NCH;
    const int d4   = (idx - rt * NCH) * 4;
    const int row0 = rt * 4;
    const int l0   = row0 & (SEQL - 1);

    const float* xz = g_xz[dir];
    float cw[4][4];
#pragma unroll
    for (int j = 0; j < 4; j++) {
        const float4 w = *(const float4*)(conv_w + (d4 + j) * DCONV);
        cw[j][0] = w.x; cw[j][1] = w.y; cw[j][2] = w.z; cw[j][3] = w.w;
    }

    float4 xv[7];
#pragma unroll
    for (int j = 0; j < 7; j++) {
        const int l = l0 - 3 + j;
        xv[j] = (l >= 0)
              ? *(const float4*)(xz + (size_t)(row0 - 3 + j) * XZW + d4)
              : make_float4(0.f, 0.f, 0.f, 0.f);
    }
    const float4 bias = *(const float4*)(conv_b + d4);

#pragma unroll
    for (int i = 0; i < 4; i++) {
        float4 s = bias;
#pragma unroll
        for (int k = 0; k < 4; k++) {
            const float4 xvv = xv[i + k];
            s.x = fmaf(cw[0][k], xvv.x, s.x);
            s.y = fmaf(cw[1][k], xvv.y, s.y);
            s.z = fmaf(cw[2][k], xvv.z, s.z);
            s.w = fmaf(cw[3][k], xvv.w, s.w);
        }
        float4 o;
        o.x = s.x / (1.f + __expf(-s.x));
        o.y = s.y / (1.f + __expf(-s.y));
        o.z = s.z / (1.f + __expf(-s.z));
        o.w = s.w / (1.f + __expf(-s.w));
        *(float4*)(g_u[dir] + (size_t)(row0 + i) * DINNER + d4) = o;
        __half2* h2 = reinterpret_cast<__half2*>(g_ur[dir] + (size_t)(row0 + i) * DINNER + d4);
        h2[0] = __floats2half2_rn(o.x, o.y);
        h2[1] = __floats2half2_rn(o.z, o.w);
    }
}

// ---------------------------------------------------------------------------
// Selective scan — unroll 8, group double-buffered. dir1 output pre-flipped.
// ---------------------------------------------------------------------------
#define UNR   8
#define NGRP  (SEQL / UNR)

__global__ __launch_bounds__(128)
void scan_kernel(const float* __restrict__ fAlog, const float* __restrict__ fD,
                 const float* __restrict__ bAlog, const float* __restrict__ bD)
{
    const int dir = blockIdx.y;
    const float* Alog = dir ? bAlog : fAlog;
    const float* Dp   = dir ? bD    : fD;
    const float* delta = g_delta[dir];
    const float* u     = g_u[dir];
    const float* xdbl  = g_xdbl[dir];
    const float* xz    = g_xz[dir];
    __half*      ypre  = g_ypre[dir];

    const int lane = threadIdx.x & 31;
    const int warp = threadIdx.x >> 5;
    const int half = lane >> 4;
    const int n    = lane & 15;

    const int c = blockIdx.x * 8 + warp * 2 + half;
    const int b = c / DINNER;
    const int d = c - b * DINNER;

    const float Aneg = -__expf(Alog[d * DSTATE + n]);
    const float Dd   = Dp[d];
    const bool  ln0  = (n == 0);

    const size_t rowbase = (size_t)b * SEQL;
    const float* pDl = delta + rowbase * DINNER + d;
    const float* pU  = u     + rowbase * DINNER + d;
    const float* pB  = xdbl  + rowbase * XDBLW + DTRANK + n;
    const float* pC  = pB + DSTATE;
    const float* pZ  = xz    + rowbase * XZW + DINNER + d;

    float cdl[UNR], cuu[UNR], cBn[UNR], cCn[UNR], czz[UNR];

    auto load_grp = [&](int g, float* adl, float* auu, float* aBn,
                        float* aCn, float* azz) {
        const int l0 = g * UNR;
#pragma unroll
        for (int i = 0; i < UNR; i++) {
            adl[i] = pDl[(size_t)(l0 + i) * DINNER];
            auu[i] = pU [(size_t)(l0 + i) * DINNER];
            aBn[i] = pB [(size_t)(l0 + i) * XDBLW];
            aCn[i] = pC [(size_t)(l0 + i) * XDBLW];
        }
        if (ln0) {
#pragma unroll
            for (int i = 0; i < UNR; i++)
                azz[i] = pZ[(size_t)(l0 + i) * XZW];
        }
    };

    load_grp(0, cdl, cuu, cBn, cCn, czz);
    float h = 0.f;

    for (int g = 0; g < NGRP; g++) {
        float ndl[UNR], nuu[UNR], nBn[UNR], nCn[UNR], nzz[UNR];
        load_grp((g + 1 < NGRP) ? (g + 1) : 0, ndl, nuu, nBn, nCn, nzz);

        float dA[UNR];
#pragma unroll
        for (int i = 0; i < UNR; i++) dA[i] = __expf(cdl[i] * Aneg);

        float yp[UNR];
#pragma unroll
        for (int i = 0; i < UNR; i++) {
            h = fmaf(dA[i], h, cdl[i] * cBn[i] * cuu[i]);
            yp[i] = h * cCn[i];
        }

#pragma unroll
        for (int s = 1; s <= 8; s <<= 1) {
#pragma unroll
            for (int i = 0; i < UNR; i++)
                yp[i] += __shfl_xor_sync(0xffffffffu, yp[i], s);
        }

        if (ln0) {
            const int l0 = g * UNR;
#pragma unroll
            for (int i = 0; i < UNR; i++) {
                float y = fmaf(cuu[i], Dd, yp[i]);
                const float zz = czz[i];
                y *= zz / (1.f + __expf(-zz));
                const size_t row  = rowbase + l0 + i;
                const size_t orow = dir ? (row ^ (SEQL - 1)) : row;
                ypre[orow * DINNER + d] = __float2half_rn(y);
            }
        }

#pragma unroll
        for (int i = 0; i < UNR; i++) {
            cdl[i] = ndl[i]; cuu[i] = nuu[i];
            cBn[i] = nBn[i]; cCn[i] = nCn[i]; czz[i] = nzz[i];
        }
    }
}

// ---------------------------------------------------------------------------
// Host launch.
// ---------------------------------------------------------------------------
extern "C" void kernel_launch(void* const* d_in, const int* in_sizes, int n_in,
                              void* d_out, int out_size)
{
    const float* x = (const float*)d_in[0];
    float* out = (float*)d_out;

    const float* f_in_w    = (const float*)d_in[1];
    const float* f_conv_w  = (const float*)d_in[2];
    const float* f_conv_b  = (const float*)d_in[3];
    const float* f_xproj_w = (const float*)d_in[4];
    const float* f_dt_w    = (const float*)d_in[5];
    const float* f_dt_b    = (const float*)d_in[6];
    const float* f_Alog    = (const float*)d_in[7];
    const float* f_D       = (const float*)d_in[8];
    const float* f_out_w   = (const float*)d_in[9];
    const float* b_in_w    = (const float*)d_in[10];
    const float* b_conv_w  = (const float*)d_in[11];
    const float* b_conv_b  = (const float*)d_in[12];
    const float* b_xproj_w = (const float*)d_in[13];
    const float* b_dt_w    = (const float*)d_in[14];
    const float* b_dt_b    = (const float*)d_in[15];
    const float* b_Alog    = (const float*)d_in[16];
    const float* b_D       = (const float*)d_in[17];
    const float* b_out_w   = (const float*)d_in[18];

    // device-global fp32 targets
    float* xz0;   float* xz1;
    float* xdbl0; float* xdbl1;
    cudaGetSymbolAddress((void**)&xz0,   g_xz);
    xz1   = xz0   + (size_t)MTOT * XZW;
    cudaGetSymbolAddress((void**)&xdbl0, g_xdbl);
    xdbl1 = xdbl0 + (size_t)MTOT * XDBLW;

    // opt-in dynamic smem
    cudaFuncSetAttribute(gemm_h<true,  false>,
                         cudaFuncAttributeMaxDynamicSharedMemorySize, SMEM_BK64);
    cudaFuncSetAttribute(gemm_h<false, true>,
                         cudaFuncAttributeMaxDynamicSharedMemorySize, SMEM_BK64);

    // fused init: zero out/xdbl + fp16 conversion of all GEMM operands
    init_kernel<<<dim3(160, 12), 256>>>(
        (float4*)out, (const float4*)x,
        (const float4*)f_in_w,    (const float4*)b_in_w,
        (const float4*)f_out_w,   (const float4*)b_out_w,
        (const float4*)f_xproj_w, (const float4*)b_xproj_w,
        (const float4*)f_dt_w,    (const float4*)b_dt_w);

    // in_proj: xz = x(flip dir1) @ in_w^T   [2048,3072], K=768 (12 tiles)
    gemm_h<true, false>
        <<<dim3(XZW / 128, MTOT / 128, 2), 256, SMEM_BK64>>>(
        HBUF_XR, HBUF_WIN, nullptr, xz0, xz1,
        XZW, DMODEL, DMODEL, XZW, XZW / 128, DMODEL);

    // depthwise conv + SiLU (writes u exact + u fp16)
    conv_silu_kernel<<<dim3(((MTOT / 4) * (DINNER / 4) + 255) / 256, 2), 256>>>(
        f_conv_w, f_conv_b, b_conv_w, b_conv_b);

    // x_proj (split-K x8, atomic): xdbl += u_h @ xproj_w^T   [2048,80], K=1536
    gemm_h<false, true>
        <<<dim3(8, MTOT / 128, 2), 256, SMEM_BK64>>>(
        HBUF_UR, HBUF_WXP, nullptr, xdbl0, xdbl1,
        XDBLW, DINNER, DINNER, XDBLW, 1, DINNER / 8);

    // delta: softplus(dt @ dt_w^T + dt_b)  [2048,1536], K=48 — fused small-K
    gemm_delta<<<dim3(DINNER / 128, MTOT / 128, 2), 256>>>(f_dt_b, b_dt_b);

    // selective scan (unroll-8 double-buffered; dir1 output pre-flipped)
    scan_kernel<<<dim3((NB * DINNER) / 8, 2), 128>>>(f_Alog, f_D, b_Alog, b_D);

    // out_proj (split-K x2, atomic): out += ypre_h @ out_w^T  [2048,768], K=1536
    gemm_h<false, true>
        <<<dim3((DMODEL / 128) * 2, MTOT / 128, 2), 256, SMEM_BK64>>>(
        HBUF_YPRE, HBUF_WOUT, out, nullptr, nullptr,
        DMODEL, DINNER, DINNER, DMODEL, DMODEL / 128, DINNER / 2);
}

// round 12
// speedup vs baseline: 6.1826x; 1.0011x over previous
#include <cuda_runtime.h>
#include <cuda_bf16.h>
#include <cuda_fp16.h>
#include <cstdint>

// ---------------------------------------------------------------------------
// BidirectionalMambaLayer — Round 12: register-unclamped fp16 GEMM with
// explicit fragment double-buffering (ldsm for ks+1 overlaps mma of ks),
// STG=3 x BK=64 cp.async pipeline. Numerics identical to round 11.
// ---------------------------------------------------------------------------

#define SEQL   1024
#define NB     2
#define MTOT   (NB * SEQL)
#define DMODEL 768
#define DINNER 1536
#define DSTATE 16
#define DTRANK 48
#define DCONV  4
#define XZW    (2 * DINNER)            // 3072
#define XDBLW  (DTRANK + 2 * DSTATE)   // 80

// -------------------------- scratch (device globals) -----------------------
__device__ float  g_xz   [2][(size_t)MTOT * XZW];
__device__ float  g_u    [2][(size_t)MTOT * DINNER];  // exact (scan)
__device__ __half g_ur   [2][(size_t)MTOT * DINNER];  // fp16 (x_proj A)
__device__ float  g_xdbl [2][(size_t)MTOT * XDBLW];   // exact totals
__device__ float  g_delta[2][(size_t)MTOT * DINNER];
__device__ __half g_ypre [2][(size_t)MTOT * DINNER];  // fp16 (out_proj A)
__device__ __half g_xr   [(size_t)MTOT * DMODEL];     // fp16 x
__device__ __half g_win  [2][(size_t)XZW * DMODEL];
__device__ __half g_wxp  [2][(size_t)XDBLW * DINNER];
__device__ __half g_wdt  [2][(size_t)DINNER * DTRANK];
__device__ __half g_wout [2][(size_t)DMODEL * DINNER];

enum { HBUF_XR = 0, HBUF_UR, HBUF_YPRE,
       HBUF_WIN, HBUF_WXP, HBUF_WOUT };

__device__ __forceinline__ __half* scratch_h(int id, int dir) {
    switch (id) {
        case HBUF_XR:   return g_xr;
        case HBUF_UR:   return g_ur[dir];
        case HBUF_YPRE: return g_ypre[dir];
        case HBUF_WIN:  return g_win[dir];
        case HBUF_WXP:  return g_wxp[dir];
        case HBUF_WOUT: return g_wout[dir];
    }
    return nullptr;
}

__device__ __forceinline__ void cp16(uint32_t saddr, const __half* gptr, bool ok) {
    int sz = ok ? 16 : 0;
    asm volatile("cp.async.cg.shared.global [%0], [%1], 16, %2;"
                 :: "r"(saddr), "l"(gptr), "r"(sz));
}
__device__ __forceinline__ void cp_commit() { asm volatile("cp.async.commit_group;"); }
__device__ __forceinline__ void cp_wait1()  { asm volatile("cp.async.wait_group 1;"); }
__device__ __forceinline__ void cp_wait0()  { asm volatile("cp.async.wait_group 0;"); }

__device__ __forceinline__ void ldsm_x4(uint32_t& r0, uint32_t& r1,
                                        uint32_t& r2, uint32_t& r3, uint32_t a) {
    asm volatile("ldmatrix.sync.aligned.m8n8.x4.shared.b16 {%0,%1,%2,%3}, [%4];"
                 : "=r"(r0), "=r"(r1), "=r"(r2), "=r"(r3) : "r"(a));
}

#define MMA_F16(acc, a, b)                                              \
    asm volatile(                                                       \
        "mma.sync.aligned.m16n8k16.row.col.f32.f16.f16.f32 "            \
        "{%0,%1,%2,%3}, {%4,%5,%6,%7}, {%8,%9}, {%0,%1,%2,%3};"         \
        : "+f"((acc)[0]), "+f"((acc)[1]), "+f"((acc)[2]), "+f"((acc)[3])\
        : "r"((a)[0]), "r"((a)[1]), "r"((a)[2]), "r"((a)[3]),           \
          "r"((b)[0]), "r"((b)[1]))

// ---------------------------------------------------------------------------
// fp16 mma.sync TN GEMM, BK=64, STG=3 (dynamic smem), dir-merged, split-K.
// BM=BN=128, 256 threads (8 warps 2m x 4n), warp tile 64x32.
// Register-unclamped; fragments double-buffered across k-steps.
// ---------------------------------------------------------------------------
#define GBK   64
#define GSTG  3
#define GSASX 72                        // 64 + 8 halves pad
#define SMEM_BK64 (GSTG * (128 * GSASX * 2) * 2)   // 110592 B

template<bool FLIPA1, bool ATOMIC>
__global__ __launch_bounds__(256)
void gemm_h(int aId, int bId,
            float* __restrict__ Cext, float* __restrict__ Cd0, float* __restrict__ Cd1,
            int N, int K, int lda, int ldc, int nxt, int kchunk)
{
    constexpr int CPR = GBK / 8;          // 8 chunks of 16B per row
    constexpr int LIT = 128 * CPR / 256;  // 4 per matrix

    const int dir = blockIdx.z;
    const __half* A = scratch_h(aId, dir);
    const __half* W = scratch_h(bId, dir);
    float*        C = Cext ? Cext : (dir ? Cd1 : Cd0);

    const int split = blockIdx.x / nxt;
    const int bn    = (blockIdx.x - split * nxt) * 128;
    const int bm    = blockIdx.y * 128;
    const int kbeg  = split * kchunk;
    const int T     = kchunk / GBK;

    extern __shared__ __half dynsmem_h[];

    const int tid  = threadIdx.x;
    const int lane = tid & 31;
    const int warp = tid >> 5;
    const int wm   = warp >> 2;
    const int wn   = warp & 3;
    const int gr   = lane >> 2;
    const int tq   = lane & 3;

    const uint32_t stage_bytes = 128 * GSASX * 2;
    const uint32_t sAb = (uint32_t)__cvta_generic_to_shared(dynsmem_h);
    const uint32_t sBb = sAb + GSTG * stage_bytes;

    const uint32_t laneA =
        ((uint32_t)((wm * 64 + (lane & 15)) * GSASX + (lane >> 4) * 8)) * 2;
    const uint32_t laneB =
        ((uint32_t)((wn * 32 + (lane & 7) + ((lane & 16) ? 8 : 0)) * GSASX +
                    ((lane & 8) ? 8 : 0))) * 2;

    int arow[LIT], aq[LIT];
    uint32_t soff[LIT];
#pragma unroll
    for (int i = 0; i < LIT; i++) {
        const int c = tid + i * 256;
        arow[i] = c / CPR;
        aq[i]   = (c - arow[i] * CPR) * 8;
        soff[i] = (uint32_t)(arow[i] * GSASX + aq[i]) * 2;
    }

    auto load_tile = [&](int t, int st) {
        const int kof = kbeg + t * GBK;
#pragma unroll
        for (int i = 0; i < LIT; i++) {
            int gm = bm + arow[i];
            if (FLIPA1 && dir) gm ^= (SEQL - 1);
            cp16(sAb + st * stage_bytes + soff[i],
                 A + (size_t)gm * lda + kof + aq[i], true);
        }
#pragma unroll
        for (int i = 0; i < LIT; i++) {
            const int wr = bn + arow[i];
            cp16(sBb + st * stage_bytes + soff[i],
                 W + (size_t)wr * K + kof + aq[i], wr < N);
        }
        cp_commit();
    };

    float acc[4][4][4];
#pragma unroll
    for (int mt = 0; mt < 4; mt++)
#pragma unroll
        for (int nt = 0; nt < 4; nt++)
#pragma unroll
            for (int r = 0; r < 4; r++) acc[mt][nt][r] = 0.f;

    // prologue: two tiles in flight
    load_tile(0, 0);
    if (T > 1) load_tile(1, 1);

    for (int t = 0; t < T; t++) {
        const int st  = t % GSTG;
        const int rem = T - 1 - t;
        if (rem >= 1) cp_wait1(); else cp_wait0();
        __syncthreads();

        if (t + 2 < T) load_tile(t + 2, (t + 2) % GSTG);

        const uint32_t aAddr = sAb + st * stage_bytes + laneA;
        const uint32_t bAddr = sBb + st * stage_bytes + laneB;

        // fragment double buffer: load ks+1 while issuing MMAs of ks
        uint32_t a[2][4][4], b[2][4][2];

        // ks = 0 fragments
#pragma unroll
        for (int mt = 0; mt < 4; mt++)
            ldsm_x4(a[0][mt][0], a[0][mt][1], a[0][mt][2], a[0][mt][3],
                    aAddr + (uint32_t)(mt * 16 * GSASX) * 2);
#pragma unroll
        for (int p = 0; p < 2; p++)
            ldsm_x4(b[0][2 * p][0], b[0][2 * p][1],
                    b[0][2 * p + 1][0], b[0][2 * p + 1][1],
                    bAddr + (uint32_t)(p * 16 * GSASX) * 2);

#pragma unroll
        for (int ks = 0; ks < GBK / 16; ks++) {
            const int cur = ks & 1;
            if (ks + 1 < GBK / 16) {
                const int nxtb = cur ^ 1;
                const uint32_t kb2 = (uint32_t)((ks + 1) * 16) * 2;
#pragma unroll
                for (int mt = 0; mt < 4; mt++)
                    ldsm_x4(a[nxtb][mt][0], a[nxtb][mt][1],
                            a[nxtb][mt][2], a[nxtb][mt][3],
                            aAddr + (uint32_t)(mt * 16 * GSASX) * 2 + kb2);
#pragma unroll
                for (int p = 0; p < 2; p++)
                    ldsm_x4(b[nxtb][2 * p][0], b[nxtb][2 * p][1],
                            b[nxtb][2 * p + 1][0], b[nxtb][2 * p + 1][1],
                            bAddr + (uint32_t)(p * 16 * GSASX) * 2 + kb2);
            }
#pragma unroll
            for (int mt = 0; mt < 4; mt++)
#pragma unroll
                for (int nt = 0; nt < 4; nt++)
                    MMA_F16(acc[mt][nt], a[cur][mt], b[cur][nt]);
        }
    }

    // epilogue (fp32)
#pragma unroll
    for (int mt = 0; mt < 4; mt++) {
        const int m0 = bm + wm * 64 + mt * 16 + gr;
#pragma unroll
        for (int half = 0; half < 2; half++) {
            const int m = m0 + half * 8;
#pragma unroll
            for (int nt = 0; nt < 4; nt++) {
                const int nbase = bn + wn * 32 + nt * 8 + 2 * tq;
#pragma unroll
                for (int j = 0; j < 2; j++) {
                    const int n = nbase + j;
                    if (n < N) {
                        const float v = acc[mt][nt][half * 2 + j];
                        if (ATOMIC) atomicAdd(&C[(size_t)m * ldc + n], v);
                        else        C[(size_t)m * ldc + n] = v;
                    }
                }
            }
        }
    }
}

// ---------------------------------------------------------------------------
// Fused small-K delta GEMM: delta = softplus(dt @ dt_w^T + dt_b), K=48.
// ---------------------------------------------------------------------------
#define DSASX 56    // 48 + 8 pad
__global__ __launch_bounds__(256, 2)
void gemm_delta(const float* __restrict__ dt_b0, const float* __restrict__ dt_b1)
{
    const int dir = blockIdx.z;
    const float*  Xd = g_xdbl[dir];
    const __half* W  = g_wdt[dir];
    const float*  bias = dir ? dt_b1 : dt_b0;
    float*        Cc = g_delta[dir];

    __shared__ __half sA[128 * DSASX];
    __shared__ __half sB[128 * DSASX];

    const int bn = blockIdx.x * 128;
    const int bm = blockIdx.y * 128;

    const int tid  = threadIdx.x;
    const int lane = tid & 31;
    const int warp = tid >> 5;
    const int wm   = warp >> 2;
    const int wn   = warp & 3;
    const int gr   = lane >> 2;
    const int tq   = lane & 3;

    const uint32_t sAb = (uint32_t)__cvta_generic_to_shared(sA);
    const uint32_t sBb = (uint32_t)__cvta_generic_to_shared(sB);

#pragma unroll
    for (int i = 0; i < 3; i++) {
        const int c = tid + i * 256;
        const int r = c / 6, q = (c - r * 6) * 8;
        cp16(sBb + (uint32_t)(r * DSASX + q) * 2, W + (size_t)(bn + r) * DTRANK + q, true);
    }
    cp_commit();

#pragma unroll
    for (int i = 0; i < 6; i++) {
        const int c = tid + i * 256;
        const int r = c / 12, q = (c - r * 12) * 4;
        const float4 v = *(const float4*)(Xd + (size_t)(bm + r) * XDBLW + q);
        __half2* d2 = reinterpret_cast<__half2*>(&sA[r * DSASX + q]);
        d2[0] = __floats2half2_rn(v.x, v.y);
        d2[1] = __floats2half2_rn(v.z, v.w);
    }
    cp_wait0();
    __syncthreads();

    const uint32_t laneA =
        ((uint32_t)((wm * 64 + (lane & 15)) * DSASX + (lane >> 4) * 8)) * 2;
    const uint32_t laneB =
        ((uint32_t)((wn * 32 + (lane & 7) + ((lane & 16) ? 8 : 0)) * DSASX +
                    ((lane & 8) ? 8 : 0))) * 2;

    float acc[4][4][4];
#pragma unroll
    for (int mt = 0; mt < 4; mt++)
#pragma unroll
        for (int nt = 0; nt < 4; nt++)
#pragma unroll
            for (int r = 0; r < 4; r++) acc[mt][nt][r] = 0.f;

#pragma unroll
    for (int ks = 0; ks < 3; ks++) {
        const uint32_t kb2 = (uint32_t)(ks * 16) * 2;
        uint32_t a[4][4], b[4][2];
#pragma unroll
        for (int mt = 0; mt < 4; mt++)
            ldsm_x4(a[mt][0], a[mt][1], a[mt][2], a[mt][3],
                    sAb + laneA + (uint32_t)(mt * 16 * DSASX) * 2 + kb2);
#pragma unroll
        for (int p = 0; p < 2; p++)
            ldsm_x4(b[2 * p][0], b[2 * p][1], b[2 * p + 1][0], b[2 * p + 1][1],
                    sBb + laneB + (uint32_t)(p * 16 * DSASX) * 2 + kb2);
#pragma unroll
        for (int mt = 0; mt < 4; mt++)
#pragma unroll
            for (int nt = 0; nt < 4; nt++)
                MMA_F16(acc[mt][nt], a[mt], b[nt]);
    }

#pragma unroll
    for (int mt = 0; mt < 4; mt++) {
        const int m0 = bm + wm * 64 + mt * 16 + gr;
#pragma unroll
        for (int half = 0; half < 2; half++) {
            const int m = m0 + half * 8;
#pragma unroll
            for (int nt = 0; nt < 4; nt++) {
                const int nbase = bn + wn * 32 + nt * 8 + 2 * tq;
#pragma unroll
                for (int j = 0; j < 2; j++) {
                    const int n = nbase + j;
                    float v = acc[mt][nt][half * 2 + j] + bias[n];
                    v = (v > 20.f) ? v : log1pf(__expf(v));
                    Cc[(size_t)m * DINNER + n] = v;
                }
            }
        }
    }
}

// ---------------------------------------------------------------------------
// Fused init: zero(out), zero(xdbl x2), + 9 fp16-conversion slices.
// ---------------------------------------------------------------------------
__global__ void init_kernel(float4* __restrict__ out4,
                            const float4* __restrict__ x,
                            const float4* __restrict__ fiw, const float4* __restrict__ biw,
                            const float4* __restrict__ fow, const float4* __restrict__ bow,
                            const float4* __restrict__ fxp, const float4* __restrict__ bxp,
                            const float4* __restrict__ fdw, const float4* __restrict__ bdw)
{
    const float4* src = nullptr; __half* hdst = nullptr; float4* zdst = nullptr; int n4;
    switch (blockIdx.y) {
        case 0:  zdst = out4;               n4 = MTOT * DMODEL / 4;    break;
        case 1:  zdst = (float4*)g_xdbl[0]; n4 = MTOT * XDBLW / 4;     break;
        case 2:  zdst = (float4*)g_xdbl[1]; n4 = MTOT * XDBLW / 4;     break;
        case 3:  src = x;   hdst = g_xr;      n4 = MTOT * DMODEL / 4;   break;
        case 4:  src = fiw; hdst = g_win[0];  n4 = XZW * DMODEL / 4;    break;
        case 5:  src = biw; hdst = g_win[1];  n4 = XZW * DMODEL / 4;    break;
        case 6:  src = fow; hdst = g_wout[0]; n4 = DMODEL * DINNER / 4; break;
        case 7:  src = bow; hdst = g_wout[1]; n4 = DMODEL * DINNER / 4; break;
        case 8:  src = fxp; hdst = g_wxp[0];  n4 = XDBLW * DINNER / 4;  break;
        case 9:  src = bxp; hdst = g_wxp[1];  n4 = XDBLW * DINNER / 4;  break;
        case 10: src = fdw; hdst = g_wdt[0];  n4 = DINNER * DTRANK / 4; break;
        default: src = bdw; hdst = g_wdt[1];  n4 = DINNER * DTRANK / 4; break;
    }
    if (src == nullptr) {
        for (int i = blockIdx.x * blockDim.x + threadIdx.x; i < n4;
             i += gridDim.x * blockDim.x)
            zdst[i] = make_float4(0.f, 0.f, 0.f, 0.f);
    } else {
        __half2* d2 = reinterpret_cast<__half2*>(hdst);
        for (int i = blockIdx.x * blockDim.x + threadIdx.x; i < n4;
             i += gridDim.x * blockDim.x) {
            float4 v = src[i];
            d2[2 * i + 0] = __floats2half2_rn(v.x, v.y);
            d2[2 * i + 1] = __floats2half2_rn(v.z, v.w);
        }
    }
}

// ---------------------------------------------------------------------------
// Causal depthwise conv (D_CONV=4) + bias + SiLU, l-tiled x4.
// ---------------------------------------------------------------------------
__global__ void conv_silu_kernel(const float* __restrict__ f_conv_w,
                                 const float* __restrict__ f_conv_b,
                                 const float* __restrict__ b_conv_w,
                                 const float* __restrict__ b_conv_b)
{
    const int dir = blockIdx.y;
    const float* conv_w = dir ? b_conv_w : f_conv_w;
    const float* conv_b = dir ? b_conv_b : f_conv_b;

    const int NCH = DINNER / 4;
    const int idx = blockIdx.x * blockDim.x + threadIdx.x;
    if (idx >= (MTOT / 4) * NCH) return;
    const int rt   = idx / NCH;
    const int d4   = (idx - rt * NCH) * 4;
    const int row0 = rt * 4;
    const int l0   = row0 & (SEQL - 1);

    const float* xz = g_xz[dir];
    float cw[4][4];
#pragma unroll
    for (int j = 0; j < 4; j++) {
        const float4 w = *(const float4*)(conv_w + (d4 + j) * DCONV);
        cw[j][0] = w.x; cw[j][1] = w.y; cw[j][2] = w.z; cw[j][3] = w.w;
    }

    float4 xv[7];
#pragma unroll
    for (int j = 0; j < 7; j++) {
        const int l = l0 - 3 + j;
        xv[j] = (l >= 0)
              ? *(const float4*)(xz + (size_t)(row0 - 3 + j) * XZW + d4)
              : make_float4(0.f, 0.f, 0.f, 0.f);
    }
    const float4 bias = *(const float4*)(conv_b + d4);

#pragma unroll
    for (int i = 0; i < 4; i++) {
        float4 s = bias;
#pragma unroll
        for (int k = 0; k < 4; k++) {
            const float4 xvv = xv[i + k];
            s.x = fmaf(cw[0][k], xvv.x, s.x);
            s.y = fmaf(cw[1][k], xvv.y, s.y);
            s.z = fmaf(cw[2][k], xvv.z, s.z);
            s.w = fmaf(cw[3][k], xvv.w, s.w);
        }
        float4 o;
        o.x = s.x / (1.f + __expf(-s.x));
        o.y = s.y / (1.f + __expf(-s.y));
        o.z = s.z / (1.f + __expf(-s.z));
        o.w = s.w / (1.f + __expf(-s.w));
        *(float4*)(g_u[dir] + (size_t)(row0 + i) * DINNER + d4) = o;
        __half2* h2 = reinterpret_cast<__half2*>(g_ur[dir] + (size_t)(row0 + i) * DINNER + d4);
        h2[0] = __floats2half2_rn(o.x, o.y);
        h2[1] = __floats2half2_rn(o.z, o.w);
    }
}

// ---------------------------------------------------------------------------
// Selective scan — unroll 8, group double-buffered. dir1 output pre-flipped.
// ---------------------------------------------------------------------------
#define UNR   8
#define NGRP  (SEQL / UNR)

__global__ __launch_bounds__(128)
void scan_kernel(const float* __restrict__ fAlog, const float* __restrict__ fD,
                 const float* __restrict__ bAlog, const float* __restrict__ bD)
{
    const int dir = blockIdx.y;
    const float* Alog = dir ? bAlog : fAlog;
    const float* Dp   = dir ? bD    : fD;
    const float* delta = g_delta[dir];
    const float* u     = g_u[dir];
    const float* xdbl  = g_xdbl[dir];
    const float* xz    = g_xz[dir];
    __half*      ypre  = g_ypre[dir];

    const int lane = threadIdx.x & 31;
    const int warp = threadIdx.x >> 5;
    const int half = lane >> 4;
    const int n    = lane & 15;

    const int c = blockIdx.x * 8 + warp * 2 + half;
    const int b = c / DINNER;
    const int d = c - b * DINNER;

    const float Aneg = -__expf(Alog[d * DSTATE + n]);
    const float Dd   = Dp[d];
    const bool  ln0  = (n == 0);

    const size_t rowbase = (size_t)b * SEQL;
    const float* pDl = delta + rowbase * DINNER + d;
    const float* pU  = u     + rowbase * DINNER + d;
    const float* pB  = xdbl  + rowbase * XDBLW + DTRANK + n;
    const float* pC  = pB + DSTATE;
    const float* pZ  = xz    + rowbase * XZW + DINNER + d;

    float cdl[UNR], cuu[UNR], cBn[UNR], cCn[UNR], czz[UNR];

    auto load_grp = [&](int g, float* adl, float* auu, float* aBn,
                        float* aCn, float* azz) {
        const int l0 = g * UNR;
#pragma unroll
        for (int i = 0; i < UNR; i++) {
            adl[i] = pDl[(size_t)(l0 + i) * DINNER];
            auu[i] = pU [(size_t)(l0 + i) * DINNER];
            aBn[i] = pB [(size_t)(l0 + i) * XDBLW];
            aCn[i] = pC [(size_t)(l0 + i) * XDBLW];
        }
        if (ln0) {
#pragma unroll
            for (int i = 0; i < UNR; i++)
                azz[i] = pZ[(size_t)(l0 + i) * XZW];
        }
    };

    load_grp(0, cdl, cuu, cBn, cCn, czz);
    float h = 0.f;

    for (int g = 0; g < NGRP; g++) {
        float ndl[UNR], nuu[UNR], nBn[UNR], nCn[UNR], nzz[UNR];
        load_grp((g + 1 < NGRP) ? (g + 1) : 0, ndl, nuu, nBn, nCn, nzz);

        float dA[UNR];
#pragma unroll
        for (int i = 0; i < UNR; i++) dA[i] = __expf(cdl[i] * Aneg);

        float yp[UNR];
#pragma unroll
        for (int i = 0; i < UNR; i++) {
            h = fmaf(dA[i], h, cdl[i] * cBn[i] * cuu[i]);
            yp[i] = h * cCn[i];
        }

#pragma unroll
        for (int s = 1; s <= 8; s <<= 1) {
#pragma unroll
            for (int i = 0; i < UNR; i++)
                yp[i] += __shfl_xor_sync(0xffffffffu, yp[i], s);
        }

        if (ln0) {
            const int l0 = g * UNR;
#pragma unroll
            for (int i = 0; i < UNR; i++) {
                float y = fmaf(cuu[i], Dd, yp[i]);
                const float zz = czz[i];
                y *= zz / (1.f + __expf(-zz));
                const size_t row  = rowbase + l0 + i;
                const size_t orow = dir ? (row ^ (SEQL - 1)) : row;
                ypre[orow * DINNER + d] = __float2half_rn(y);
            }
        }

#pragma unroll
        for (int i = 0; i < UNR; i++) {
            cdl[i] = ndl[i]; cuu[i] = nuu[i];
            cBn[i] = nBn[i]; cCn[i] = nCn[i]; czz[i] = nzz[i];
        }
    }
}

// ---------------------------------------------------------------------------
// Host launch.
// ---------------------------------------------------------------------------
extern "C" void kernel_launch(void* const* d_in, const int* in_sizes, int n_in,
                              void* d_out, int out_size)
{
    const float* x = (const float*)d_in[0];
    float* out = (float*)d_out;

    const float* f_in_w    = (const float*)d_in[1];
    const float* f_conv_w  = (const float*)d_in[2];
    const float* f_conv_b  = (const float*)d_in[3];
    const float* f_xproj_w = (const float*)d_in[4];
    const float* f_dt_w    = (const float*)d_in[5];
    const float* f_dt_b    = (const float*)d_in[6];
    const float* f_Alog    = (const float*)d_in[7];
    const float* f_D       = (const float*)d_in[8];
    const float* f_out_w   = (const float*)d_in[9];
    const float* b_in_w    = (const float*)d_in[10];
    const float* b_conv_w  = (const float*)d_in[11];
    const float* b_conv_b  = (const float*)d_in[12];
    const float* b_xproj_w = (const float*)d_in[13];
    const float* b_dt_w    = (const float*)d_in[14];
    const float* b_dt_b    = (const float*)d_in[15];
    const float* b_Alog    = (const float*)d_in[16];
    const float* b_D       = (const float*)d_in[17];
    const float* b_out_w   = (const float*)d_in[18];

    // device-global fp32 targets
    float* xz0;   float* xz1;
    float* xdbl0; float* xdbl1;
    cudaGetSymbolAddress((void**)&xz0,   g_xz);
    xz1   = xz0   + (size_t)MTOT * XZW;
    cudaGetSymbolAddress((void**)&xdbl0, g_xdbl);
    xdbl1 = xdbl0 + (size_t)MTOT * XDBLW;

    // opt-in dynamic smem
    cudaFuncSetAttribute(gemm_h<true,  false>,
                         cudaFuncAttributeMaxDynamicSharedMemorySize, SMEM_BK64);
    cudaFuncSetAttribute(gemm_h<false, true>,
                         cudaFuncAttributeMaxDynamicSharedMemorySize, SMEM_BK64);

    // fused init: zero out/xdbl + fp16 conversion of all GEMM operands
    init_kernel<<<dim3(160, 12), 256>>>(
        (float4*)out, (const float4*)x,
        (const float4*)f_in_w,    (const float4*)b_in_w,
        (const float4*)f_out_w,   (const float4*)b_out_w,
        (const float4*)f_xproj_w, (const float4*)b_xproj_w,
        (const float4*)f_dt_w,    (const float4*)b_dt_w);

    // in_proj: xz = x(flip dir1) @ in_w^T   [2048,3072], K=768 (12 tiles)
    gemm_h<true, false>
        <<<dim3(XZW / 128, MTOT / 128, 2), 256, SMEM_BK64>>>(
        HBUF_XR, HBUF_WIN, nullptr, xz0, xz1,
        XZW, DMODEL, DMODEL, XZW, XZW / 128, DMODEL);

    // depthwise conv + SiLU (writes u exact + u fp16)
    conv_silu_kernel<<<dim3(((MTOT / 4) * (DINNER / 4) + 255) / 256, 2), 256>>>(
        f_conv_w, f_conv_b, b_conv_w, b_conv_b);

    // x_proj (split-K x8, atomic): xdbl += u_h @ xproj_w^T   [2048,80], K=1536
    gemm_h<false, true>
        <<<dim3(8, MTOT / 128, 2), 256, SMEM_BK64>>>(
        HBUF_UR, HBUF_WXP, nullptr, xdbl0, xdbl1,
        XDBLW, DINNER, DINNER, XDBLW, 1, DINNER / 8);

    // delta: softplus(dt @ dt_w^T + dt_b)  [2048,1536], K=48 — fused small-K
    gemm_delta<<<dim3(DINNER / 128, MTOT / 128, 2), 256>>>(f_dt_b, b_dt_b);

    // selective scan (unroll-8 double-buffered; dir1 output pre-flipped)
    scan_kernel<<<dim3((NB * DINNER) / 8, 2), 128>>>(f_Alog, f_D, b_Alog, b_D);

    // out_proj (split-K x2, atomic): out += ypre_h @ out_w^T  [2048,768], K=1536
    gemm_h<false, true>
        <<<dim3((DMODEL / 128) * 2, MTOT / 128, 2), 256, SMEM_BK64>>>(
        HBUF_YPRE, HBUF_WOUT, out, nullptr, nullptr,
        DMODEL, DINNER, DINNER, DMODEL, DMODEL / 128, DINNER / 2);
}